// round 5
// baseline (speedup 1.0000x reference)
#include <cuda_runtime.h>
#include <cuda_bf16.h>
#include <cstdint>

#define N_BT  32
#define HWD   1024
#define CHN   64
#define PLANE 65536      /* CHN*HWD */
#define TOT   2097152    /* N_BT*PLANE */

// ---- scratch (module-load allocated, legal) ----
__device__ float g_qT[TOT];   // [n][i][c]
__device__ float g_kT[TOT];   // [n][j][c]
__device__ float g_v [TOT];   // [n][c][i]
__device__ float g_A [TOT];   // a_s then += a_c   [n][c][i]
__device__ float g_Xe[TOT];   // [n][c][i]
__device__ float g_cl[N_BT * 64 * 64];
__device__ float g_tl[256];
__device__ __nv_bfloat16 g_L16[N_BT << 20]; // 64 MB spatial logits (bf16)
__device__ float g_C [HWD * HWD];           // mx + ln(sum) per (i,j)

__device__ __forceinline__ void mma_tf32(float* d, const uint32_t* a,
                                         uint32_t b0, uint32_t b1) {
    asm volatile(
        "mma.sync.aligned.m16n8k8.row.col.f32.tf32.tf32.f32 "
        "{%0,%1,%2,%3}, {%4,%5,%6,%7}, {%8,%9}, {%0,%1,%2,%3};\n"
        : "+f"(d[0]), "+f"(d[1]), "+f"(d[2]), "+f"(d[3])
        : "r"(a[0]), "r"(a[1]), "r"(a[2]), "r"(a[3]), "r"(b0), "r"(b1));
}

__device__ __forceinline__ void cp_async16(void* smem_dst, const void* gsrc) {
    uint32_t d = (uint32_t)__cvta_generic_to_shared(smem_dst);
    asm volatile("cp.async.cg.shared.global [%0], [%1], 16;\n" :: "r"(d), "l"(gsrc));
}
__device__ __forceinline__ void cp_commit() {
    asm volatile("cp.async.commit_group;\n");
}
__device__ __forceinline__ void cp_wait1() {
    asm volatile("cp.async.wait_group 1;\n");
}

// ============================================================
__global__ void k_zero() {
    int i = blockIdx.x * 256 + threadIdx.x;
    if (i < N_BT * 4096) g_cl[i] = 0.f;
    if (blockIdx.x == 0) g_tl[threadIdx.x] = 0.f;
}

// ---- QKV fused: relu(W x + b). q,k -> [n][i][c]; v -> [n][c][i] ----
__global__ void k_qkv(const float* __restrict__ x,
                      const float* __restrict__ wq, const float* __restrict__ bq,
                      const float* __restrict__ wk, const float* __restrict__ bk,
                      const float* __restrict__ wv, const float* __restrict__ bv) {
    __shared__ float sX[64][68];
    __shared__ float sW[64][68];
    int tid = threadIdx.x;
    int pt = blockIdx.x;
    int n  = pt >> 4;
    int i0 = (pt & 15) << 6;
    int b = n >> 3, t = n & 7;
    const float* ws[3] = {wq, wk, wv};
    const float* bs[3] = {bq, bk, bv};
    for (int idx = tid; idx < 4096; idx += 256) {
        int c = idx >> 6, p = idx & 63;
        sX[c][p] = x[((b * 64 + c) * 8 + t) * 1024 + i0 + p];
    }
    int tx = tid & 15, ty = tid >> 4;
    for (int ph = 0; ph < 3; ph++) {
        __syncthreads();
        for (int idx = tid; idx < 4096; idx += 256)
            sW[idx >> 6][idx & 63] = ws[ph][idx];
        __syncthreads();
        float acc[4][4] = {};
#pragma unroll
        for (int c = 0; c < 64; c++) {
            float4 a4 = *(const float4*)&sX[c][tx * 4];
            float ra[4] = {a4.x, a4.y, a4.z, a4.w};
            float rb[4];
#pragma unroll
            for (int v = 0; v < 4; v++) rb[v] = sW[ty * 4 + v][c];
#pragma unroll
            for (int v = 0; v < 4; v++)
#pragma unroll
                for (int u = 0; u < 4; u++) acc[v][u] = fmaf(rb[v], ra[u], acc[v][u]);
        }
#pragma unroll
        for (int v = 0; v < 4; v++) {
            float bb = bs[ph][ty * 4 + v];
#pragma unroll
            for (int u = 0; u < 4; u++) acc[v][u] = fmaxf(acc[v][u] + bb, 0.f);
        }
        if (ph == 2) {
#pragma unroll
            for (int v = 0; v < 4; v++)
#pragma unroll
                for (int u = 0; u < 4; u++)
                    g_v[n * PLANE + (ty * 4 + v) * HWD + i0 + tx * 4 + u] = acc[v][u];
        } else {
            __syncthreads();
#pragma unroll
            for (int v = 0; v < 4; v++)
#pragma unroll
                for (int u = 0; u < 4; u++)
                    sW[ty * 4 + v][tx * 4 + u] = acc[v][u];
            __syncthreads();
            float* outp = (ph == 0) ? g_qT : g_kT;
            for (int idx = tid; idx < 4096; idx += 256) {
                int li = idx >> 6, o = idx & 63;
                outp[n * PLANE + (i0 + li) * 64 + o] = sW[o][li];
            }
        }
    }
}

// ---- fused spatial logits + online logsumexp over n ----
// grid (jt=16, it=16); each block: 64x64 (i,j) tile, loops n=0..31.
// Stores bf16 logits (coalesced via smem staging) and g_C = mx + ln(sum).
__global__ void k_slog() {
    __shared__ float sb[2][128][36];      // rows 0-63: Q(i), 64-127: K(j); 32-c chunk
    __shared__ uint32_t sStage[64][36];   // 64x64 bf16 tile as packed pairs
    int jt = blockIdx.x, it = blockIdx.y;
    int tid = threadIdx.x;

    auto stage = [&](int st) {            // st = n*2 + kc
        int s = st & 1;
        int n = st >> 1, kc = st & 1 ? 32 : 0;  // BUG-PRONE: kc from st parity? no!
        (void)n; (void)kc;
    };
    // (real stage below; lambda above unused)

    int warp = tid >> 5, lane = tid & 31;
    int r = lane >> 2, cc = lane & 3;
    int wi = (warp & 1) * 32;            // 2 warps along i
    int wj = (warp >> 1) * 16;           // 4 warps along j

    float mr[2][2][4], sr[2][2][4];
#pragma unroll
    for (int m = 0; m < 2; m++)
#pragma unroll
        for (int t = 0; t < 2; t++)
#pragma unroll
            for (int k = 0; k < 4; k++) { mr[m][t][k] = -1e30f; sr[m][t][k] = 0.f; }

    auto do_stage = [&](int st) {
        int s = st & 1;
        int n = st >> 1;
        int kc = (st & 1) ? 32 : 0;      // NOTE: stage parity == k-chunk parity since 2 chunks/n
        // careful: st = n*2 + chunk, chunk = st&1 ✓ ; buffer s = st&1 (2 buffers, ok)
#pragma unroll
        for (int v = 0; v < 4; v++) {
            int e = tid + v * 256;        // 0..1023 float4s
            int row = e >> 3;
            int c4 = (e & 7) * 4;
            const float* src;
            if (row < 64) src = g_qT + n * PLANE + (it * 64 + row) * 64 + kc + c4;
            else          src = g_kT + n * PLANE + (jt * 64 + row - 64) * 64 + kc + c4;
            cp_async16(&sb[s][row][c4], src);
        }
        cp_commit();
    };

    do_stage(0); do_stage(1);

    float acc[2][2][4] = {};
    for (int st = 0; st < 64; st++) {
        cp_wait1();
        __syncthreads();
        int s = st & 1;
        float (*sQ)[36] = sb[s];
        float (*sK)[36] = sb[s] + 64;
#pragma unroll
        for (int ks = 0; ks < 4; ks++) {
            int kk = ks * 8;
            uint32_t a[2][4];
#pragma unroll
            for (int m = 0; m < 2; m++) {
                int i0 = wi + m * 16;
                a[m][0] = __float_as_uint(sQ[i0 + r][kk + cc]);
                a[m][1] = __float_as_uint(sQ[i0 + r + 8][kk + cc]);
                a[m][2] = __float_as_uint(sQ[i0 + r][kk + cc + 4]);
                a[m][3] = __float_as_uint(sQ[i0 + r + 8][kk + cc + 4]);
            }
#pragma unroll
            for (int t = 0; t < 2; t++) {
                uint32_t b0 = __float_as_uint(sK[wj + t * 8 + r][kk + cc]);
                uint32_t b1 = __float_as_uint(sK[wj + t * 8 + r][kk + cc + 4]);
#pragma unroll
                for (int m = 0; m < 2; m++) mma_tf32(acc[m][t], a[m], b0, b1);
            }
        }
        __syncthreads();
        if (st + 2 < 64) do_stage(st + 2);
        else cp_commit();

        if (st & 1) {
            int n = st >> 1;
            // pack bf16 pairs into sStage + online logsumexp update
#pragma unroll
            for (int m = 0; m < 2; m++)
#pragma unroll
                for (int t = 0; t < 2; t++) {
                    int colu = (wj + t * 8) / 2 + cc;   // uint32 (pair) column
                    __nv_bfloat162 lo2 = __floats2bfloat162_rn(acc[m][t][0], acc[m][t][1]);
                    __nv_bfloat162 hi2 = __floats2bfloat162_rn(acc[m][t][2], acc[m][t][3]);
                    sStage[wi + m * 16 + r][colu]     = *(uint32_t*)&lo2;
                    sStage[wi + m * 16 + r + 8][colu] = *(uint32_t*)&hi2;
#pragma unroll
                    for (int k = 0; k < 4; k++) {
                        float l = acc[m][t][k];
                        float d = l - mr[m][t][k];
                        if (d <= 0.f) {
                            sr[m][t][k] += __expf(d);
                        } else {
                            sr[m][t][k] = sr[m][t][k] * __expf(-d) + 1.f;
                            mr[m][t][k] = l;
                        }
                        acc[m][t][k] = 0.f;   // reset for next n
                    }
                }
            __syncthreads();
            // coalesced copy-out: 64 rows x 128B
#pragma unroll
            for (int v = 0; v < 2; v++) {
                int e = tid + v * 256;      // 0..511 uint4s
                int row = e >> 3, q4 = e & 7;
                uint4 val = *(uint4*)&sStage[row][q4 * 4];
                __nv_bfloat16* dst = g_L16 + (n << 20) + (it * 64 + row) * 1024
                                     + jt * 64 + q4 * 8;
                *(uint4*)dst = val;
            }
            // no extra sync needed: >=2 syncthreads before next sStage write
        }
    }
    // write C
#pragma unroll
    for (int m = 0; m < 2; m++)
#pragma unroll
        for (int t = 0; t < 2; t++)
#pragma unroll
            for (int k = 0; k < 4; k++) {
                int row = it * 64 + wi + m * 16 + r + (k >= 2 ? 8 : 0);
                int col = jt * 64 + wj + t * 8 + cc * 2 + (k & 1);
                g_C[row * HWD + col] = mr[m][t][k] + __logf(sr[m][t][k]);
            }
}

// ---- a_s via tf32 MMA, fused exp from bf16 logits; g_A = a_s (pure store) ----
__global__ void k_as() {
    __shared__ __nv_bfloat16 sL[2][128][24];
    __shared__ float sV[2][64][20];
    __shared__ float sP[128][20];
    int n = blockIdx.y, it = blockIdx.x;
    int tid = threadIdx.x;
    const float* vb = g_v + n * PLANE;
    const __nv_bfloat16* lb = g_L16 + (n << 20) + (it * 128) * HWD;

    auto stage = [&](int ch) {
        int s = ch & 1;
        int j0 = ch * 16;
        {
            int row = tid >> 1;
            int half = (tid & 1) * 8;
            cp_async16(&sL[s][row][half], lb + row * HWD + j0 + half);
        }
        {
            int row = tid >> 2;
            int c4 = (tid & 3) * 4;
            cp_async16(&sV[s][row][c4], vb + row * HWD + j0 + c4);
        }
        cp_commit();
    };
    stage(0); stage(1);

    int warp = tid >> 5, lane = tid & 31;
    int r = lane >> 2, cc = lane & 3;
    int wc = (warp & 1) * 32;
    int wi = (warp >> 1) * 32;
    float acc[2][4][4] = {};

    for (int ch = 0; ch < 64; ch++) {
        cp_wait1();
        __syncthreads();
        int s = ch & 1;
        // prefetch A fragments (V) into registers from sV[s]
        uint32_t areg[2][2][4];   // [ks][m][frag]
#pragma unroll
        for (int ks = 0; ks < 2; ks++) {
            int kk = ks * 8;
#pragma unroll
            for (int m = 0; m < 2; m++) {
                int c0 = wc + m * 16;
                areg[ks][m][0] = __float_as_uint(sV[s][c0 + r][kk + cc]);
                areg[ks][m][1] = __float_as_uint(sV[s][c0 + r + 8][kk + cc]);
                areg[ks][m][2] = __float_as_uint(sV[s][c0 + r][kk + cc + 4]);
                areg[ks][m][3] = __float_as_uint(sV[s][c0 + r + 8][kk + cc + 4]);
            }
        }
        // raw bf16 logits -> probabilities in sP
#pragma unroll
        for (int v = 0; v < 8; v++) {
            int e = tid + v * 256;
            int row = e >> 4, jj = e & 15;
            float Cv = g_C[(it * 128 + row) * HWD + ch * 16 + jj];
            float l = __bfloat162float(sL[s][row][jj]);
            sP[row][jj] = __expf(l - Cv);
        }
        __syncthreads();
        if (ch + 2 < 64) stage(ch + 2);
        else cp_commit();
#pragma unroll
        for (int ks = 0; ks < 2; ks++) {
            int kk = ks * 8;
#pragma unroll
            for (int t = 0; t < 4; t++) {
                uint32_t b0 = __float_as_uint(sP[wi + t * 8 + r][kk + cc]);
                uint32_t b1 = __float_as_uint(sP[wi + t * 8 + r][kk + cc + 4]);
#pragma unroll
                for (int m = 0; m < 2; m++) mma_tf32(acc[m][t], areg[ks][m], b0, b1);
            }
        }
    }
#pragma unroll
    for (int m = 0; m < 2; m++)
#pragma unroll
        for (int t = 0; t < 4; t++) {
            int c0 = wc + m * 16 + r;
            int i0 = it * 128 + wi + t * 8 + cc * 2;
            float2 o0 = {acc[m][t][0], acc[m][t][1]};
            float2 o1 = {acc[m][t][2], acc[m][t][3]};
            *(float2*)&g_A[n * PLANE + c0 * HWD + i0] = o0;
            *(float2*)&g_A[n * PLANE + (c0 + 8) * HWD + i0] = o1;
        }
}

// ---- channel logits (split-k atomics) ----
__global__ void k_cl() {
    __shared__ float sQT[64][68];
    __shared__ float sKT[64][68];
    int n = blockIdx.y;
    int tid = threadIdx.x, tx = tid & 15, ty = tid >> 4;
    float acc[4][4] = {};
    for (int sub = 0; sub < 4; sub++) {
        int k0 = blockIdx.x * 256 + sub * 64;
        __syncthreads();
        for (int idx = tid; idx < 4096; idx += 256) {
            int kk = idx >> 6, c = idx & 63;
            sQT[kk][c] = g_qT[n * PLANE + (k0 + kk) * 64 + c];
            sKT[kk][c] = g_kT[n * PLANE + (k0 + kk) * 64 + c];
        }
        __syncthreads();
#pragma unroll 16
        for (int kk = 0; kk < 64; kk++) {
            float ra[4], rb[4];
#pragma unroll
            for (int v = 0; v < 4; v++) ra[v] = sQT[kk][ty * 4 + v];
#pragma unroll
            for (int u = 0; u < 4; u++) rb[u] = sKT[kk][tx * 4 + u];
#pragma unroll
            for (int v = 0; v < 4; v++)
#pragma unroll
                for (int u = 0; u < 4; u++) acc[v][u] = fmaf(ra[v], rb[u], acc[v][u]);
        }
    }
#pragma unroll
    for (int v = 0; v < 4; v++)
#pragma unroll
        for (int u = 0; u < 4; u++)
            atomicAdd(&g_cl[n * 4096 + (ty * 4 + v) * 64 + tx * 4 + u], acc[v][u]);
}

// ---- softmax over n on (n,c,d) ----
__global__ void k_softmax_c() {
    int p = blockIdx.x * 256 + threadIdx.x;
    float vals[32], mx = -1e30f;
#pragma unroll
    for (int nn = 0; nn < 32; nn++) { vals[nn] = g_cl[nn * 4096 + p]; mx = fmaxf(mx, vals[nn]); }
    float s = 0.f;
#pragma unroll
    for (int nn = 0; nn < 32; nn++) { vals[nn] = __expf(vals[nn] - mx); s += vals[nn]; }
    float inv = 1.f / s;
#pragma unroll
    for (int nn = 0; nn < 32; nn++) g_cl[nn * 4096 + p] = vals[nn] * inv;
}

// ---- a_c: g_A += m_c @ v ----
__global__ void k_ac() {
    __shared__ float sM[64][65];
    __shared__ float sV[32][128];
    int n = blockIdx.y, it = blockIdx.x;
    int tid = threadIdx.x, tx = tid & 15, ty = tid >> 4;
    for (int idx = tid; idx < 4096; idx += 256)
        sM[idx >> 6][idx & 63] = g_cl[n * 4096 + idx];
    float acc[4][8] = {};
    for (int dh = 0; dh < 2; dh++) {
        __syncthreads();
        for (int idx4 = tid; idx4 < 1024; idx4 += 256) {
            int d = idx4 >> 5, ii = (idx4 & 31) << 2;
            *(float4*)&sV[d][ii] =
                *(const float4*)&g_v[n * PLANE + (dh * 32 + d) * HWD + it * 128 + ii];
        }
        __syncthreads();
#pragma unroll 8
        for (int d = 0; d < 32; d++) {
            float rm[4];
#pragma unroll
            for (int v = 0; v < 4; v++) rm[v] = sM[ty * 4 + v][dh * 32 + d];
            float4 va = *(const float4*)&sV[d][tx * 8];
            float4 vb = *(const float4*)&sV[d][tx * 8 + 4];
            float rv[8] = {va.x, va.y, va.z, va.w, vb.x, vb.y, vb.z, vb.w};
#pragma unroll
            for (int v = 0; v < 4; v++)
#pragma unroll
                for (int u = 0; u < 8; u++) acc[v][u] = fmaf(rm[v], rv[u], acc[v][u]);
        }
    }
#pragma unroll
    for (int v = 0; v < 4; v++)
#pragma unroll
        for (int u = 0; u < 8; u++) {
            int a = n * PLANE + (ty * 4 + v) * HWD + it * 128 + tx * 8 + u;
            g_A[a] = g_A[a] + acc[v][u];
        }
}

// ---- temporal conv (3,1,1) pad 1 + relu -> g_Xe ----
__global__ void k_tconv(const float* __restrict__ wX, const float* __restrict__ bX) {
    __shared__ float sA[32][132];
    __shared__ float sW[64][68];
    int n = blockIdx.y, it = blockIdx.x;
    int b = n >> 3, t = n & 7;
    int tid = threadIdx.x, tx = tid & 15, ty = tid >> 4;
    float acc[4][8] = {};
    for (int kk = 0; kk < 3; kk++) {
        int tp = t + kk - 1;
        if (tp < 0 || tp >= 8) continue;
        __syncthreads();
        for (int idx = tid; idx < 4096; idx += 256) {
            int o = idx >> 6, c = idx & 63;
            sW[o][c] = wX[o * 192 + c * 3 + kk];
        }
        for (int ch = 0; ch < 2; ch++) {
            __syncthreads();
            for (int idx4 = tid; idx4 < 1024; idx4 += 256) {
                int c = idx4 >> 5, ii = (idx4 & 31) << 2;
                *(float4*)&sA[c][ii] =
                    *(const float4*)&g_A[(b * 8 + tp) * PLANE + (ch * 32 + c) * HWD + it * 128 + ii];
            }
            __syncthreads();
#pragma unroll 4
            for (int c = 0; c < 32; c++) {
                float rw[4];
#pragma unroll
                for (int v = 0; v < 4; v++) rw[v] = sW[ty * 4 + v][ch * 32 + c];
                float4 aa = *(const float4*)&sA[c][tx * 8];
                float4 ab = *(const float4*)&sA[c][tx * 8 + 4];
                float ra[8] = {aa.x, aa.y, aa.z, aa.w, ab.x, ab.y, ab.z, ab.w};
#pragma unroll
                for (int v = 0; v < 4; v++)
#pragma unroll
                    for (int u = 0; u < 8; u++) acc[v][u] = fmaf(rw[v], ra[u], acc[v][u]);
            }
        }
    }
#pragma unroll
    for (int v = 0; v < 4; v++) {
        float bb = bX[ty * 4 + v];
#pragma unroll
        for (int u = 0; u < 8; u++)
            g_Xe[n * PLANE + (ty * 4 + v) * HWD + it * 128 + tx * 8 + u] =
                fmaxf(acc[v][u] + bb, 0.f);
    }
}

// ---- temporal Gram: g_tl[b,t,s] += partial dot over d-slice ----
__global__ void k_tl() {
    __shared__ float sXe[8][1032];
    int b = blockIdx.y;
    int d0 = blockIdx.x * 1024;
    int tid = threadIdx.x;
    for (int v = 0; v < 8; v++) {
        int e = tid + v * 256;
        int t = e >> 8;
        int d4 = (e & 255) * 4;
        *(float4*)&sXe[t][d4] = *(const float4*)&g_Xe[(b * 8 + t) * PLANE + d0 + d4];
    }
    __syncthreads();
    int p = tid >> 2, sub = tid & 3;
    int t = p >> 3, s = p & 7;
    float acc = 0.f;
#pragma unroll 8
    for (int it = 0; it < 64; it++) {
        int col = sub * 4 + it * 16;
        float4 a = *(const float4*)&sXe[t][col];
        float4 c = *(const float4*)&sXe[s][col];
        acc += a.x * c.x + a.y * c.y + a.z * c.z + a.w * c.w;
    }
    acc += __shfl_xor_sync(0xffffffff, acc, 1);
    acc += __shfl_xor_sync(0xffffffff, acc, 2);
    if (sub == 0) atomicAdd(&g_tl[b * 64 + p], acc);
}

__global__ void k_softmax_t() {
    int p = threadIdx.x;
    float v0 = g_tl[p], v1 = g_tl[64 + p], v2 = g_tl[128 + p], v3 = g_tl[192 + p];
    float mx = fmaxf(fmaxf(v0, v1), fmaxf(v2, v3));
    v0 = __expf(v0 - mx); v1 = __expf(v1 - mx); v2 = __expf(v2 - mx); v3 = __expf(v3 - mx);
    float inv = 1.f / (v0 + v1 + v2 + v3);
    g_tl[p] = v0 * inv; g_tl[64 + p] = v1 * inv;
    g_tl[128 + p] = v2 * inv; g_tl[192 + p] = v3 * inv;
}

__global__ void k_out(float* __restrict__ out) {
    __shared__ float sM[64];
    int gid = blockIdx.x * 256 + threadIdx.x;
    int b = gid >> 16;
    if (threadIdx.x < 64) sM[threadIdx.x] = g_tl[b * 64 + threadIdx.x];
    __syncthreads();
    int rem = gid & 65535;
    int c = rem >> 10, i = rem & 1023;
    float vv[8];
#pragma unroll
    for (int s = 0; s < 8; s++) vv[s] = g_v[(b * 8 + s) * PLANE + c * HWD + i];
#pragma unroll
    for (int t = 0; t < 8; t++) {
        float rsum = 0.f;
#pragma unroll
        for (int s = 0; s < 8; s++) rsum = fmaf(sM[t * 8 + s], vv[s], rsum);
        out[((b * 64 + c) * 8 + t) * HWD + i] = rsum;
    }
}

// ============================================================
extern "C" void kernel_launch(void* const* d_in, const int* in_sizes, int n_in,
                              void* d_out, int out_size) {
    const float* x  = (const float*)d_in[0];
    const float* wq = (const float*)d_in[1];
    const float* bq = (const float*)d_in[2];
    const float* wk = (const float*)d_in[3];
    const float* bk = (const float*)d_in[4];
    const float* wv = (const float*)d_in[5];
    const float* bv = (const float*)d_in[6];
    const float* wX = (const float*)d_in[7];
    const float* bX = (const float*)d_in[8];
    float* out = (float*)d_out;

    k_zero<<<512, 256>>>();                                // 0
    k_qkv<<<512, 256>>>(x, wq, bq, wk, bk, wv, bv);        // 1
    k_slog<<<dim3(16, 16), 256>>>();                       // 2
    k_as<<<dim3(8, 32), 256>>>();                          // 3  <- ncu capture slot
    k_cl<<<dim3(4, 32), 256>>>();                          // 4
    k_softmax_c<<<16, 256>>>();                            // 5
    k_ac<<<dim3(8, 32), 256>>>();                          // 6  (+= a_c)
    k_tconv<<<dim3(8, 32), 256>>>(wX, bX);                 // 7
    k_tl<<<dim3(64, 4), 256>>>();                          // 8
    k_softmax_t<<<1, 64>>>();                              // 9
    k_out<<<1024, 256>>>(out);                             // 10
}

// round 6
// speedup vs baseline: 1.2177x; 1.2177x over previous
#include <cuda_runtime.h>
#include <cuda_bf16.h>
#include <cstdint>

#define N_BT  32
#define HWD   1024
#define CHN   64
#define PLANE 65536      /* CHN*HWD */
#define TOT   2097152    /* N_BT*PLANE */

// ---- scratch (module-load allocated, legal) ----
__device__ __nv_bfloat16 g_qT16[TOT];  // [n][i][c]
__device__ __nv_bfloat16 g_kT16[TOT];  // [n][j][c]
__device__ float g_v [TOT];            // [n][c][i] fp32 (k_ac, k_out)
__device__ __nv_bfloat16 g_v16[TOT];   // [n][c][i] bf16 (k_as)
__device__ float g_A [TOT];            // a_s then += a_c   [n][c][i]
__device__ float g_Xe[TOT];            // [n][c][i]
__device__ float g_cl[N_BT * 64 * 64];
__device__ float g_tl[256];
__device__ __nv_bfloat16 g_L16[N_BT << 20]; // 64 MB spatial logits (bf16)
__device__ float g_C [HWD * HWD];           // mx + ln(sum) per (i,j)

__device__ __forceinline__ void mma_bf16(float* d, const uint32_t* a,
                                         uint32_t b0, uint32_t b1) {
    asm volatile(
        "mma.sync.aligned.m16n8k16.row.col.f32.bf16.bf16.f32 "
        "{%0,%1,%2,%3}, {%4,%5,%6,%7}, {%8,%9}, {%0,%1,%2,%3};\n"
        : "+f"(d[0]), "+f"(d[1]), "+f"(d[2]), "+f"(d[3])
        : "r"(a[0]), "r"(a[1]), "r"(a[2]), "r"(a[3]), "r"(b0), "r"(b1));
}

__device__ __forceinline__ void cp_async16(void* smem_dst, const void* gsrc) {
    uint32_t d = (uint32_t)__cvta_generic_to_shared(smem_dst);
    asm volatile("cp.async.cg.shared.global [%0], [%1], 16;\n" :: "r"(d), "l"(gsrc));
}
__device__ __forceinline__ void cp_commit() { asm volatile("cp.async.commit_group;\n"); }
__device__ __forceinline__ void cp_wait1()  { asm volatile("cp.async.wait_group 1;\n"); }
__device__ __forceinline__ void cp_wait0()  { asm volatile("cp.async.wait_group 0;\n"); }

// ============================================================
__global__ void k_zero() {
    int i = blockIdx.x * 256 + threadIdx.x;
    if (i < N_BT * 4096) g_cl[i] = 0.f;
    if (blockIdx.x == 0) g_tl[threadIdx.x] = 0.f;
}

// ---- QKV fused: relu(W x + b). q,k -> bf16 [n][i][c]; v -> fp32+bf16 [n][c][i] ----
__global__ void k_qkv(const float* __restrict__ x,
                      const float* __restrict__ wq, const float* __restrict__ bq,
                      const float* __restrict__ wk, const float* __restrict__ bk,
                      const float* __restrict__ wv, const float* __restrict__ bv) {
    __shared__ float sX[64][68];
    __shared__ float sW[64][68];
    int tid = threadIdx.x;
    int pt = blockIdx.x;
    int n  = pt >> 4;
    int i0 = (pt & 15) << 6;
    int b = n >> 3, t = n & 7;
    const float* ws[3] = {wq, wk, wv};
    const float* bs[3] = {bq, bk, bv};
    for (int idx = tid; idx < 4096; idx += 256) {
        int c = idx >> 6, p = idx & 63;
        sX[c][p] = x[((b * 64 + c) * 8 + t) * 1024 + i0 + p];
    }
    int tx = tid & 15, ty = tid >> 4;
    for (int ph = 0; ph < 3; ph++) {
        __syncthreads();
        for (int idx = tid; idx < 4096; idx += 256)
            sW[idx >> 6][idx & 63] = ws[ph][idx];
        __syncthreads();
        float acc[4][4] = {};
#pragma unroll
        for (int c = 0; c < 64; c++) {
            float4 a4 = *(const float4*)&sX[c][tx * 4];
            float ra[4] = {a4.x, a4.y, a4.z, a4.w};
            float rb[4];
#pragma unroll
            for (int v = 0; v < 4; v++) rb[v] = sW[ty * 4 + v][c];
#pragma unroll
            for (int v = 0; v < 4; v++)
#pragma unroll
                for (int u = 0; u < 4; u++) acc[v][u] = fmaf(rb[v], ra[u], acc[v][u]);
        }
#pragma unroll
        for (int v = 0; v < 4; v++) {
            float bb = bs[ph][ty * 4 + v];
#pragma unroll
            for (int u = 0; u < 4; u++) acc[v][u] = fmaxf(acc[v][u] + bb, 0.f);
        }
        if (ph == 2) {
#pragma unroll
            for (int v = 0; v < 4; v++)
#pragma unroll
                for (int u = 0; u < 4; u++) {
                    int a = n * PLANE + (ty * 4 + v) * HWD + i0 + tx * 4 + u;
                    g_v[a] = acc[v][u];
                    g_v16[a] = __float2bfloat16(acc[v][u]);
                }
        } else {
            __syncthreads();
#pragma unroll
            for (int v = 0; v < 4; v++)
#pragma unroll
                for (int u = 0; u < 4; u++)
                    sW[ty * 4 + v][tx * 4 + u] = acc[v][u];
            __syncthreads();
            __nv_bfloat16* outp = (ph == 0) ? g_qT16 : g_kT16;
            for (int idx = tid; idx < 4096; idx += 256) {
                int li = idx >> 6, o = idx & 63;
                outp[n * PLANE + (i0 + li) * 64 + o] = __float2bfloat16(sW[o][li]);
            }
        }
    }
}

// ---- spatial logits via bf16 MMA: L[n,i,j] = sum_c q[i,c] k[j,c] -> bf16 ----
// grid (jt8, it8, n32); 128x128 tile per block; K=64 single stage.
__global__ void k_slogits() {
    __shared__ __align__(16) __nv_bfloat16 sQK[2][128][72];   // [0]=Q rows, [1]=K rows
    int jt = blockIdx.x, it = blockIdx.y, n = blockIdx.z;
    int tid = threadIdx.x;
    const __nv_bfloat16* qb = g_qT16 + n * PLANE + (it * 128) * 64;
    const __nv_bfloat16* kb = g_kT16 + n * PLANE + (jt * 128) * 64;

    // load Q and K tiles: 2*128 rows x 128B
#pragma unroll
    for (int v = 0; v < 8; v++) {
        int e = tid + v * 256;         // 0..2047 16B chunks
        int row = e >> 3;              // 0..255
        int p8 = (e & 7) * 8;          // bf16 offset
        const __nv_bfloat16* src = (row < 128) ? (qb + row * 64 + p8)
                                               : (kb + (row - 128) * 64 + p8);
        cp_async16(&sQK[row >> 7][row & 127][p8], src);
    }
    cp_commit(); cp_wait0();
    __syncthreads();

    int warp = tid >> 5, lane = tid & 31;
    int r = lane >> 2, cc = lane & 3;
    int wi = (warp & 3) * 32;          // 4 warps along i
    int wj = (warp >> 2) * 64;         // 2 warps along j
    float acc[2][8][4] = {};

#pragma unroll
    for (int ks = 0; ks < 4; ks++) {
        int kk = ks * 16;
        uint32_t a[2][4];
#pragma unroll
        for (int m = 0; m < 2; m++) {
            int i0 = wi + m * 16;
            a[m][0] = *(const uint32_t*)&sQK[0][i0 + r][kk + 2 * cc];
            a[m][1] = *(const uint32_t*)&sQK[0][i0 + r + 8][kk + 2 * cc];
            a[m][2] = *(const uint32_t*)&sQK[0][i0 + r][kk + 2 * cc + 8];
            a[m][3] = *(const uint32_t*)&sQK[0][i0 + r + 8][kk + 2 * cc + 8];
        }
#pragma unroll
        for (int t = 0; t < 8; t++) {
            uint32_t b0 = *(const uint32_t*)&sQK[1][wj + t * 8 + r][kk + 2 * cc];
            uint32_t b1 = *(const uint32_t*)&sQK[1][wj + t * 8 + r][kk + 2 * cc + 8];
#pragma unroll
            for (int m = 0; m < 2; m++) mma_bf16(acc[m][t], a[m], b0, b1);
        }
    }

    // stage bf16 results into smem (reusing sQK) then coalesced copy out
    __syncthreads();
    uint32_t (*stg)[68] = (uint32_t(*)[68])sQK;   // 128 x 64(+4 pad) words
#pragma unroll
    for (int m = 0; m < 2; m++)
#pragma unroll
        for (int t = 0; t < 8; t++) {
            int rowl = wi + m * 16 + r;
            int colw = (wj + t * 8) / 2 + cc;
            __nv_bfloat162 lo = __floats2bfloat162_rn(acc[m][t][0], acc[m][t][1]);
            __nv_bfloat162 hi = __floats2bfloat162_rn(acc[m][t][2], acc[m][t][3]);
            stg[rowl][colw]     = *(uint32_t*)&lo;
            stg[rowl + 8][colw] = *(uint32_t*)&hi;
        }
    __syncthreads();
#pragma unroll
    for (int v = 0; v < 8; v++) {
        int e = tid + v * 256;          // 0..2047 uint4s
        int row = e >> 4, q = e & 15;
        uint4 val = *(uint4*)&stg[row][q * 4];
        __nv_bfloat16* dst = g_L16 + ((size_t)n << 20) + (it * 128 + row) * 1024
                             + jt * 128 + q * 8;
        *(uint4*)dst = val;
    }
}

// ---- per-(i,j): C = mx + ln(sum_n exp(L - mx)) from bf16 logits ----
__global__ void k_smax() {
    int idx = blockIdx.x * 256 + threadIdx.x;
    float vals[32], mx = -1e30f;
#pragma unroll
    for (int nn = 0; nn < 32; nn++) {
        vals[nn] = __bfloat162float(g_L16[((size_t)nn << 20) + idx]);
        mx = fmaxf(mx, vals[nn]);
    }
    float s = 0.f;
#pragma unroll
    for (int nn = 0; nn < 32; nn++) s += __expf(vals[nn] - mx);
    g_C[idx] = mx + __logf(s);
}

// ---- a_s via bf16 MMA, fused exp; g_A = a_s (pure store) ----
// grid (it8, n32); block: c64 x i128, K=1024 over j, chunk 32.
__global__ void k_as() {
    __shared__ __nv_bfloat16 sL[2][128][40];
    __shared__ __nv_bfloat16 sV[2][64][40];
    __shared__ __nv_bfloat16 sP[128][40];
    int it = blockIdx.x, n = blockIdx.y;
    int tid = threadIdx.x;
    const __nv_bfloat16* vb = g_v16 + n * PLANE;
    const __nv_bfloat16* lb = g_L16 + ((size_t)n << 20) + (it * 128) * 1024;

    auto stage = [&](int ch) {
        int s = ch & 1;
        int j0 = ch * 32;
#pragma unroll
        for (int v = 0; v < 2; v++) {
            int e = tid + v * 256;       // 0..511
            int row = e >> 2;
            int p8 = (e & 3) * 8;
            cp_async16(&sL[s][row][p8], lb + row * 1024 + j0 + p8);
        }
        {
            int row = tid >> 2;
            int p8 = (tid & 3) * 8;
            cp_async16(&sV[s][row][p8], vb + row * 1024 + j0 + p8);
        }
        cp_commit();
    };
    stage(0); stage(1);

    int warp = tid >> 5, lane = tid & 31;
    int r = lane >> 2, cc = lane & 3;
    int wc = (warp & 1) * 32;            // 2 warps along c (M)
    int wi = (warp >> 1) * 32;           // 4 warps along i (N)
    float acc[2][4][4] = {};

    for (int ch = 0; ch < 32; ch++) {
        cp_wait1();
        __syncthreads();
        int s = ch & 1;
        // prefetch A fragments (V) into registers from sV[s]
        uint32_t areg[2][2][4];          // [ks][m][frag]
#pragma unroll
        for (int ks = 0; ks < 2; ks++) {
            int kk = ks * 16;
#pragma unroll
            for (int m = 0; m < 2; m++) {
                int c0 = wc + m * 16;
                areg[ks][m][0] = *(const uint32_t*)&sV[s][c0 + r][kk + 2 * cc];
                areg[ks][m][1] = *(const uint32_t*)&sV[s][c0 + r + 8][kk + 2 * cc];
                areg[ks][m][2] = *(const uint32_t*)&sV[s][c0 + r][kk + 2 * cc + 8];
                areg[ks][m][3] = *(const uint32_t*)&sV[s][c0 + r + 8][kk + 2 * cc + 8];
            }
        }
        // bf16 logits -> probabilities in sP
#pragma unroll
        for (int v = 0; v < 16; v++) {
            int e = tid + v * 256;
            int row = e >> 5, jj = e & 31;
            float Cv = g_C[(it * 128 + row) * 1024 + ch * 32 + jj];
            float l = __bfloat162float(sL[s][row][jj]);
            sP[row][jj] = __float2bfloat16(__expf(l - Cv));
        }
        __syncthreads();
        if (ch + 2 < 32) stage(ch + 2);
        else cp_commit();
#pragma unroll
        for (int ks = 0; ks < 2; ks++) {
            int kk = ks * 16;
#pragma unroll
            for (int t = 0; t < 4; t++) {
                uint32_t b0 = *(const uint32_t*)&sP[wi + t * 8 + r][kk + 2 * cc];
                uint32_t b1 = *(const uint32_t*)&sP[wi + t * 8 + r][kk + 2 * cc + 8];
#pragma unroll
                for (int m = 0; m < 2; m++) mma_bf16(acc[m][t], areg[ks][m], b0, b1);
            }
        }
    }
#pragma unroll
    for (int m = 0; m < 2; m++)
#pragma unroll
        for (int t = 0; t < 4; t++) {
            int c0 = wc + m * 16 + r;
            int i0 = it * 128 + wi + t * 8 + cc * 2;
            float2 o0 = {acc[m][t][0], acc[m][t][1]};
            float2 o1 = {acc[m][t][2], acc[m][t][3]};
            *(float2*)&g_A[n * PLANE + c0 * HWD + i0] = o0;
            *(float2*)&g_A[n * PLANE + (c0 + 8) * HWD + i0] = o1;
        }
}

// ---- channel logits (split-k atomics), bf16 inputs ----
__global__ void k_cl() {
    __shared__ float sQT[64][68];
    __shared__ float sKT[64][68];
    int n = blockIdx.y;
    int tid = threadIdx.x, tx = tid & 15, ty = tid >> 4;
    float acc[4][4] = {};
    for (int sub = 0; sub < 4; sub++) {
        int k0 = blockIdx.x * 256 + sub * 64;
        __syncthreads();
        for (int idx = tid; idx < 4096; idx += 256) {
            int kk = idx >> 6, c = idx & 63;
            sQT[kk][c] = __bfloat162float(g_qT16[n * PLANE + (k0 + kk) * 64 + c]);
            sKT[kk][c] = __bfloat162float(g_kT16[n * PLANE + (k0 + kk) * 64 + c]);
        }
        __syncthreads();
#pragma unroll 16
        for (int kk = 0; kk < 64; kk++) {
            float ra[4], rb[4];
#pragma unroll
            for (int v = 0; v < 4; v++) ra[v] = sQT[kk][ty * 4 + v];
#pragma unroll
            for (int u = 0; u < 4; u++) rb[u] = sKT[kk][tx * 4 + u];
#pragma unroll
            for (int v = 0; v < 4; v++)
#pragma unroll
                for (int u = 0; u < 4; u++) acc[v][u] = fmaf(ra[v], rb[u], acc[v][u]);
        }
    }
#pragma unroll
    for (int v = 0; v < 4; v++)
#pragma unroll
        for (int u = 0; u < 4; u++)
            atomicAdd(&g_cl[n * 4096 + (ty * 4 + v) * 64 + tx * 4 + u], acc[v][u]);
}

// ---- softmax over n on (n,c,d) ----
__global__ void k_softmax_c() {
    int p = blockIdx.x * 256 + threadIdx.x;
    float vals[32], mx = -1e30f;
#pragma unroll
    for (int nn = 0; nn < 32; nn++) { vals[nn] = g_cl[nn * 4096 + p]; mx = fmaxf(mx, vals[nn]); }
    float s = 0.f;
#pragma unroll
    for (int nn = 0; nn < 32; nn++) { vals[nn] = __expf(vals[nn] - mx); s += vals[nn]; }
    float inv = 1.f / s;
#pragma unroll
    for (int nn = 0; nn < 32; nn++) g_cl[nn * 4096 + p] = vals[nn] * inv;
}

// ---- a_c: g_A += m_c @ v ----
__global__ void k_ac() {
    __shared__ float sM[64][65];
    __shared__ float sV[32][128];
    int n = blockIdx.y, it = blockIdx.x;
    int tid = threadIdx.x, tx = tid & 15, ty = tid >> 4;
    for (int idx = tid; idx < 4096; idx += 256)
        sM[idx >> 6][idx & 63] = g_cl[n * 4096 + idx];
    float acc[4][8] = {};
    for (int dh = 0; dh < 2; dh++) {
        __syncthreads();
        for (int idx4 = tid; idx4 < 1024; idx4 += 256) {
            int d = idx4 >> 5, ii = (idx4 & 31) << 2;
            *(float4*)&sV[d][ii] =
                *(const float4*)&g_v[n * PLANE + (dh * 32 + d) * HWD + it * 128 + ii];
        }
        __syncthreads();
#pragma unroll 8
        for (int d = 0; d < 32; d++) {
            float rm[4];
#pragma unroll
            for (int v = 0; v < 4; v++) rm[v] = sM[ty * 4 + v][dh * 32 + d];
            float4 va = *(const float4*)&sV[d][tx * 8];
            float4 vb = *(const float4*)&sV[d][tx * 8 + 4];
            float rv[8] = {va.x, va.y, va.z, va.w, vb.x, vb.y, vb.z, vb.w};
#pragma unroll
            for (int v = 0; v < 4; v++)
#pragma unroll
                for (int u = 0; u < 8; u++) acc[v][u] = fmaf(rm[v], rv[u], acc[v][u]);
        }
    }
#pragma unroll
    for (int v = 0; v < 4; v++)
#pragma unroll
        for (int u = 0; u < 8; u++) {
            int a = n * PLANE + (ty * 4 + v) * HWD + it * 128 + tx * 8 + u;
            g_A[a] = g_A[a] + acc[v][u];
        }
}

// ---- temporal conv (3,1,1) pad 1 + relu -> g_Xe ----
__global__ void k_tconv(const float* __restrict__ wX, const float* __restrict__ bX) {
    __shared__ float sA[32][132];
    __shared__ float sW[64][68];
    int n = blockIdx.y, it = blockIdx.x;
    int b = n >> 3, t = n & 7;
    int tid = threadIdx.x, tx = tid & 15, ty = tid >> 4;
    float acc[4][8] = {};
    for (int kk = 0; kk < 3; kk++) {
        int tp = t + kk - 1;
        if (tp < 0 || tp >= 8) continue;
        __syncthreads();
        for (int idx = tid; idx < 4096; idx += 256) {
            int o = idx >> 6, c = idx & 63;
            sW[o][c] = wX[o * 192 + c * 3 + kk];
        }
        for (int ch = 0; ch < 2; ch++) {
            __syncthreads();
            for (int idx4 = tid; idx4 < 1024; idx4 += 256) {
                int c = idx4 >> 5, ii = (idx4 & 31) << 2;
                *(float4*)&sA[c][ii] =
                    *(const float4*)&g_A[(b * 8 + tp) * PLANE + (ch * 32 + c) * HWD + it * 128 + ii];
            }
            __syncthreads();
#pragma unroll 4
            for (int c = 0; c < 32; c++) {
                float rw[4];
#pragma unroll
                for (int v = 0; v < 4; v++) rw[v] = sW[ty * 4 + v][ch * 32 + c];
                float4 aa = *(const float4*)&sA[c][tx * 8];
                float4 ab = *(const float4*)&sA[c][tx * 8 + 4];
                float ra[8] = {aa.x, aa.y, aa.z, aa.w, ab.x, ab.y, ab.z, ab.w};
#pragma unroll
                for (int v = 0; v < 4; v++)
#pragma unroll
                    for (int u = 0; u < 8; u++) acc[v][u] = fmaf(rw[v], ra[u], acc[v][u]);
            }
        }
    }
#pragma unroll
    for (int v = 0; v < 4; v++) {
        float bb = bX[ty * 4 + v];
#pragma unroll
        for (int u = 0; u < 8; u++)
            g_Xe[n * PLANE + (ty * 4 + v) * HWD + it * 128 + tx * 8 + u] =
                fmaxf(acc[v][u] + bb, 0.f);
    }
}

// ---- temporal Gram: g_tl[b,t,s] += partial dot over d-slice ----
__global__ void k_tl() {
    __shared__ float sXe[8][1032];
    int b = blockIdx.y;
    int d0 = blockIdx.x * 1024;
    int tid = threadIdx.x;
    for (int v = 0; v < 8; v++) {
        int e = tid + v * 256;
        int t = e >> 8;
        int d4 = (e & 255) * 4;
        *(float4*)&sXe[t][d4] = *(const float4*)&g_Xe[(b * 8 + t) * PLANE + d0 + d4];
    }
    __syncthreads();
    int p = tid >> 2, sub = tid & 3;
    int t = p >> 3, s = p & 7;
    float acc = 0.f;
#pragma unroll 8
    for (int it = 0; it < 64; it++) {
        int col = sub * 4 + it * 16;
        float4 a = *(const float4*)&sXe[t][col];
        float4 c = *(const float4*)&sXe[s][col];
        acc += a.x * c.x + a.y * c.y + a.z * c.z + a.w * c.w;
    }
    acc += __shfl_xor_sync(0xffffffff, acc, 1);
    acc += __shfl_xor_sync(0xffffffff, acc, 2);
    if (sub == 0) atomicAdd(&g_tl[b * 64 + p], acc);
}

__global__ void k_softmax_t() {
    int p = threadIdx.x;
    float v0 = g_tl[p], v1 = g_tl[64 + p], v2 = g_tl[128 + p], v3 = g_tl[192 + p];
    float mx = fmaxf(fmaxf(v0, v1), fmaxf(v2, v3));
    v0 = __expf(v0 - mx); v1 = __expf(v1 - mx); v2 = __expf(v2 - mx); v3 = __expf(v3 - mx);
    float inv = 1.f / (v0 + v1 + v2 + v3);
    g_tl[p] = v0 * inv; g_tl[64 + p] = v1 * inv;
    g_tl[128 + p] = v2 * inv; g_tl[192 + p] = v3 * inv;
}

__global__ void k_out(float* __restrict__ out) {
    __shared__ float sM[64];
    int gid = blockIdx.x * 256 + threadIdx.x;
    int b = gid >> 16;
    if (threadIdx.x < 64) sM[threadIdx.x] = g_tl[b * 64 + threadIdx.x];
    __syncthreads();
    int rem = gid & 65535;
    int c = rem >> 10, i = rem & 1023;
    float vv[8];
#pragma unroll
    for (int s = 0; s < 8; s++) vv[s] = g_v[(b * 8 + s) * PLANE + c * HWD + i];
#pragma unroll
    for (int t = 0; t < 8; t++) {
        float rsum = 0.f;
#pragma unroll
        for (int s = 0; s < 8; s++) rsum = fmaf(sM[t * 8 + s], vv[s], rsum);
        out[((b * 64 + c) * 8 + t) * HWD + i] = rsum;
    }
}

// ============================================================
extern "C" void kernel_launch(void* const* d_in, const int* in_sizes, int n_in,
                              void* d_out, int out_size) {
    const float* x  = (const float*)d_in[0];
    const float* wq = (const float*)d_in[1];
    const float* bq = (const float*)d_in[2];
    const float* wk = (const float*)d_in[3];
    const float* bk = (const float*)d_in[4];
    const float* wv = (const float*)d_in[5];
    const float* bv = (const float*)d_in[6];
    const float* wX = (const float*)d_in[7];
    const float* bX = (const float*)d_in[8];
    float* out = (float*)d_out;

    k_qkv<<<512, 256>>>(x, wq, bq, wk, bk, wv, bv);        // 0
    k_slogits<<<dim3(8, 8, 32), 256>>>();                  // 1
    k_smax<<<4096, 256>>>();                               // 2
    k_as<<<dim3(8, 32), 256>>>();                          // 3  <- ncu capture slot
    k_zero<<<512, 256>>>();                                // 4
    k_cl<<<dim3(4, 32), 256>>>();                          // 5
    k_softmax_c<<<16, 256>>>();                            // 6
    k_ac<<<dim3(8, 32), 256>>>();                          // 7  (+= a_c)
    k_tconv<<<dim3(8, 32), 256>>>(wX, bX);                 // 8
    k_tl<<<dim3(64, 4), 256>>>();                          // 9
    k_softmax_t<<<1, 64>>>();                              // 10
    k_out<<<1024, 256>>>(out);                             // 11
}

// round 7
// speedup vs baseline: 1.3936x; 1.1445x over previous
#include <cuda_runtime.h>
#include <cuda_bf16.h>
#include <cstdint>

#define N_BT  32
#define HWD   1024
#define CHN   64
#define PLANE 65536      /* CHN*HWD */
#define TOT   2097152    /* N_BT*PLANE */

// ---- scratch (module-load allocated, legal) ----
__device__ __nv_bfloat16 g_qT16[TOT];  // [n][i][c]
__device__ __nv_bfloat16 g_kT16[TOT];  // [n][j][c]
__device__ float g_v [TOT];            // [n][c][i] fp32 (k_ac, k_out)
__device__ __nv_bfloat16 g_v16[TOT];   // [n][c][i] bf16 (k_as)
__device__ float g_A [TOT];            // a_s then += a_c   [n][c][i]
__device__ float g_Xe[TOT];            // [n][c][i]
__device__ float g_cl[N_BT * 64 * 64];
__device__ float g_tl[256];
__device__ __nv_bfloat16 g_L16[N_BT << 20]; // 64 MB spatial logits (bf16)
__device__ __nv_bfloat16 g_P16[N_BT << 20]; // 64 MB softmaxed probabilities (bf16)

__device__ __forceinline__ void mma_bf16(float* d, const uint32_t* a,
                                         uint32_t b0, uint32_t b1) {
    asm volatile(
        "mma.sync.aligned.m16n8k16.row.col.f32.bf16.bf16.f32 "
        "{%0,%1,%2,%3}, {%4,%5,%6,%7}, {%8,%9}, {%0,%1,%2,%3};\n"
        : "+f"(d[0]), "+f"(d[1]), "+f"(d[2]), "+f"(d[3])
        : "r"(a[0]), "r"(a[1]), "r"(a[2]), "r"(a[3]), "r"(b0), "r"(b1));
}

__device__ __forceinline__ void cp_async16(void* smem_dst, const void* gsrc) {
    uint32_t d = (uint32_t)__cvta_generic_to_shared(smem_dst);
    asm volatile("cp.async.cg.shared.global [%0], [%1], 16;\n" :: "r"(d), "l"(gsrc));
}
__device__ __forceinline__ void cp_commit() { asm volatile("cp.async.commit_group;\n"); }
__device__ __forceinline__ void cp_wait1()  { asm volatile("cp.async.wait_group 1;\n"); }
__device__ __forceinline__ void cp_wait0()  { asm volatile("cp.async.wait_group 0;\n"); }

// ============================================================
__global__ void k_zero() {
    int i = blockIdx.x * 256 + threadIdx.x;
    if (i < N_BT * 4096) g_cl[i] = 0.f;
    if (blockIdx.x == 0) g_tl[threadIdx.x] = 0.f;
}

// ---- QKV fused: relu(W x + b). q,k -> bf16 [n][i][c]; v -> fp32+bf16 [n][c][i] ----
__global__ void k_qkv(const float* __restrict__ x,
                      const float* __restrict__ wq, const float* __restrict__ bq,
                      const float* __restrict__ wk, const float* __restrict__ bk,
                      const float* __restrict__ wv, const float* __restrict__ bv) {
    __shared__ float sX[64][68];
    __shared__ float sW[64][68];
    int tid = threadIdx.x;
    int pt = blockIdx.x;
    int n  = pt >> 4;
    int i0 = (pt & 15) << 6;
    int b = n >> 3, t = n & 7;
    const float* ws[3] = {wq, wk, wv};
    const float* bs[3] = {bq, bk, bv};
    for (int idx = tid; idx < 4096; idx += 256) {
        int c = idx >> 6, p = idx & 63;
        sX[c][p] = x[((b * 64 + c) * 8 + t) * 1024 + i0 + p];
    }
    int tx = tid & 15, ty = tid >> 4;
    for (int ph = 0; ph < 3; ph++) {
        __syncthreads();
        for (int idx = tid; idx < 4096; idx += 256)
            sW[idx >> 6][idx & 63] = ws[ph][idx];
        __syncthreads();
        float acc[4][4] = {};
#pragma unroll
        for (int c = 0; c < 64; c++) {
            float4 a4 = *(const float4*)&sX[c][tx * 4];
            float ra[4] = {a4.x, a4.y, a4.z, a4.w};
            float rb[4];
#pragma unroll
            for (int v = 0; v < 4; v++) rb[v] = sW[ty * 4 + v][c];
#pragma unroll
            for (int v = 0; v < 4; v++)
#pragma unroll
                for (int u = 0; u < 4; u++) acc[v][u] = fmaf(rb[v], ra[u], acc[v][u]);
        }
#pragma unroll
        for (int v = 0; v < 4; v++) {
            float bb = bs[ph][ty * 4 + v];
#pragma unroll
            for (int u = 0; u < 4; u++) acc[v][u] = fmaxf(acc[v][u] + bb, 0.f);
        }
        if (ph == 2) {
#pragma unroll
            for (int v = 0; v < 4; v++)
#pragma unroll
                for (int u = 0; u < 4; u++) {
                    int a = n * PLANE + (ty * 4 + v) * HWD + i0 + tx * 4 + u;
                    g_v[a] = acc[v][u];
                    g_v16[a] = __float2bfloat16(acc[v][u]);
                }
        } else {
            __syncthreads();
#pragma unroll
            for (int v = 0; v < 4; v++)
#pragma unroll
                for (int u = 0; u < 4; u++)
                    sW[ty * 4 + v][tx * 4 + u] = acc[v][u];
            __syncthreads();
            __nv_bfloat16* outp = (ph == 0) ? g_qT16 : g_kT16;
            for (int idx = tid; idx < 4096; idx += 256) {
                int li = idx >> 6, o = idx & 63;
                outp[n * PLANE + (i0 + li) * 64 + o] = __float2bfloat16(sW[o][li]);
            }
        }
    }
}

// ---- spatial logits via bf16 MMA: L[n,i,j] = sum_c q[i,c] k[j,c] -> bf16 ----
__global__ void k_slogits() {
    __shared__ __align__(16) __nv_bfloat16 sQK[2][128][72];   // [0]=Q rows, [1]=K rows
    int jt = blockIdx.x, it = blockIdx.y, n = blockIdx.z;
    int tid = threadIdx.x;
    const __nv_bfloat16* qb = g_qT16 + n * PLANE + (it * 128) * 64;
    const __nv_bfloat16* kb = g_kT16 + n * PLANE + (jt * 128) * 64;

#pragma unroll
    for (int v = 0; v < 8; v++) {
        int e = tid + v * 256;
        int row = e >> 3;
        int p8 = (e & 7) * 8;
        const __nv_bfloat16* src = (row < 128) ? (qb + row * 64 + p8)
                                               : (kb + (row - 128) * 64 + p8);
        cp_async16(&sQK[row >> 7][row & 127][p8], src);
    }
    cp_commit(); cp_wait0();
    __syncthreads();

    int warp = tid >> 5, lane = tid & 31;
    int r = lane >> 2, cc = lane & 3;
    int wi = (warp & 3) * 32;
    int wj = (warp >> 2) * 64;
    float acc[2][8][4] = {};

#pragma unroll
    for (int ks = 0; ks < 4; ks++) {
        int kk = ks * 16;
        uint32_t a[2][4];
#pragma unroll
        for (int m = 0; m < 2; m++) {
            int i0 = wi + m * 16;
            a[m][0] = *(const uint32_t*)&sQK[0][i0 + r][kk + 2 * cc];
            a[m][1] = *(const uint32_t*)&sQK[0][i0 + r + 8][kk + 2 * cc];
            a[m][2] = *(const uint32_t*)&sQK[0][i0 + r][kk + 2 * cc + 8];
            a[m][3] = *(const uint32_t*)&sQK[0][i0 + r + 8][kk + 2 * cc + 8];
        }
#pragma unroll
        for (int t = 0; t < 8; t++) {
            uint32_t b0 = *(const uint32_t*)&sQK[1][wj + t * 8 + r][kk + 2 * cc];
            uint32_t b1 = *(const uint32_t*)&sQK[1][wj + t * 8 + r][kk + 2 * cc + 8];
#pragma unroll
            for (int m = 0; m < 2; m++) mma_bf16(acc[m][t], a[m], b0, b1);
        }
    }

    __syncthreads();
    uint32_t (*stg)[68] = (uint32_t(*)[68])sQK;
#pragma unroll
    for (int m = 0; m < 2; m++)
#pragma unroll
        for (int t = 0; t < 8; t++) {
            int rowl = wi + m * 16 + r;
            int colw = (wj + t * 8) / 2 + cc;
            __nv_bfloat162 lo = __floats2bfloat162_rn(acc[m][t][0], acc[m][t][1]);
            __nv_bfloat162 hi = __floats2bfloat162_rn(acc[m][t][2], acc[m][t][3]);
            stg[rowl][colw]     = *(uint32_t*)&lo;
            stg[rowl + 8][colw] = *(uint32_t*)&hi;
        }
    __syncthreads();
#pragma unroll
    for (int v = 0; v < 8; v++) {
        int e = tid + v * 256;
        int row = e >> 4, q = e & 15;
        uint4 val = *(uint4*)&stg[row][q * 4];
        __nv_bfloat16* dst = g_L16 + ((size_t)n << 20) + (it * 128 + row) * 1024
                             + jt * 128 + q * 8;
        *(uint4*)dst = val;
    }
}

// ---- per-(i,j) softmax over n: write P = exp(l-mx)/sum directly (bf16) ----
__global__ void k_smax() {
    int idx = blockIdx.x * 256 + threadIdx.x;
    float vals[32], mx = -1e30f;
#pragma unroll
    for (int nn = 0; nn < 32; nn++) {
        vals[nn] = __bfloat162float(g_L16[((size_t)nn << 20) + idx]);
        mx = fmaxf(mx, vals[nn]);
    }
    float s = 0.f;
#pragma unroll
    for (int nn = 0; nn < 32; nn++) { vals[nn] = __expf(vals[nn] - mx); s += vals[nn]; }
    float inv = 1.f / s;
#pragma unroll
    for (int nn = 0; nn < 32; nn++)
        g_P16[((size_t)nn << 20) + idx] = __float2bfloat16(vals[nn] * inv);
}

// ---- a_s = V @ P^T via bf16 MMA; pure GEMM, 3-stage pipeline, 1 sync/chunk ----
// grid (it8, n32); block: c64 (M) x i128 (N), K=1024 over j, chunk 32.
__global__ void __launch_bounds__(256, 2) k_as() {
    __shared__ __nv_bfloat16 sP[3][128][40];   // B: [i][j-chunk]
    __shared__ __nv_bfloat16 sV[3][64][40];    // A: [c][j-chunk]
    int it = blockIdx.x, n = blockIdx.y;
    int tid = threadIdx.x;
    const __nv_bfloat16* vb = g_v16 + n * PLANE;
    const __nv_bfloat16* pb = g_P16 + ((size_t)n << 20) + (it * 128) * 1024;

    auto stage = [&](int ch) {
        int s = ch % 3;
        int j0 = ch * 32;
#pragma unroll
        for (int v = 0; v < 2; v++) {
            int e = tid + v * 256;       // 0..511
            int row = e >> 2;
            int p8 = (e & 3) * 8;
            cp_async16(&sP[s][row][p8], pb + row * 1024 + j0 + p8);
        }
        {
            int row = tid >> 2;
            int p8 = (tid & 3) * 8;
            cp_async16(&sV[s][row][p8], vb + row * 1024 + j0 + p8);
        }
        cp_commit();
    };
    stage(0); stage(1);

    int warp = tid >> 5, lane = tid & 31;
    int r = lane >> 2, cc = lane & 3;
    int wc = (warp & 1) * 32;            // 2 warps along c (M)
    int wi = (warp >> 1) * 32;           // 4 warps along i (N)
    float acc[2][4][4] = {};

    for (int ch = 0; ch < 32; ch++) {
        cp_wait1();
        __syncthreads();
        if (ch + 2 < 32) stage(ch + 2);  // buf (ch+2)%3: != ch%3, != (ch+1)%3
        else cp_commit();
        int s = ch % 3;
#pragma unroll
        for (int ks = 0; ks < 2; ks++) {
            int kk = ks * 16;
            uint32_t a[2][4];
#pragma unroll
            for (int m = 0; m < 2; m++) {
                int c0 = wc + m * 16;
                a[m][0] = *(const uint32_t*)&sV[s][c0 + r][kk + 2 * cc];
                a[m][1] = *(const uint32_t*)&sV[s][c0 + r + 8][kk + 2 * cc];
                a[m][2] = *(const uint32_t*)&sV[s][c0 + r][kk + 2 * cc + 8];
                a[m][3] = *(const uint32_t*)&sV[s][c0 + r + 8][kk + 2 * cc + 8];
            }
#pragma unroll
            for (int t = 0; t < 4; t++) {
                uint32_t b0 = *(const uint32_t*)&sP[s][wi + t * 8 + r][kk + 2 * cc];
                uint32_t b1 = *(const uint32_t*)&sP[s][wi + t * 8 + r][kk + 2 * cc + 8];
#pragma unroll
                for (int m = 0; m < 2; m++) mma_bf16(acc[m][t], a[m], b0, b1);
            }
        }
    }
#pragma unroll
    for (int m = 0; m < 2; m++)
#pragma unroll
        for (int t = 0; t < 4; t++) {
            int c0 = wc + m * 16 + r;
            int i0 = it * 128 + wi + t * 8 + cc * 2;
            float2 o0 = {acc[m][t][0], acc[m][t][1]};
            float2 o1 = {acc[m][t][2], acc[m][t][3]};
            *(float2*)&g_A[n * PLANE + c0 * HWD + i0] = o0;
            *(float2*)&g_A[n * PLANE + (c0 + 8) * HWD + i0] = o1;
        }
}

// ---- channel logits (split-k atomics), bf16 inputs ----
__global__ void k_cl() {
    __shared__ float sQT[64][68];
    __shared__ float sKT[64][68];
    int n = blockIdx.y;
    int tid = threadIdx.x, tx = tid & 15, ty = tid >> 4;
    float acc[4][4] = {};
    for (int sub = 0; sub < 4; sub++) {
        int k0 = blockIdx.x * 256 + sub * 64;
        __syncthreads();
        for (int idx = tid; idx < 4096; idx += 256) {
            int kk = idx >> 6, c = idx & 63;
            sQT[kk][c] = __bfloat162float(g_qT16[n * PLANE + (k0 + kk) * 64 + c]);
            sKT[kk][c] = __bfloat162float(g_kT16[n * PLANE + (k0 + kk) * 64 + c]);
        }
        __syncthreads();
#pragma unroll 16
        for (int kk = 0; kk < 64; kk++) {
            float ra[4], rb[4];
#pragma unroll
            for (int v = 0; v < 4; v++) ra[v] = sQT[kk][ty * 4 + v];
#pragma unroll
            for (int u = 0; u < 4; u++) rb[u] = sKT[kk][tx * 4 + u];
#pragma unroll
            for (int v = 0; v < 4; v++)
#pragma unroll
                for (int u = 0; u < 4; u++) acc[v][u] = fmaf(ra[v], rb[u], acc[v][u]);
        }
    }
#pragma unroll
    for (int v = 0; v < 4; v++)
#pragma unroll
        for (int u = 0; u < 4; u++)
            atomicAdd(&g_cl[n * 4096 + (ty * 4 + v) * 64 + tx * 4 + u], acc[v][u]);
}

// ---- softmax over n on (n,c,d) ----
__global__ void k_softmax_c() {
    int p = blockIdx.x * 256 + threadIdx.x;
    float vals[32], mx = -1e30f;
#pragma unroll
    for (int nn = 0; nn < 32; nn++) { vals[nn] = g_cl[nn * 4096 + p]; mx = fmaxf(mx, vals[nn]); }
    float s = 0.f;
#pragma unroll
    for (int nn = 0; nn < 32; nn++) { vals[nn] = __expf(vals[nn] - mx); s += vals[nn]; }
    float inv = 1.f / s;
#pragma unroll
    for (int nn = 0; nn < 32; nn++) g_cl[nn * 4096 + p] = vals[nn] * inv;
}

// ---- a_c: g_A += m_c @ v ----
__global__ void k_ac() {
    __shared__ float sM[64][65];
    __shared__ float sV[32][128];
    int n = blockIdx.y, it = blockIdx.x;
    int tid = threadIdx.x, tx = tid & 15, ty = tid >> 4;
    for (int idx = tid; idx < 4096; idx += 256)
        sM[idx >> 6][idx & 63] = g_cl[n * 4096 + idx];
    float acc[4][8] = {};
    for (int dh = 0; dh < 2; dh++) {
        __syncthreads();
        for (int idx4 = tid; idx4 < 1024; idx4 += 256) {
            int d = idx4 >> 5, ii = (idx4 & 31) << 2;
            *(float4*)&sV[d][ii] =
                *(const float4*)&g_v[n * PLANE + (dh * 32 + d) * HWD + it * 128 + ii];
        }
        __syncthreads();
#pragma unroll 8
        for (int d = 0; d < 32; d++) {
            float rm[4];
#pragma unroll
            for (int v = 0; v < 4; v++) rm[v] = sM[ty * 4 + v][dh * 32 + d];
            float4 va = *(const float4*)&sV[d][tx * 8];
            float4 vb = *(const float4*)&sV[d][tx * 8 + 4];
            float rv[8] = {va.x, va.y, va.z, va.w, vb.x, vb.y, vb.z, vb.w};
#pragma unroll
            for (int v = 0; v < 4; v++)
#pragma unroll
                for (int u = 0; u < 8; u++) acc[v][u] = fmaf(rm[v], rv[u], acc[v][u]);
        }
    }
#pragma unroll
    for (int v = 0; v < 4; v++)
#pragma unroll
        for (int u = 0; u < 8; u++) {
            int a = n * PLANE + (ty * 4 + v) * HWD + it * 128 + tx * 8 + u;
            g_A[a] = g_A[a] + acc[v][u];
        }
}

// ---- temporal conv (3,1,1) pad 1 + relu -> g_Xe ----
__global__ void k_tconv(const float* __restrict__ wX, const float* __restrict__ bX) {
    __shared__ float sA[32][132];
    __shared__ float sW[64][68];
    int n = blockIdx.y, it = blockIdx.x;
    int b = n >> 3, t = n & 7;
    int tid = threadIdx.x, tx = tid & 15, ty = tid >> 4;
    float acc[4][8] = {};
    for (int kk = 0; kk < 3; kk++) {
        int tp = t + kk - 1;
        if (tp < 0 || tp >= 8) continue;
        __syncthreads();
        for (int idx = tid; idx < 4096; idx += 256) {
            int o = idx >> 6, c = idx & 63;
            sW[o][c] = wX[o * 192 + c * 3 + kk];
        }
        for (int ch = 0; ch < 2; ch++) {
            __syncthreads();
            for (int idx4 = tid; idx4 < 1024; idx4 += 256) {
                int c = idx4 >> 5, ii = (idx4 & 31) << 2;
                *(float4*)&sA[c][ii] =
                    *(const float4*)&g_A[(b * 8 + tp) * PLANE + (ch * 32 + c) * HWD + it * 128 + ii];
            }
            __syncthreads();
#pragma unroll 4
            for (int c = 0; c < 32; c++) {
                float rw[4];
#pragma unroll
                for (int v = 0; v < 4; v++) rw[v] = sW[ty * 4 + v][ch * 32 + c];
                float4 aa = *(const float4*)&sA[c][tx * 8];
                float4 ab = *(const float4*)&sA[c][tx * 8 + 4];
                float ra[8] = {aa.x, aa.y, aa.z, aa.w, ab.x, ab.y, ab.z, ab.w};
#pragma unroll
                for (int v = 0; v < 4; v++)
#pragma unroll
                    for (int u = 0; u < 8; u++) acc[v][u] = fmaf(rw[v], ra[u], acc[v][u]);
            }
        }
    }
#pragma unroll
    for (int v = 0; v < 4; v++) {
        float bb = bX[ty * 4 + v];
#pragma unroll
        for (int u = 0; u < 8; u++)
            g_Xe[n * PLANE + (ty * 4 + v) * HWD + it * 128 + tx * 8 + u] =
                fmaxf(acc[v][u] + bb, 0.f);
    }
}

// ---- temporal Gram: g_tl[b,t,s] += partial dot over d-slice ----
__global__ void k_tl() {
    __shared__ float sXe[8][1032];
    int b = blockIdx.y;
    int d0 = blockIdx.x * 1024;
    int tid = threadIdx.x;
    for (int v = 0; v < 8; v++) {
        int e = tid + v * 256;
        int t = e >> 8;
        int d4 = (e & 255) * 4;
        *(float4*)&sXe[t][d4] = *(const float4*)&g_Xe[(b * 8 + t) * PLANE + d0 + d4];
    }
    __syncthreads();
    int p = tid >> 2, sub = tid & 3;
    int t = p >> 3, s = p & 7;
    float acc = 0.f;
#pragma unroll 8
    for (int it = 0; it < 64; it++) {
        int col = sub * 4 + it * 16;
        float4 a = *(const float4*)&sXe[t][col];
        float4 c = *(const float4*)&sXe[s][col];
        acc += a.x * c.x + a.y * c.y + a.z * c.z + a.w * c.w;
    }
    acc += __shfl_xor_sync(0xffffffff, acc, 1);
    acc += __shfl_xor_sync(0xffffffff, acc, 2);
    if (sub == 0) atomicAdd(&g_tl[b * 64 + p], acc);
}

__global__ void k_softmax_t() {
    int p = threadIdx.x;
    float v0 = g_tl[p], v1 = g_tl[64 + p], v2 = g_tl[128 + p], v3 = g_tl[192 + p];
    float mx = fmaxf(fmaxf(v0, v1), fmaxf(v2, v3));
    v0 = __expf(v0 - mx); v1 = __expf(v1 - mx); v2 = __expf(v2 - mx); v3 = __expf(v3 - mx);
    float inv = 1.f / (v0 + v1 + v2 + v3);
    g_tl[p] = v0 * inv; g_tl[64 + p] = v1 * inv;
    g_tl[128 + p] = v2 * inv; g_tl[192 + p] = v3 * inv;
}

__global__ void k_out(float* __restrict__ out) {
    __shared__ float sM[64];
    int gid = blockIdx.x * 256 + threadIdx.x;
    int b = gid >> 16;
    if (threadIdx.x < 64) sM[threadIdx.x] = g_tl[b * 64 + threadIdx.x];
    __syncthreads();
    int rem = gid & 65535;
    int c = rem >> 10, i = rem & 1023;
    float vv[8];
#pragma unroll
    for (int s = 0; s < 8; s++) vv[s] = g_v[(b * 8 + s) * PLANE + c * HWD + i];
#pragma unroll
    for (int t = 0; t < 8; t++) {
        float rsum = 0.f;
#pragma unroll
        for (int s = 0; s < 8; s++) rsum = fmaf(sM[t * 8 + s], vv[s], rsum);
        out[((b * 64 + c) * 8 + t) * HWD + i] = rsum;
    }
}

// ============================================================
extern "C" void kernel_launch(void* const* d_in, const int* in_sizes, int n_in,
                              void* d_out, int out_size) {
    const float* x  = (const float*)d_in[0];
    const float* wq = (const float*)d_in[1];
    const float* bq = (const float*)d_in[2];
    const float* wk = (const float*)d_in[3];
    const float* bk = (const float*)d_in[4];
    const float* wv = (const float*)d_in[5];
    const float* bv = (const float*)d_in[6];
    const float* wX = (const float*)d_in[7];
    const float* bX = (const float*)d_in[8];
    float* out = (float*)d_out;

    k_qkv<<<512, 256>>>(x, wq, bq, wk, bk, wv, bv);        // 0
    k_slogits<<<dim3(8, 8, 32), 256>>>();                  // 1
    k_smax<<<4096, 256>>>();                               // 2
    k_as<<<dim3(8, 32), 256>>>();                          // 3  <- ncu capture slot
    k_zero<<<512, 256>>>();                                // 4
    k_cl<<<dim3(4, 32), 256>>>();                          // 5
    k_softmax_c<<<16, 256>>>();                            // 6
    k_ac<<<dim3(8, 32), 256>>>();                          // 7  (+= a_c)
    k_tconv<<<dim3(8, 32), 256>>>(wX, bX);                 // 8
    k_tl<<<dim3(64, 4), 256>>>();                          // 9
    k_softmax_t<<<1, 64>>>();                              // 10
    k_out<<<1024, 256>>>(out);                             // 11
}

// round 9
// speedup vs baseline: 1.5556x; 1.1162x over previous
#include <cuda_runtime.h>
#include <cuda_bf16.h>
#include <cstdint>

#define N_BT  32
#define HWD   1024
#define CHN   64
#define PLANE 65536      /* CHN*HWD */
#define TOT   2097152    /* N_BT*PLANE */

// ---- scratch (module-load allocated, legal) ----
__device__ __nv_bfloat16 g_qT16[TOT];  // [n][i][c]
__device__ __nv_bfloat16 g_kT16[TOT];  // [n][j][c]
__device__ float g_v [TOT];            // [n][c][i] fp32 (k_out)
__device__ __nv_bfloat16 g_v16[TOT];   // [n][c][i] bf16 (k_as A)
__device__ __nv_bfloat16 g_vT16[TOT];  // [n][i][c] bf16 (k_as a_c epilogue B)
__device__ __nv_bfloat16 g_A16[TOT];   // a_s + a_c   [n][c][i] bf16
__device__ float g_Xe[TOT];            // [n][c][i]
__device__ float g_cl[N_BT * 64 * 64];
__device__ __nv_bfloat16 g_mc16[N_BT * 64 * 64];  // m_c bf16 [n][c][d]
__device__ float g_tl[256];
__device__ __nv_bfloat16 g_L16[N_BT << 20]; // 64 MB spatial logits (bf16)
__device__ __nv_bfloat16 g_P16[N_BT << 20]; // 64 MB softmaxed probabilities (bf16)

__device__ __forceinline__ void mma_bf16(float* d, const uint32_t* a,
                                         uint32_t b0, uint32_t b1) {
    asm volatile(
        "mma.sync.aligned.m16n8k16.row.col.f32.bf16.bf16.f32 "
        "{%0,%1,%2,%3}, {%4,%5,%6,%7}, {%8,%9}, {%0,%1,%2,%3};\n"
        : "+f"(d[0]), "+f"(d[1]), "+f"(d[2]), "+f"(d[3])
        : "r"(a[0]), "r"(a[1]), "r"(a[2]), "r"(a[3]), "r"(b0), "r"(b1));
}

__device__ __forceinline__ void cp_async16(void* smem_dst, const void* gsrc) {
    uint32_t d = (uint32_t)__cvta_generic_to_shared(smem_dst);
    asm volatile("cp.async.cg.shared.global [%0], [%1], 16;\n" :: "r"(d), "l"(gsrc));
}
__device__ __forceinline__ void cp_commit() { asm volatile("cp.async.commit_group;\n"); }
__device__ __forceinline__ void cp_wait1()  { asm volatile("cp.async.wait_group 1;\n"); }
__device__ __forceinline__ void cp_wait0()  { asm volatile("cp.async.wait_group 0;\n"); }

// ============================================================
// ---- QKV fused: relu(W x + b). q,k -> bf16 [n][i][c]; v -> fp32/bf16 [n][c][i]
//      + transposed vT bf16 [n][i][c]; also zeroes g_cl / g_tl.
__global__ void k_qkv(const float* __restrict__ x,
                      const float* __restrict__ wq, const float* __restrict__ bq,
                      const float* __restrict__ wk, const float* __restrict__ bk,
                      const float* __restrict__ wv, const float* __restrict__ bv) {
    __shared__ float sX[64][68];
    __shared__ float sW[64][68];
    int tid = threadIdx.x;
    int pt = blockIdx.x;
    g_cl[pt * 256 + tid] = 0.f;                 // 512*256 == 32*4096
    if (pt == 0) g_tl[tid] = 0.f;
    int n  = pt >> 4;
    int i0 = (pt & 15) << 6;
    int b = n >> 3, t = n & 7;
    const float* ws[3] = {wq, wk, wv};
    const float* bs[3] = {bq, bk, bv};
    for (int idx = tid; idx < 4096; idx += 256) {
        int c = idx >> 6, p = idx & 63;
        sX[c][p] = x[((b * 64 + c) * 8 + t) * 1024 + i0 + p];
    }
    int tx = tid & 15, ty = tid >> 4;
    for (int ph = 0; ph < 3; ph++) {
        __syncthreads();
        for (int idx = tid; idx < 4096; idx += 256)
            sW[idx >> 6][idx & 63] = ws[ph][idx];
        __syncthreads();
        float acc[4][4] = {};
#pragma unroll
        for (int c = 0; c < 64; c++) {
            float4 a4 = *(const float4*)&sX[c][tx * 4];
            float ra[4] = {a4.x, a4.y, a4.z, a4.w};
            float rb[4];
#pragma unroll
            for (int v = 0; v < 4; v++) rb[v] = sW[ty * 4 + v][c];
#pragma unroll
            for (int v = 0; v < 4; v++)
#pragma unroll
                for (int u = 0; u < 4; u++) acc[v][u] = fmaf(rb[v], ra[u], acc[v][u]);
        }
#pragma unroll
        for (int v = 0; v < 4; v++) {
            float bb = bs[ph][ty * 4 + v];
#pragma unroll
            for (int u = 0; u < 4; u++) acc[v][u] = fmaxf(acc[v][u] + bb, 0.f);
        }
        if (ph == 2) {
            // direct [c][i] stores (fp32 + bf16)
#pragma unroll
            for (int v = 0; v < 4; v++)
#pragma unroll
                for (int u = 0; u < 4; u++) {
                    int a = n * PLANE + (ty * 4 + v) * HWD + i0 + tx * 4 + u;
                    g_v[a] = acc[v][u];
                    g_v16[a] = __float2bfloat16(acc[v][u]);
                }
            // transpose -> vT [i][c]
            __syncthreads();
#pragma unroll
            for (int v = 0; v < 4; v++)
#pragma unroll
                for (int u = 0; u < 4; u++)
                    sW[ty * 4 + v][tx * 4 + u] = acc[v][u];
            __syncthreads();
            for (int idx = tid; idx < 4096; idx += 256) {
                int li = idx >> 6, o = idx & 63;
                g_vT16[n * PLANE + (i0 + li) * 64 + o] = __float2bfloat16(sW[o][li]);
            }
        } else {
            __syncthreads();
#pragma unroll
            for (int v = 0; v < 4; v++)
#pragma unroll
                for (int u = 0; u < 4; u++)
                    sW[ty * 4 + v][tx * 4 + u] = acc[v][u];
            __syncthreads();
            __nv_bfloat16* outp = (ph == 0) ? g_qT16 : g_kT16;
            for (int idx = tid; idx < 4096; idx += 256) {
                int li = idx >> 6, o = idx & 63;
                outp[n * PLANE + (i0 + li) * 64 + o] = __float2bfloat16(sW[o][li]);
            }
        }
    }
}

// ---- spatial logits via bf16 MMA: L[n,i,j] = sum_c q[i,c] k[j,c] -> bf16 ----
__global__ void k_slogits() {
    __shared__ __align__(16) __nv_bfloat16 sQK[2][128][72];
    int jt = blockIdx.x, it = blockIdx.y, n = blockIdx.z;
    int tid = threadIdx.x;
    const __nv_bfloat16* qb = g_qT16 + n * PLANE + (it * 128) * 64;
    const __nv_bfloat16* kb = g_kT16 + n * PLANE + (jt * 128) * 64;

#pragma unroll
    for (int v = 0; v < 8; v++) {
        int e = tid + v * 256;
        int row = e >> 3;
        int p8 = (e & 7) * 8;
        const __nv_bfloat16* src = (row < 128) ? (qb + row * 64 + p8)
                                               : (kb + (row - 128) * 64 + p8);
        cp_async16(&sQK[row >> 7][row & 127][p8], src);
    }
    cp_commit(); cp_wait0();
    __syncthreads();

    int warp = tid >> 5, lane = tid & 31;
    int r = lane >> 2, cc = lane & 3;
    int wi = (warp & 3) * 32;
    int wj = (warp >> 2) * 64;
    float acc[2][8][4] = {};

#pragma unroll
    for (int ks = 0; ks < 4; ks++) {
        int kk = ks * 16;
        uint32_t a[2][4];
#pragma unroll
        for (int m = 0; m < 2; m++) {
            int i0 = wi + m * 16;
            a[m][0] = *(const uint32_t*)&sQK[0][i0 + r][kk + 2 * cc];
            a[m][1] = *(const uint32_t*)&sQK[0][i0 + r + 8][kk + 2 * cc];
            a[m][2] = *(const uint32_t*)&sQK[0][i0 + r][kk + 2 * cc + 8];
            a[m][3] = *(const uint32_t*)&sQK[0][i0 + r + 8][kk + 2 * cc + 8];
        }
#pragma unroll
        for (int t = 0; t < 8; t++) {
            uint32_t b0 = *(const uint32_t*)&sQK[1][wj + t * 8 + r][kk + 2 * cc];
            uint32_t b1 = *(const uint32_t*)&sQK[1][wj + t * 8 + r][kk + 2 * cc + 8];
#pragma unroll
            for (int m = 0; m < 2; m++) mma_bf16(acc[m][t], a[m], b0, b1);
        }
    }

    __syncthreads();
    uint32_t (*stg)[68] = (uint32_t(*)[68])sQK;
#pragma unroll
    for (int m = 0; m < 2; m++)
#pragma unroll
        for (int t = 0; t < 8; t++) {
            int rowl = wi + m * 16 + r;
            int colw = (wj + t * 8) / 2 + cc;
            __nv_bfloat162 lo = __floats2bfloat162_rn(acc[m][t][0], acc[m][t][1]);
            __nv_bfloat162 hi = __floats2bfloat162_rn(acc[m][t][2], acc[m][t][3]);
            stg[rowl][colw]     = *(uint32_t*)&lo;
            stg[rowl + 8][colw] = *(uint32_t*)&hi;
        }
    __syncthreads();
#pragma unroll
    for (int v = 0; v < 8; v++) {
        int e = tid + v * 256;
        int row = e >> 4, q = e & 15;
        uint4 val = *(uint4*)&stg[row][q * 4];
        __nv_bfloat16* dst = g_L16 + ((size_t)n << 20) + (it * 128 + row) * 1024
                             + jt * 128 + q * 8;
        *(uint4*)dst = val;
    }
}

// ---- per-(i,j) softmax over n -> P bf16. 4 idx per thread, uint2 I/O ----
__global__ void k_smax() {
    int base = (blockIdx.x * 256 + threadIdx.x) * 4;
    uint2 raw[32];
#pragma unroll
    for (int nn = 0; nn < 32; nn++)
        raw[nn] = *(const uint2*)&g_L16[((size_t)nn << 20) + base];
    float mx[4] = {-1e30f, -1e30f, -1e30f, -1e30f};
#pragma unroll
    for (int nn = 0; nn < 32; nn++) {
        float2 f0 = __bfloat1622float2(*(__nv_bfloat162*)&raw[nn].x);
        float2 f1 = __bfloat1622float2(*(__nv_bfloat162*)&raw[nn].y);
        mx[0] = fmaxf(mx[0], f0.x); mx[1] = fmaxf(mx[1], f0.y);
        mx[2] = fmaxf(mx[2], f1.x); mx[3] = fmaxf(mx[3], f1.y);
    }
    float s[4] = {0.f, 0.f, 0.f, 0.f};
#pragma unroll
    for (int nn = 0; nn < 32; nn++) {
        float2 f0 = __bfloat1622float2(*(__nv_bfloat162*)&raw[nn].x);
        float2 f1 = __bfloat1622float2(*(__nv_bfloat162*)&raw[nn].y);
        s[0] += __expf(f0.x - mx[0]); s[1] += __expf(f0.y - mx[1]);
        s[2] += __expf(f1.x - mx[2]); s[3] += __expf(f1.y - mx[3]);
    }
    float inv[4] = {1.f / s[0], 1.f / s[1], 1.f / s[2], 1.f / s[3]};
#pragma unroll
    for (int nn = 0; nn < 32; nn++) {
        float2 f0 = __bfloat1622float2(*(__nv_bfloat162*)&raw[nn].x);
        float2 f1 = __bfloat1622float2(*(__nv_bfloat162*)&raw[nn].y);
        __nv_bfloat162 p0 = __floats2bfloat162_rn(__expf(f0.x - mx[0]) * inv[0],
                                                  __expf(f0.y - mx[1]) * inv[1]);
        __nv_bfloat162 p1 = __floats2bfloat162_rn(__expf(f1.x - mx[2]) * inv[2],
                                                  __expf(f1.y - mx[3]) * inv[3]);
        uint2 o; o.x = *(uint32_t*)&p0; o.y = *(uint32_t*)&p1;
        *(uint2*)&g_P16[((size_t)nn << 20) + base] = o;
    }
}

// ---- a_s = V @ P^T + a_c = m_c @ v  (bf16 MMA); g_A16 = result (bf16) ----
// grid (it8, n32); block: c64 (M) x i128 (N).
__global__ void __launch_bounds__(256, 2) k_as() {
    __shared__ __align__(16) char sbuf[46080];
    __nv_bfloat16 (*sP)[40] = (__nv_bfloat16(*)[40])sbuf;            // [3][128][40]
    __nv_bfloat16 (*sV)[40] = (__nv_bfloat16(*)[40])(sbuf + 30720);  // [3][64][40]
    int it = blockIdx.x, n = blockIdx.y;
    int tid = threadIdx.x;
    const __nv_bfloat16* vb = g_v16 + n * PLANE;
    const __nv_bfloat16* pb = g_P16 + ((size_t)n << 20) + (it * 128) * 1024;

    auto stage = [&](int ch) {
        int s = ch % 3;
        int j0 = ch * 32;
#pragma unroll
        for (int v = 0; v < 2; v++) {
            int e = tid + v * 256;
            int row = e >> 2;
            int p8 = (e & 3) * 8;
            cp_async16(&sP[s * 128 + row][p8], pb + row * 1024 + j0 + p8);
        }
        {
            int row = tid >> 2;
            int p8 = (tid & 3) * 8;
            cp_async16(&sV[s * 64 + row][p8], vb + row * 1024 + j0 + p8);
        }
        cp_commit();
    };
    stage(0); stage(1);

    int warp = tid >> 5, lane = tid & 31;
    int r = lane >> 2, cc = lane & 3;
    int wc = (warp & 1) * 32;            // 2 warps along c (M)
    int wi = (warp >> 1) * 32;           // 4 warps along i (N)
    float acc[2][4][4] = {};

    for (int ch = 0; ch < 32; ch++) {
        cp_wait1();
        __syncthreads();
        if (ch + 2 < 32) stage(ch + 2);
        else cp_commit();
        int s = ch % 3;
#pragma unroll
        for (int ks = 0; ks < 2; ks++) {
            int kk = ks * 16;
            uint32_t a[2][4];
#pragma unroll
            for (int m = 0; m < 2; m++) {
                int c0 = wc + m * 16;
                a[m][0] = *(const uint32_t*)&sV[s * 64 + c0 + r][kk + 2 * cc];
                a[m][1] = *(const uint32_t*)&sV[s * 64 + c0 + r + 8][kk + 2 * cc];
                a[m][2] = *(const uint32_t*)&sV[s * 64 + c0 + r][kk + 2 * cc + 8];
                a[m][3] = *(const uint32_t*)&sV[s * 64 + c0 + r + 8][kk + 2 * cc + 8];
            }
#pragma unroll
            for (int t = 0; t < 4; t++) {
                uint32_t b0 = *(const uint32_t*)&sP[s * 128 + wi + t * 8 + r][kk + 2 * cc];
                uint32_t b1 = *(const uint32_t*)&sP[s * 128 + wi + t * 8 + r][kk + 2 * cc + 8];
#pragma unroll
                for (int m = 0; m < 2; m++) mma_bf16(acc[m][t], a[m], b0, b1);
            }
        }
    }

    // ---- a_c epilogue: acc += m_c[n] @ vT (K = 64 channels d) ----
    cp_wait0();
    __syncthreads();                      // buffers now reusable
    __nv_bfloat16 (*sMc)[72] = (__nv_bfloat16(*)[72])sbuf;           // [64][72]
    __nv_bfloat16 (*sVT)[72] = (__nv_bfloat16(*)[72])(sbuf + 9216);  // [128][72]
#pragma unroll
    for (int v = 0; v < 2; v++) {         // m_c: 64x64 bf16 = 512 x 16B
        int e = tid + v * 256;
        int row = e >> 3, p8 = (e & 7) * 8;
        cp_async16(&sMc[row][p8], g_mc16 + n * 4096 + row * 64 + p8);
    }
#pragma unroll
    for (int v = 0; v < 4; v++) {         // vT tile: 128x64 bf16 = 1024 x 16B
        int e = tid + v * 256;
        int row = e >> 3, p8 = (e & 7) * 8;
        cp_async16(&sVT[row][p8], g_vT16 + n * PLANE + (it * 128 + row) * 64 + p8);
    }
    cp_commit(); cp_wait0();
    __syncthreads();
#pragma unroll
    for (int ks = 0; ks < 4; ks++) {
        int kk = ks * 16;
        uint32_t a[2][4];
#pragma unroll
        for (int m = 0; m < 2; m++) {
            int c0 = wc + m * 16;
            a[m][0] = *(const uint32_t*)&sMc[c0 + r][kk + 2 * cc];
            a[m][1] = *(const uint32_t*)&sMc[c0 + r + 8][kk + 2 * cc];
            a[m][2] = *(const uint32_t*)&sMc[c0 + r][kk + 2 * cc + 8];
            a[m][3] = *(const uint32_t*)&sMc[c0 + r + 8][kk + 2 * cc + 8];
        }
#pragma unroll
        for (int t = 0; t < 4; t++) {
            uint32_t b0 = *(const uint32_t*)&sVT[wi + t * 8 + r][kk + 2 * cc];
            uint32_t b1 = *(const uint32_t*)&sVT[wi + t * 8 + r][kk + 2 * cc + 8];
#pragma unroll
            for (int m = 0; m < 2; m++) mma_bf16(acc[m][t], a[m], b0, b1);
        }
    }

    // ---- store bf16 ----
#pragma unroll
    for (int m = 0; m < 2; m++)
#pragma unroll
        for (int t = 0; t < 4; t++) {
            int c0 = wc + m * 16 + r;
            int i0 = it * 128 + wi + t * 8 + cc * 2;
            __nv_bfloat162 p0 = __floats2bfloat162_rn(acc[m][t][0], acc[m][t][1]);
            __nv_bfloat162 p1 = __floats2bfloat162_rn(acc[m][t][2], acc[m][t][3]);
            *(uint32_t*)&g_A16[n * PLANE + c0 * HWD + i0] = *(uint32_t*)&p0;
            *(uint32_t*)&g_A16[n * PLANE + (c0 + 8) * HWD + i0] = *(uint32_t*)&p1;
        }
}

// ---- channel logits (split-k atomics), bf16 inputs ----
__global__ void k_cl() {
    __shared__ float sQT[64][68];
    __shared__ float sKT[64][68];
    int n = blockIdx.y;
    int tid = threadIdx.x, tx = tid & 15, ty = tid >> 4;
    float acc[4][4] = {};
    for (int sub = 0; sub < 4; sub++) {
        int k0 = blockIdx.x * 256 + sub * 64;
        __syncthreads();
        for (int idx = tid; idx < 4096; idx += 256) {
            int kk = idx >> 6, c = idx & 63;
            sQT[kk][c] = __bfloat162float(g_qT16[n * PLANE + (k0 + kk) * 64 + c]);
            sKT[kk][c] = __bfloat162float(g_kT16[n * PLANE + (k0 + kk) * 64 + c]);
        }
        __syncthreads();
#pragma unroll 16
        for (int kk = 0; kk < 64; kk++) {
            float ra[4], rb[4];
#pragma unroll
            for (int v = 0; v < 4; v++) ra[v] = sQT[kk][ty * 4 + v];
#pragma unroll
            for (int u = 0; u < 4; u++) rb[u] = sKT[kk][tx * 4 + u];
#pragma unroll
            for (int v = 0; v < 4; v++)
#pragma unroll
                for (int u = 0; u < 4; u++) acc[v][u] = fmaf(ra[v], rb[u], acc[v][u]);
        }
    }
#pragma unroll
    for (int v = 0; v < 4; v++)
#pragma unroll
        for (int u = 0; u < 4; u++)
            atomicAdd(&g_cl[n * 4096 + (ty * 4 + v) * 64 + tx * 4 + u], acc[v][u]);
}

// ---- softmax over n on (n,c,d) -> m_c bf16 ----
__global__ void k_softmax_c() {
    int p = blockIdx.x * 256 + threadIdx.x;
    float vals[32], mx = -1e30f;
#pragma unroll
    for (int nn = 0; nn < 32; nn++) { vals[nn] = g_cl[nn * 4096 + p]; mx = fmaxf(mx, vals[nn]); }
    float s = 0.f;
#pragma unroll
    for (int nn = 0; nn < 32; nn++) { vals[nn] = __expf(vals[nn] - mx); s += vals[nn]; }
    float inv = 1.f / s;
#pragma unroll
    for (int nn = 0; nn < 32; nn++)
        g_mc16[nn * 4096 + p] = __float2bfloat16(vals[nn] * inv);
}

// ---- temporal conv (3,1,1) pad 1 + relu -> g_Xe (reads bf16 A) ----
__global__ void k_tconv(const float* __restrict__ wX, const float* __restrict__ bX) {
    __shared__ float sA[32][132];
    __shared__ float sW[64][68];
    int n = blockIdx.y, it = blockIdx.x;
    int b = n >> 3, t = n & 7;
    int tid = threadIdx.x, tx = tid & 15, ty = tid >> 4;
    float acc[4][8] = {};
    for (int kk = 0; kk < 3; kk++) {
        int tp = t + kk - 1;
        if (tp < 0 || tp >= 8) continue;
        __syncthreads();
        for (int idx = tid; idx < 4096; idx += 256) {
            int o = idx >> 6, c = idx & 63;
            sW[o][c] = wX[o * 192 + c * 3 + kk];
        }
        for (int ch = 0; ch < 2; ch++) {
            __syncthreads();
            for (int e = tid; e < 2048; e += 256) {       // 2048 bf16 pairs
                int c = e >> 6, ii = (e & 63) * 2;
                uint32_t u = *(const uint32_t*)&g_A16[(b * 8 + tp) * PLANE +
                                (ch * 32 + c) * HWD + it * 128 + ii];
                float2 f = __bfloat1622float2(*(__nv_bfloat162*)&u);
                sA[c][ii] = f.x; sA[c][ii + 1] = f.y;
            }
            __syncthreads();
#pragma unroll 4
            for (int c = 0; c < 32; c++) {
                float rw[4];
#pragma unroll
                for (int v = 0; v < 4; v++) rw[v] = sW[ty * 4 + v][ch * 32 + c];
                float4 aa = *(const float4*)&sA[c][tx * 8];
                float4 ab = *(const float4*)&sA[c][tx * 8 + 4];
                float ra[8] = {aa.x, aa.y, aa.z, aa.w, ab.x, ab.y, ab.z, ab.w};
#pragma unroll
                for (int v = 0; v < 4; v++)
#pragma unroll
                    for (int u = 0; u < 8; u++) acc[v][u] = fmaf(rw[v], ra[u], acc[v][u]);
            }
        }
    }
#pragma unroll
    for (int v = 0; v < 4; v++) {
        float bb = bX[ty * 4 + v];
#pragma unroll
        for (int u = 0; u < 8; u++)
            g_Xe[n * PLANE + (ty * 4 + v) * HWD + it * 128 + tx * 8 + u] =
                fmaxf(acc[v][u] + bb, 0.f);
    }
}

// ---- temporal Gram: g_tl[b,t,s] += partial dot over d-slice ----
__global__ void k_tl() {
    __shared__ float sXe[8][1032];
    int b = blockIdx.y;
    int d0 = blockIdx.x * 1024;
    int tid = threadIdx.x;
    for (int v = 0; v < 8; v++) {
        int e = tid + v * 256;
        int t = e >> 8;
        int d4 = (e & 255) * 4;
        *(float4*)&sXe[t][d4] = *(const float4*)&g_Xe[(b * 8 + t) * PLANE + d0 + d4];
    }
    __syncthreads();
    int p = tid >> 2, sub = tid & 3;
    int t = p >> 3, s = p & 7;
    float acc = 0.f;
#pragma unroll 8
    for (int it = 0; it < 64; it++) {
        int col = sub * 4 + it * 16;
        float4 a = *(const float4*)&sXe[t][col];
        float4 c = *(const float4*)&sXe[s][col];
        acc += a.x * c.x + a.y * c.y + a.z * c.z + a.w * c.w;
    }
    acc += __shfl_xor_sync(0xffffffff, acc, 1);
    acc += __shfl_xor_sync(0xffffffff, acc, 2);
    if (sub == 0) atomicAdd(&g_tl[b * 64 + p], acc);
}

__global__ void k_softmax_t() {
    int p = threadIdx.x;
    float v0 = g_tl[p], v1 = g_tl[64 + p], v2 = g_tl[128 + p], v3 = g_tl[192 + p];
    float mx = fmaxf(fmaxf(v0, v1), fmaxf(v2, v3));
    v0 = __expf(v0 - mx); v1 = __expf(v1 - mx); v2 = __expf(v2 - mx); v3 = __expf(v3 - mx);
    float inv = 1.f / (v0 + v1 + v2 + v3);
    g_tl[p] = v0 * inv; g_tl[64 + p] = v1 * inv;
    g_tl[128 + p] = v2 * inv; g_tl[192 + p] = v3 * inv;
}

__global__ void k_out(float* __restrict__ out) {
    __shared__ float sM[64];
    int gid = blockIdx.x * 256 + threadIdx.x;
    int b = gid >> 16;
    if (threadIdx.x < 64) sM[threadIdx.x] = g_tl[b * 64 + threadIdx.x];
    __syncthreads();
    int rem = gid & 65535;
    int c = rem >> 10, i = rem & 1023;
    float vv[8];
#pragma unroll
    for (int s = 0; s < 8; s++) vv[s] = g_v[(b * 8 + s) * PLANE + c * HWD + i];
#pragma unroll
    for (int t = 0; t < 8; t++) {
        float rsum = 0.f;
#pragma unroll
        for (int s = 0; s < 8; s++) rsum = fmaf(sM[t * 8 + s], vv[s], rsum);
        out[((b * 64 + c) * 8 + t) * HWD + i] = rsum;
    }
}

// ============================================================
extern "C" void kernel_launch(void* const* d_in, const int* in_sizes, int n_in,
                              void* d_out, int out_size) {
    const float* x  = (const float*)d_in[0];
    const float* wq = (const float*)d_in[1];
    const float* bq = (const float*)d_in[2];
    const float* wk = (const float*)d_in[3];
    const float* bk = (const float*)d_in[4];
    const float* wv = (const float*)d_in[5];
    const float* bv = (const float*)d_in[6];
    const float* wX = (const float*)d_in[7];
    const float* bX = (const float*)d_in[8];
    float* out = (float*)d_out;

    k_qkv<<<512, 256>>>(x, wq, bq, wk, bk, wv, bv);        // 0
    k_slogits<<<dim3(8, 8, 32), 256>>>();                  // 1
    k_cl<<<dim3(4, 32), 256>>>();                          // 2
    k_smax<<<1024, 256>>>();                               // 3  <- ncu capture slot
    k_softmax_c<<<16, 256>>>();                            // 4
    k_as<<<dim3(8, 32), 256>>>();                          // 5
    k_tconv<<<dim3(8, 32), 256>>>(wX, bX);                 // 6
    k_tl<<<dim3(64, 4), 256>>>();                          // 7
    k_softmax_t<<<1, 64>>>();                              // 8
    k_out<<<1024, 256>>>(out);                             // 9
}

// round 12
// speedup vs baseline: 1.6730x; 1.0755x over previous
#include <cuda_runtime.h>
#include <cuda_bf16.h>
#include <cstdint>

#define N_BT  32
#define HWD   1024
#define CHN   64
#define PLANE 65536      /* CHN*HWD */
#define TOT   2097152    /* N_BT*PLANE */

// ---- scratch (module-load allocated, legal) ----
__device__ __nv_bfloat16 g_qT16[TOT];  // [n][i][c]
__device__ __nv_bfloat16 g_kT16[TOT];  // [n][j][c]
__device__ float g_v [TOT];            // [n][c][i] fp32 (k_out)
__device__ __nv_bfloat16 g_v16[TOT];   // [n][c][i] bf16 (k_as A)
__device__ __nv_bfloat16 g_vT16[TOT];  // [n][i][c] bf16 (k_as a_c epilogue B)
__device__ __nv_bfloat16 g_A16[TOT];   // a_s + a_c   [n][c][i] bf16
__device__ __nv_bfloat16 g_Xe16[TOT];  // [n][c][i] bf16
__device__ float g_cl[N_BT * 64 * 64];
__device__ __nv_bfloat16 g_mc16[N_BT * 64 * 64];  // m_c bf16 [n][c][d]
__device__ float g_tl[256];
__device__ __nv_bfloat16 g_L16[N_BT << 20]; // 64 MB spatial logits (bf16)
__device__ __nv_bfloat16 g_P16[N_BT << 20]; // 64 MB softmaxed probabilities (bf16)

__device__ __forceinline__ void mma_bf16(float* d, const uint32_t* a,
                                         uint32_t b0, uint32_t b1) {
    asm volatile(
        "mma.sync.aligned.m16n8k16.row.col.f32.bf16.bf16.f32 "
        "{%0,%1,%2,%3}, {%4,%5,%6,%7}, {%8,%9}, {%0,%1,%2,%3};\n"
        : "+f"(d[0]), "+f"(d[1]), "+f"(d[2]), "+f"(d[3])
        : "r"(a[0]), "r"(a[1]), "r"(a[2]), "r"(a[3]), "r"(b0), "r"(b1));
}

__device__ __forceinline__ void cp_async16(void* smem_dst, const void* gsrc) {
    uint32_t d = (uint32_t)__cvta_generic_to_shared(smem_dst);
    asm volatile("cp.async.cg.shared.global [%0], [%1], 16;\n" :: "r"(d), "l"(gsrc));
}
__device__ __forceinline__ void cp_commit() { asm volatile("cp.async.commit_group;\n"); }
__device__ __forceinline__ void cp_wait1()  { asm volatile("cp.async.wait_group 1;\n"); }
__device__ __forceinline__ void cp_wait0()  { asm volatile("cp.async.wait_group 0;\n"); }

// ============================================================
// ---- QKV fused: relu(W x + b). q,k -> bf16 [n][i][c]; v -> fp32/bf16 [n][c][i]
//      + transposed vT bf16 [n][i][c]; also zeroes g_cl / g_tl.
__global__ void k_qkv(const float* __restrict__ x,
                      const float* __restrict__ wq, const float* __restrict__ bq,
                      const float* __restrict__ wk, const float* __restrict__ bk,
                      const float* __restrict__ wv, const float* __restrict__ bv) {
    __shared__ float sX[64][68];
    __shared__ float sW[64][68];
    int tid = threadIdx.x;
    int pt = blockIdx.x;
    g_cl[pt * 256 + tid] = 0.f;                 // 512*256 == 32*4096
    if (pt == 0) g_tl[tid] = 0.f;
    int n  = pt >> 4;
    int i0 = (pt & 15) << 6;
    int b = n >> 3, t = n & 7;
    const float* ws[3] = {wq, wk, wv};
    const float* bs[3] = {bq, bk, bv};
    for (int idx = tid; idx < 4096; idx += 256) {
        int c = idx >> 6, p = idx & 63;
        sX[c][p] = x[((b * 64 + c) * 8 + t) * 1024 + i0 + p];
    }
    int tx = tid & 15, ty = tid >> 4;
    for (int ph = 0; ph < 3; ph++) {
        __syncthreads();
        for (int idx = tid; idx < 4096; idx += 256)
            sW[idx >> 6][idx & 63] = ws[ph][idx];
        __syncthreads();
        float acc[4][4] = {};
#pragma unroll
        for (int c = 0; c < 64; c++) {
            float4 a4 = *(const float4*)&sX[c][tx * 4];
            float ra[4] = {a4.x, a4.y, a4.z, a4.w};
            float rb[4];
#pragma unroll
            for (int v = 0; v < 4; v++) rb[v] = sW[ty * 4 + v][c];
#pragma unroll
            for (int v = 0; v < 4; v++)
#pragma unroll
                for (int u = 0; u < 4; u++) acc[v][u] = fmaf(rb[v], ra[u], acc[v][u]);
        }
#pragma unroll
        for (int v = 0; v < 4; v++) {
            float bb = bs[ph][ty * 4 + v];
#pragma unroll
            for (int u = 0; u < 4; u++) acc[v][u] = fmaxf(acc[v][u] + bb, 0.f);
        }
        if (ph == 2) {
            // direct [c][i] stores (fp32 + bf16)
#pragma unroll
            for (int v = 0; v < 4; v++)
#pragma unroll
                for (int u = 0; u < 4; u++) {
                    int a = n * PLANE + (ty * 4 + v) * HWD + i0 + tx * 4 + u;
                    g_v[a] = acc[v][u];
                    g_v16[a] = __float2bfloat16(acc[v][u]);
                }
            // transpose -> vT [i][c]
            __syncthreads();
#pragma unroll
            for (int v = 0; v < 4; v++)
#pragma unroll
                for (int u = 0; u < 4; u++)
                    sW[ty * 4 + v][tx * 4 + u] = acc[v][u];
            __syncthreads();
            for (int idx = tid; idx < 4096; idx += 256) {
                int li = idx >> 6, o = idx & 63;
                g_vT16[n * PLANE + (i0 + li) * 64 + o] = __float2bfloat16(sW[o][li]);
            }
        } else {
            __syncthreads();
#pragma unroll
            for (int v = 0; v < 4; v++)
#pragma unroll
                for (int u = 0; u < 4; u++)
                    sW[ty * 4 + v][tx * 4 + u] = acc[v][u];
            __syncthreads();
            __nv_bfloat16* outp = (ph == 0) ? g_qT16 : g_kT16;
            for (int idx = tid; idx < 4096; idx += 256) {
                int li = idx >> 6, o = idx & 63;
                outp[n * PLANE + (i0 + li) * 64 + o] = __float2bfloat16(sW[o][li]);
            }
        }
    }
}

// ---- spatial logits via bf16 MMA: L[n,i,j] = sum_c q[i,c] k[j,c] -> bf16 ----
__global__ void k_slogits() {
    __shared__ __align__(16) __nv_bfloat16 sQK[2][128][72];
    int jt = blockIdx.x, it = blockIdx.y, n = blockIdx.z;
    int tid = threadIdx.x;
    const __nv_bfloat16* qb = g_qT16 + n * PLANE + (it * 128) * 64;
    const __nv_bfloat16* kb = g_kT16 + n * PLANE + (jt * 128) * 64;

#pragma unroll
    for (int v = 0; v < 8; v++) {
        int e = tid + v * 256;
        int row = e >> 3;
        int p8 = (e & 7) * 8;
        const __nv_bfloat16* src = (row < 128) ? (qb + row * 64 + p8)
                                               : (kb + (row - 128) * 64 + p8);
        cp_async16(&sQK[row >> 7][row & 127][p8], src);
    }
    cp_commit(); cp_wait0();
    __syncthreads();

    int warp = tid >> 5, lane = tid & 31;
    int r = lane >> 2, cc = lane & 3;
    int wi = (warp & 3) * 32;
    int wj = (warp >> 2) * 64;
    float acc[2][8][4] = {};

#pragma unroll
    for (int ks = 0; ks < 4; ks++) {
        int kk = ks * 16;
        uint32_t a[2][4];
#pragma unroll
        for (int m = 0; m < 2; m++) {
            int i0 = wi + m * 16;
            a[m][0] = *(const uint32_t*)&sQK[0][i0 + r][kk + 2 * cc];
            a[m][1] = *(const uint32_t*)&sQK[0][i0 + r + 8][kk + 2 * cc];
            a[m][2] = *(const uint32_t*)&sQK[0][i0 + r][kk + 2 * cc + 8];
            a[m][3] = *(const uint32_t*)&sQK[0][i0 + r + 8][kk + 2 * cc + 8];
        }
#pragma unroll
        for (int t = 0; t < 8; t++) {
            uint32_t b0 = *(const uint32_t*)&sQK[1][wj + t * 8 + r][kk + 2 * cc];
            uint32_t b1 = *(const uint32_t*)&sQK[1][wj + t * 8 + r][kk + 2 * cc + 8];
#pragma unroll
            for (int m = 0; m < 2; m++) mma_bf16(acc[m][t], a[m], b0, b1);
        }
    }

    __syncthreads();
    uint32_t (*stg)[68] = (uint32_t(*)[68])sQK;
#pragma unroll
    for (int m = 0; m < 2; m++)
#pragma unroll
        for (int t = 0; t < 8; t++) {
            int rowl = wi + m * 16 + r;
            int colw = (wj + t * 8) / 2 + cc;
            __nv_bfloat162 lo = __floats2bfloat162_rn(acc[m][t][0], acc[m][t][1]);
            __nv_bfloat162 hi = __floats2bfloat162_rn(acc[m][t][2], acc[m][t][3]);
            stg[rowl][colw]     = *(uint32_t*)&lo;
            stg[rowl + 8][colw] = *(uint32_t*)&hi;
        }
    __syncthreads();
#pragma unroll
    for (int v = 0; v < 8; v++) {
        int e = tid + v * 256;
        int row = e >> 4, q = e & 15;
        uint4 val = *(uint4*)&stg[row][q * 4];
        __nv_bfloat16* dst = g_L16 + ((size_t)n << 20) + (it * 128 + row) * 1024
                             + jt * 128 + q * 8;
        *(uint4*)dst = val;
    }
}

// ---- per-(i,j) softmax over n -> P bf16. 2 idx/thread, convert ONCE, exp ONCE ----
__global__ void k_smax() {
    int base = (blockIdx.x * 256 + threadIdx.x) * 2;
    float f[64];
#pragma unroll
    for (int nn = 0; nn < 32; nn++) {
        uint32_t u = *(const uint32_t*)&g_L16[((size_t)nn << 20) + base];
        float2 fp = __bfloat1622float2(*(__nv_bfloat162*)&u);
        f[2 * nn] = fp.x; f[2 * nn + 1] = fp.y;
    }
    float mx0 = -1e30f, mx1 = -1e30f;
#pragma unroll
    for (int nn = 0; nn < 32; nn++) {
        mx0 = fmaxf(mx0, f[2 * nn]); mx1 = fmaxf(mx1, f[2 * nn + 1]);
    }
    float s0 = 0.f, s1 = 0.f;
#pragma unroll
    for (int nn = 0; nn < 32; nn++) {
        f[2 * nn]     = __expf(f[2 * nn] - mx0);     s0 += f[2 * nn];
        f[2 * nn + 1] = __expf(f[2 * nn + 1] - mx1); s1 += f[2 * nn + 1];
    }
    float inv0 = 1.f / s0, inv1 = 1.f / s1;
#pragma unroll
    for (int nn = 0; nn < 32; nn++) {
        __nv_bfloat162 p = __floats2bfloat162_rn(f[2 * nn] * inv0, f[2 * nn + 1] * inv1);
        *(uint32_t*)&g_P16[((size_t)nn << 20) + base] = *(uint32_t*)&p;
    }
}

// ---- a_s = V @ P^T + a_c = m_c @ v  (bf16 MMA); g_A16 = result (bf16) ----
// grid (it8, n32); block: c64 (M) x i128 (N).
__global__ void __launch_bounds__(256, 2) k_as() {
    __shared__ __align__(16) char sbuf[46080];
    __nv_bfloat16 (*sP)[40] = (__nv_bfloat16(*)[40])sbuf;            // [3][128][40]
    __nv_bfloat16 (*sV)[40] = (__nv_bfloat16(*)[40])(sbuf + 30720);  // [3][64][40]
    int it = blockIdx.x, n = blockIdx.y;
    int tid = threadIdx.x;
    const __nv_bfloat16* vb = g_v16 + n * PLANE;
    const __nv_bfloat16* pb = g_P16 + ((size_t)n << 20) + (it * 128) * 1024;

    auto stage = [&](int ch) {
        int s = ch % 3;
        int j0 = ch * 32;
#pragma unroll
        for (int v = 0; v < 2; v++) {
            int e = tid + v * 256;
            int row = e >> 2;
            int p8 = (e & 3) * 8;
            cp_async16(&sP[s * 128 + row][p8], pb + row * 1024 + j0 + p8);
        }
        {
            int row = tid >> 2;
            int p8 = (tid & 3) * 8;
            cp_async16(&sV[s * 64 + row][p8], vb + row * 1024 + j0 + p8);
        }
        cp_commit();
    };
    stage(0); stage(1);

    int warp = tid >> 5, lane = tid & 31;
    int r = lane >> 2, cc = lane & 3;
    int wc = (warp & 1) * 32;            // 2 warps along c (M)
    int wi = (warp >> 1) * 32;           // 4 warps along i (N)
    float acc[2][4][4] = {};

    for (int ch = 0; ch < 32; ch++) {
        cp_wait1();
        __syncthreads();
        if (ch + 2 < 32) stage(ch + 2);
        else cp_commit();
        int s = ch % 3;
#pragma unroll
        for (int ks = 0; ks < 2; ks++) {
            int kk = ks * 16;
            uint32_t a[2][4];
#pragma unroll
            for (int m = 0; m < 2; m++) {
                int c0 = wc + m * 16;
                a[m][0] = *(const uint32_t*)&sV[s * 64 + c0 + r][kk + 2 * cc];
                a[m][1] = *(const uint32_t*)&sV[s * 64 + c0 + r + 8][kk + 2 * cc];
                a[m][2] = *(const uint32_t*)&sV[s * 64 + c0 + r][kk + 2 * cc + 8];
                a[m][3] = *(const uint32_t*)&sV[s * 64 + c0 + r + 8][kk + 2 * cc + 8];
            }
#pragma unroll
            for (int t = 0; t < 4; t++) {
                uint32_t b0 = *(const uint32_t*)&sP[s * 128 + wi + t * 8 + r][kk + 2 * cc];
                uint32_t b1 = *(const uint32_t*)&sP[s * 128 + wi + t * 8 + r][kk + 2 * cc + 8];
#pragma unroll
                for (int m = 0; m < 2; m++) mma_bf16(acc[m][t], a[m], b0, b1);
            }
        }
    }

    // ---- a_c epilogue: acc += m_c[n] @ vT (K = 64 channels d) ----
    cp_wait0();
    __syncthreads();                      // buffers now reusable
    __nv_bfloat16 (*sMc)[72] = (__nv_bfloat16(*)[72])sbuf;           // [64][72]
    __nv_bfloat16 (*sVT)[72] = (__nv_bfloat16(*)[72])(sbuf + 9216);  // [128][72]
#pragma unroll
    for (int v = 0; v < 2; v++) {         // m_c: 64x64 bf16 = 512 x 16B
        int e = tid + v * 256;
        int row = e >> 3, p8 = (e & 7) * 8;
        cp_async16(&sMc[row][p8], g_mc16 + n * 4096 + row * 64 + p8);
    }
#pragma unroll
    for (int v = 0; v < 4; v++) {         // vT tile: 128x64 bf16 = 1024 x 16B
        int e = tid + v * 256;
        int row = e >> 3, p8 = (e & 7) * 8;
        cp_async16(&sVT[row][p8], g_vT16 + n * PLANE + (it * 128 + row) * 64 + p8);
    }
    cp_commit(); cp_wait0();
    __syncthreads();
#pragma unroll
    for (int ks = 0; ks < 4; ks++) {
        int kk = ks * 16;
        uint32_t a[2][4];
#pragma unroll
        for (int m = 0; m < 2; m++) {
            int c0 = wc + m * 16;
            a[m][0] = *(const uint32_t*)&sMc[c0 + r][kk + 2 * cc];
            a[m][1] = *(const uint32_t*)&sMc[c0 + r + 8][kk + 2 * cc];
            a[m][2] = *(const uint32_t*)&sMc[c0 + r][kk + 2 * cc + 8];
            a[m][3] = *(const uint32_t*)&sMc[c0 + r + 8][kk + 2 * cc + 8];
        }
#pragma unroll
        for (int t = 0; t < 4; t++) {
            uint32_t b0 = *(const uint32_t*)&sVT[wi + t * 8 + r][kk + 2 * cc];
            uint32_t b1 = *(const uint32_t*)&sVT[wi + t * 8 + r][kk + 2 * cc + 8];
#pragma unroll
            for (int m = 0; m < 2; m++) mma_bf16(acc[m][t], a[m], b0, b1);
        }
    }

    // ---- store bf16 ----
#pragma unroll
    for (int m = 0; m < 2; m++)
#pragma unroll
        for (int t = 0; t < 4; t++) {
            int c0 = wc + m * 16 + r;
            int i0 = it * 128 + wi + t * 8 + cc * 2;
            __nv_bfloat162 p0 = __floats2bfloat162_rn(acc[m][t][0], acc[m][t][1]);
            __nv_bfloat162 p1 = __floats2bfloat162_rn(acc[m][t][2], acc[m][t][3]);
            *(uint32_t*)&g_A16[n * PLANE + c0 * HWD + i0] = *(uint32_t*)&p0;
            *(uint32_t*)&g_A16[n * PLANE + (c0 + 8) * HWD + i0] = *(uint32_t*)&p1;
        }
}

// ---- channel logits (split-k atomics), bf16 inputs ----
__global__ void k_cl() {
    __shared__ float sQT[64][68];
    __shared__ float sKT[64][68];
    int n = blockIdx.y;
    int tid = threadIdx.x, tx = tid & 15, ty = tid >> 4;
    float acc[4][4] = {};
    for (int sub = 0; sub < 4; sub++) {
        int k0 = blockIdx.x * 256 + sub * 64;
        __syncthreads();
        for (int idx = tid; idx < 4096; idx += 256) {
            int kk = idx >> 6, c = idx & 63;
            sQT[kk][c] = __bfloat162float(g_qT16[n * PLANE + (k0 + kk) * 64 + c]);
            sKT[kk][c] = __bfloat162float(g_kT16[n * PLANE + (k0 + kk) * 64 + c]);
        }
        __syncthreads();
#pragma unroll 16
        for (int kk = 0; kk < 64; kk++) {
            float ra[4], rb[4];
#pragma unroll
            for (int v = 0; v < 4; v++) ra[v] = sQT[kk][ty * 4 + v];
#pragma unroll
            for (int u = 0; u < 4; u++) rb[u] = sKT[kk][tx * 4 + u];
#pragma unroll
            for (int v = 0; v < 4; v++)
#pragma unroll
                for (int u = 0; u < 4; u++) acc[v][u] = fmaf(ra[v], rb[u], acc[v][u]);
        }
    }
#pragma unroll
    for (int v = 0; v < 4; v++)
#pragma unroll
        for (int u = 0; u < 4; u++)
            atomicAdd(&g_cl[n * 4096 + (ty * 4 + v) * 64 + tx * 4 + u], acc[v][u]);
}

// ---- softmax over n on (n,c,d) -> m_c bf16 ----
__global__ void k_softmax_c() {
    int p = blockIdx.x * 256 + threadIdx.x;
    float vals[32], mx = -1e30f;
#pragma unroll
    for (int nn = 0; nn < 32; nn++) { vals[nn] = g_cl[nn * 4096 + p]; mx = fmaxf(mx, vals[nn]); }
    float s = 0.f;
#pragma unroll
    for (int nn = 0; nn < 32; nn++) { vals[nn] = __expf(vals[nn] - mx); s += vals[nn]; }
    float inv = 1.f / s;
#pragma unroll
    for (int nn = 0; nn < 32; nn++)
        g_mc16[nn * 4096 + p] = __float2bfloat16(vals[nn] * inv);
}

// ---- temporal conv (3,1,1) pad 1 + relu -> g_Xe16 (bf16) ----
__global__ void k_tconv(const float* __restrict__ wX, const float* __restrict__ bX) {
    __shared__ float sA[32][132];
    __shared__ float sW[64][68];
    int n = blockIdx.y, it = blockIdx.x;
    int b = n >> 3, t = n & 7;
    int tid = threadIdx.x, tx = tid & 15, ty = tid >> 4;
    float acc[4][8] = {};
    for (int kk = 0; kk < 3; kk++) {
        int tp = t + kk - 1;
        if (tp < 0 || tp >= 8) continue;
        __syncthreads();
        for (int idx = tid; idx < 4096; idx += 256) {
            int o = idx >> 6, c = idx & 63;
            sW[o][c] = wX[o * 192 + c * 3 + kk];
        }
        for (int ch = 0; ch < 2; ch++) {
            __syncthreads();
            for (int e = tid; e < 2048; e += 256) {       // 2048 bf16 pairs
                int c = e >> 6, ii = (e & 63) * 2;
                uint32_t u = *(const uint32_t*)&g_A16[(b * 8 + tp) * PLANE +
                                (ch * 32 + c) * HWD + it * 128 + ii];
                float2 f = __bfloat1622float2(*(__nv_bfloat162*)&u);
                sA[c][ii] = f.x; sA[c][ii + 1] = f.y;
            }
            __syncthreads();
#pragma unroll 4
            for (int c = 0; c < 32; c++) {
                float rw[4];
#pragma unroll
                for (int v = 0; v < 4; v++) rw[v] = sW[ty * 4 + v][ch * 32 + c];
                float4 aa = *(const float4*)&sA[c][tx * 8];
                float4 ab = *(const float4*)&sA[c][tx * 8 + 4];
                float ra[8] = {aa.x, aa.y, aa.z, aa.w, ab.x, ab.y, ab.z, ab.w};
#pragma unroll
                for (int v = 0; v < 4; v++)
#pragma unroll
                    for (int u = 0; u < 8; u++) acc[v][u] = fmaf(rw[v], ra[u], acc[v][u]);
            }
        }
    }
#pragma unroll
    for (int v = 0; v < 4; v++) {
        float bb = bX[ty * 4 + v];
#pragma unroll
        for (int u = 0; u < 8; u += 2) {
            float r0 = fmaxf(acc[v][u] + bb, 0.f);
            float r1 = fmaxf(acc[v][u + 1] + bb, 0.f);
            __nv_bfloat162 p = __floats2bfloat162_rn(r0, r1);
            *(uint32_t*)&g_Xe16[n * PLANE + (ty * 4 + v) * HWD + it * 128 + tx * 8 + u] =
                *(uint32_t*)&p;
        }
    }
}

// ---- temporal Gram: g_tl[b,t,s] += partial dot over d-slice (bf16 Xe) ----
__global__ void k_tl() {
    __shared__ float sXe[8][1032];
    int b = blockIdx.y;
    int d0 = blockIdx.x * 1024;
    int tid = threadIdx.x;
#pragma unroll
    for (int v = 0; v < 4; v++) {
        int e = tid + v * 256;          // 0..1023 uint4s (8 bf16 each)
        int t = e >> 7;
        int d8 = (e & 127) * 8;
        uint4 raw = *(const uint4*)&g_Xe16[(b * 8 + t) * PLANE + d0 + d8];
        uint32_t* pu = (uint32_t*)&raw;
#pragma unroll
        for (int w = 0; w < 4; w++) {
            float2 f = __bfloat1622float2(*(__nv_bfloat162*)&pu[w]);
            sXe[t][d8 + 2 * w] = f.x; sXe[t][d8 + 2 * w + 1] = f.y;
        }
    }
    __syncthreads();
    int p = tid >> 2, sub = tid & 3;
    int t = p >> 3, s = p & 7;
    float acc = 0.f;
#pragma unroll 8
    for (int it = 0; it < 64; it++) {
        int col = sub * 4 + it * 16;
        float4 a = *(const float4*)&sXe[t][col];
        float4 c = *(const float4*)&sXe[s][col];
        acc += a.x * c.x + a.y * c.y + a.z * c.z + a.w * c.w;
    }
    acc += __shfl_xor_sync(0xffffffff, acc, 1);
    acc += __shfl_xor_sync(0xffffffff, acc, 2);
    if (sub == 0) atomicAdd(&g_tl[b * 64 + p], acc);
}

__global__ void k_softmax_t() {
    int p = threadIdx.x;
    float v0 = g_tl[p], v1 = g_tl[64 + p], v2 = g_tl[128 + p], v3 = g_tl[192 + p];
    float mx = fmaxf(fmaxf(v0, v1), fmaxf(v2, v3));
    v0 = __expf(v0 - mx); v1 = __expf(v1 - mx); v2 = __expf(v2 - mx); v3 = __expf(v3 - mx);
    float inv = 1.f / (v0 + v1 + v2 + v3);
    g_tl[p] = v0 * inv; g_tl[64 + p] = v1 * inv;
    g_tl[128 + p] = v2 * inv; g_tl[192 + p] = v3 * inv;
}

__global__ void k_out(float* __restrict__ out) {
    __shared__ float sM[64];
    int gid = blockIdx.x * 256 + threadIdx.x;
    int b = gid >> 16;
    if (threadIdx.x < 64) sM[threadIdx.x] = g_tl[b * 64 + threadIdx.x];
    __syncthreads();
    int rem = gid & 65535;
    int c = rem >> 10, i = rem & 1023;
    float vv[8];
#pragma unroll
    for (int s = 0; s < 8; s++) vv[s] = g_v[(b * 8 + s) * PLANE + c * HWD + i];
#pragma unroll
    for (int t = 0; t < 8; t++) {
        float rsum = 0.f;
#pragma unroll
        for (int s = 0; s < 8; s++) rsum = fmaf(sM[t * 8 + s], vv[s], rsum);
        out[((b * 64 + c) * 8 + t) * HWD + i] = rsum;
    }
}

// ============================================================
extern "C" void kernel_launch(void* const* d_in, const int* in_sizes, int n_in,
                              void* d_out, int out_size) {
    const float* x  = (const float*)d_in[0];
    const float* wq = (const float*)d_in[1];
    const float* bq = (const float*)d_in[2];
    const float* wk = (const float*)d_in[3];
    const float* bk = (const float*)d_in[4];
    const float* wv = (const float*)d_in[5];
    const float* bv = (const float*)d_in[6];
    const float* wX = (const float*)d_in[7];
    const float* bX = (const float*)d_in[8];
    float* out = (float*)d_out;

    k_qkv<<<512, 256>>>(x, wq, bq, wk, bk, wv, bv);        // 0
    k_slogits<<<dim3(8, 8, 32), 256>>>();                  // 1
    k_cl<<<dim3(4, 32), 256>>>();                          // 2
    k_smax<<<2048, 256>>>();                               // 3  <- ncu capture slot
    k_softmax_c<<<16, 256>>>();                            // 4
    k_as<<<dim3(8, 32), 256>>>();                          // 5
    k_tconv<<<dim3(8, 32), 256>>>(wX, bX);                 // 6
    k_tl<<<dim3(64, 4), 256>>>();                          // 7
    k_softmax_t<<<1, 64>>>();                              // 8
    k_out<<<1024, 256>>>(out);                             // 9
}

// round 14
// speedup vs baseline: 1.7548x; 1.0489x over previous
#include <cuda_runtime.h>
#include <cuda_bf16.h>
#include <cstdint>

#define N_BT  32
#define HWD   1024
#define CHN   64
#define PLANE 65536      /* CHN*HWD */
#define TOT   2097152    /* N_BT*PLANE */

// ---- scratch (module-load allocated, legal) ----
__device__ __nv_bfloat16 g_qT16[TOT];  // [n][i][c]  (k_slogits)
__device__ __nv_bfloat16 g_kT16[TOT];  // [n][j][c]
__device__ __nv_bfloat16 g_q16[TOT];   // [n][c][i]  (k_cl)
__device__ __nv_bfloat16 g_k16[TOT];   // [n][c][i]
__device__ float g_v [TOT];            // [n][c][i] fp32 (k_out)
__device__ __nv_bfloat16 g_v16[TOT];   // [n][c][i] bf16 (k_as A)
__device__ __nv_bfloat16 g_vT16[TOT];  // [n][i][c] bf16 (k_as a_c epilogue B)
__device__ __nv_bfloat16 g_A16[TOT];   // a_s + a_c   [n][c][i] bf16
__device__ __nv_bfloat16 g_Xe16[TOT];  // [n][c][i] bf16
__device__ float g_cl[N_BT * 64 * 64];
__device__ __nv_bfloat16 g_mc16[N_BT * 64 * 64];  // m_c bf16 [n][c][d]
__device__ float g_tl[256];
__device__ __nv_bfloat16 g_L16[N_BT << 20]; // 64 MB spatial logits (bf16)
__device__ __nv_bfloat16 g_P16[N_BT << 20]; // 64 MB softmaxed probabilities (bf16)

__device__ __forceinline__ void mma_bf16(float* d, const uint32_t* a,
                                         uint32_t b0, uint32_t b1) {
    asm volatile(
        "mma.sync.aligned.m16n8k16.row.col.f32.bf16.bf16.f32 "
        "{%0,%1,%2,%3}, {%4,%5,%6,%7}, {%8,%9}, {%0,%1,%2,%3};\n"
        : "+f"(d[0]), "+f"(d[1]), "+f"(d[2]), "+f"(d[3])
        : "r"(a[0]), "r"(a[1]), "r"(a[2]), "r"(a[3]), "r"(b0), "r"(b1));
}

__device__ __forceinline__ void cp_async16(void* smem_dst, const void* gsrc) {
    uint32_t d = (uint32_t)__cvta_generic_to_shared(smem_dst);
    asm volatile("cp.async.cg.shared.global [%0], [%1], 16;\n" :: "r"(d), "l"(gsrc));
}
__device__ __forceinline__ void cp_commit() { asm volatile("cp.async.commit_group;\n"); }
__device__ __forceinline__ void cp_wait1()  { asm volatile("cp.async.wait_group 1;\n"); }
__device__ __forceinline__ void cp_wait0()  { asm volatile("cp.async.wait_group 0;\n"); }

// ============================================================
// ---- QKV fused: relu(W x + b). q,k -> bf16 [n][i][c] AND [n][c][i];
//      v -> fp32/bf16 [n][c][i] + vT bf16 [n][i][c]; zeroes g_tl.
__global__ void k_qkv(const float* __restrict__ x,
                      const float* __restrict__ wq, const float* __restrict__ bq,
                      const float* __restrict__ wk, const float* __restrict__ bk,
                      const float* __restrict__ wv, const float* __restrict__ bv) {
    __shared__ float sX[64][68];
    __shared__ float sW[64][68];
    int tid = threadIdx.x;
    int pt = blockIdx.x;
    if (pt == 0) g_tl[tid] = 0.f;
    int n  = pt >> 4;
    int i0 = (pt & 15) << 6;
    int b = n >> 3, t = n & 7;
    const float* ws[3] = {wq, wk, wv};
    const float* bs[3] = {bq, bk, bv};
    for (int idx = tid; idx < 4096; idx += 256) {
        int c = idx >> 6, p = idx & 63;
        sX[c][p] = x[((b * 64 + c) * 8 + t) * 1024 + i0 + p];
    }
    int tx = tid & 15, ty = tid >> 4;
    for (int ph = 0; ph < 3; ph++) {
        __syncthreads();
        for (int idx = tid; idx < 4096; idx += 256)
            sW[idx >> 6][idx & 63] = ws[ph][idx];
        __syncthreads();
        float acc[4][4] = {};
#pragma unroll
        for (int c = 0; c < 64; c++) {
            float4 a4 = *(const float4*)&sX[c][tx * 4];
            float ra[4] = {a4.x, a4.y, a4.z, a4.w};
            float rb[4];
#pragma unroll
            for (int v = 0; v < 4; v++) rb[v] = sW[ty * 4 + v][c];
#pragma unroll
            for (int v = 0; v < 4; v++)
#pragma unroll
                for (int u = 0; u < 4; u++) acc[v][u] = fmaf(rb[v], ra[u], acc[v][u]);
        }
#pragma unroll
        for (int v = 0; v < 4; v++) {
            float bb = bs[ph][ty * 4 + v];
#pragma unroll
            for (int u = 0; u < 4; u++) acc[v][u] = fmaxf(acc[v][u] + bb, 0.f);
        }
        if (ph == 2) {
            // direct [c][i] stores (fp32 + bf16)
#pragma unroll
            for (int v = 0; v < 4; v++)
#pragma unroll
                for (int u = 0; u < 4; u++) {
                    int a = n * PLANE + (ty * 4 + v) * HWD + i0 + tx * 4 + u;
                    g_v[a] = acc[v][u];
                    g_v16[a] = __float2bfloat16(acc[v][u]);
                }
            // transpose -> vT [i][c]
            __syncthreads();
#pragma unroll
            for (int v = 0; v < 4; v++)
#pragma unroll
                for (int u = 0; u < 4; u++)
                    sW[ty * 4 + v][tx * 4 + u] = acc[v][u];
            __syncthreads();
            for (int idx = tid; idx < 4096; idx += 256) {
                int li = idx >> 6, o = idx & 63;
                g_vT16[n * PLANE + (i0 + li) * 64 + o] = __float2bfloat16(sW[o][li]);
            }
        } else {
            // direct [c][i] bf16 store for k_cl
            __nv_bfloat16* dirp = (ph == 0) ? g_q16 : g_k16;
#pragma unroll
            for (int v = 0; v < 4; v++)
#pragma unroll
                for (int u = 0; u < 4; u++)
                    dirp[n * PLANE + (ty * 4 + v) * HWD + i0 + tx * 4 + u] =
                        __float2bfloat16(acc[v][u]);
            // transposed [i][c] store for k_slogits
            __syncthreads();
#pragma unroll
            for (int v = 0; v < 4; v++)
#pragma unroll
                for (int u = 0; u < 4; u++)
                    sW[ty * 4 + v][tx * 4 + u] = acc[v][u];
            __syncthreads();
            __nv_bfloat16* outp = (ph == 0) ? g_qT16 : g_kT16;
            for (int idx = tid; idx < 4096; idx += 256) {
                int li = idx >> 6, o = idx & 63;
                outp[n * PLANE + (i0 + li) * 64 + o] = __float2bfloat16(sW[o][li]);
            }
        }
    }
}

// ---- channel logits via bf16 MMA: cl[n,c,d] = sum_i q[c,i] k[d,i] (fp32 out) ----
// grid 32 (n); block: c64 (M) x d64 (N), K=1024 over i, chunk 32, 3-stage.
__global__ void __launch_bounds__(256, 2) k_cl() {
    __shared__ __align__(16) __nv_bfloat16 sQ[3][64][40];
    __shared__ __align__(16) __nv_bfloat16 sK[3][64][40];
    int n = blockIdx.x;
    int tid = threadIdx.x;
    const __nv_bfloat16* qb = g_q16 + n * PLANE;
    const __nv_bfloat16* kb = g_k16 + n * PLANE;

    auto stage = [&](int ch) {
        int s = ch % 3;
        int i0 = ch * 32;
        {   // 64 rows x 32 bf16 = 256 x 16B for each of Q,K
            int row = tid >> 2;
            int p8 = (tid & 3) * 8;
            cp_async16(&sQ[s][row][p8], qb + row * HWD + i0 + p8);
            cp_async16(&sK[s][row][p8], kb + row * HWD + i0 + p8);
        }
        cp_commit();
    };
    stage(0); stage(1);

    int warp = tid >> 5, lane = tid & 31;
    int r = lane >> 2, cc = lane & 3;
    int wc = (warp & 1) * 32;            // 2 warps along c (M)
    int wd = (warp >> 1) * 16;           // 4 warps along d (N)
    float acc[2][2][4] = {};

    for (int ch = 0; ch < 32; ch++) {
        cp_wait1();
        __syncthreads();
        if (ch + 2 < 32) stage(ch + 2);
        else cp_commit();
        int s = ch % 3;
#pragma unroll
        for (int ks = 0; ks < 2; ks++) {
            int kk = ks * 16;
            uint32_t a[2][4];
#pragma unroll
            for (int m = 0; m < 2; m++) {
                int c0 = wc + m * 16;
                a[m][0] = *(const uint32_t*)&sQ[s][c0 + r][kk + 2 * cc];
                a[m][1] = *(const uint32_t*)&sQ[s][c0 + r + 8][kk + 2 * cc];
                a[m][2] = *(const uint32_t*)&sQ[s][c0 + r][kk + 2 * cc + 8];
                a[m][3] = *(const uint32_t*)&sQ[s][c0 + r + 8][kk + 2 * cc + 8];
            }
#pragma unroll
            for (int t = 0; t < 2; t++) {
                uint32_t b0 = *(const uint32_t*)&sK[s][wd + t * 8 + r][kk + 2 * cc];
                uint32_t b1 = *(const uint32_t*)&sK[s][wd + t * 8 + r][kk + 2 * cc + 8];
#pragma unroll
                for (int m = 0; m < 2; m++) mma_bf16(acc[m][t], a[m], b0, b1);
            }
        }
    }
#pragma unroll
    for (int m = 0; m < 2; m++)
#pragma unroll
        for (int t = 0; t < 2; t++) {
            int c0 = wc + m * 16 + r;
            int d0 = wd + t * 8 + cc * 2;
            float2 o0 = {acc[m][t][0], acc[m][t][1]};
            float2 o1 = {acc[m][t][2], acc[m][t][3]};
            *(float2*)&g_cl[n * 4096 + c0 * 64 + d0] = o0;
            *(float2*)&g_cl[n * 4096 + (c0 + 8) * 64 + d0] = o1;
        }
}

// ---- softmax over n on (n,c,d) -> m_c bf16 ----
__global__ void k_softmax_c() {
    int p = blockIdx.x * 256 + threadIdx.x;
    float vals[32], mx = -1e30f;
#pragma unroll
    for (int nn = 0; nn < 32; nn++) { vals[nn] = g_cl[nn * 4096 + p]; mx = fmaxf(mx, vals[nn]); }
    float s = 0.f;
#pragma unroll
    for (int nn = 0; nn < 32; nn++) { vals[nn] = __expf(vals[nn] - mx); s += vals[nn]; }
    float inv = 1.f / s;
#pragma unroll
    for (int nn = 0; nn < 32; nn++)
        g_mc16[nn * 4096 + p] = __float2bfloat16(vals[nn] * inv);
}

// ---- spatial logits via bf16 MMA: L[n,i,j] = sum_c q[i,c] k[j,c] -> bf16 ----
__global__ void k_slogits() {
    __shared__ __align__(16) __nv_bfloat16 sQK[2][128][72];
    int jt = blockIdx.x, it = blockIdx.y, n = blockIdx.z;
    int tid = threadIdx.x;
    const __nv_bfloat16* qb = g_qT16 + n * PLANE + (it * 128) * 64;
    const __nv_bfloat16* kb = g_kT16 + n * PLANE + (jt * 128) * 64;

#pragma unroll
    for (int v = 0; v < 8; v++) {
        int e = tid + v * 256;
        int row = e >> 3;
        int p8 = (e & 7) * 8;
        const __nv_bfloat16* src = (row < 128) ? (qb + row * 64 + p8)
                                               : (kb + (row - 128) * 64 + p8);
        cp_async16(&sQK[row >> 7][row & 127][p8], src);
    }
    cp_commit(); cp_wait0();
    __syncthreads();

    int warp = tid >> 5, lane = tid & 31;
    int r = lane >> 2, cc = lane & 3;
    int wi = (warp & 3) * 32;
    int wj = (warp >> 2) * 64;
    float acc[2][8][4] = {};

#pragma unroll
    for (int ks = 0; ks < 4; ks++) {
        int kk = ks * 16;
        uint32_t a[2][4];
#pragma unroll
        for (int m = 0; m < 2; m++) {
            int i0 = wi + m * 16;
            a[m][0] = *(const uint32_t*)&sQK[0][i0 + r][kk + 2 * cc];
            a[m][1] = *(const uint32_t*)&sQK[0][i0 + r + 8][kk + 2 * cc];
            a[m][2] = *(const uint32_t*)&sQK[0][i0 + r][kk + 2 * cc + 8];
            a[m][3] = *(const uint32_t*)&sQK[0][i0 + r + 8][kk + 2 * cc + 8];
        }
#pragma unroll
        for (int t = 0; t < 8; t++) {
            uint32_t b0 = *(const uint32_t*)&sQK[1][wj + t * 8 + r][kk + 2 * cc];
            uint32_t b1 = *(const uint32_t*)&sQK[1][wj + t * 8 + r][kk + 2 * cc + 8];
#pragma unroll
            for (int m = 0; m < 2; m++) mma_bf16(acc[m][t], a[m], b0, b1);
        }
    }

    __syncthreads();
    uint32_t (*stg)[68] = (uint32_t(*)[68])sQK;
#pragma unroll
    for (int m = 0; m < 2; m++)
#pragma unroll
        for (int t = 0; t < 8; t++) {
            int rowl = wi + m * 16 + r;
            int colw = (wj + t * 8) / 2 + cc;
            __nv_bfloat162 lo = __floats2bfloat162_rn(acc[m][t][0], acc[m][t][1]);
            __nv_bfloat162 hi = __floats2bfloat162_rn(acc[m][t][2], acc[m][t][3]);
            stg[rowl][colw]     = *(uint32_t*)&lo;
            stg[rowl + 8][colw] = *(uint32_t*)&hi;
        }
    __syncthreads();
#pragma unroll
    for (int v = 0; v < 8; v++) {
        int e = tid + v * 256;
        int row = e >> 4, q = e & 15;
        uint4 val = *(uint4*)&stg[row][q * 4];
        __nv_bfloat16* dst = g_L16 + ((size_t)n << 20) + (it * 128 + row) * 1024
                             + jt * 128 + q * 8;
        *(uint4*)dst = val;
    }
}

// ---- per-(i,j) softmax over n -> P bf16. 2 idx/thread, convert ONCE, exp ONCE ----
__global__ void k_smax() {
    int base = (blockIdx.x * 256 + threadIdx.x) * 2;
    float f[64];
#pragma unroll
    for (int nn = 0; nn < 32; nn++) {
        uint32_t u = *(const uint32_t*)&g_L16[((size_t)nn << 20) + base];
        float2 fp = __bfloat1622float2(*(__nv_bfloat162*)&u);
        f[2 * nn] = fp.x; f[2 * nn + 1] = fp.y;
    }
    float mx0 = -1e30f, mx1 = -1e30f;
#pragma unroll
    for (int nn = 0; nn < 32; nn++) {
        mx0 = fmaxf(mx0, f[2 * nn]); mx1 = fmaxf(mx1, f[2 * nn + 1]);
    }
    float s0 = 0.f, s1 = 0.f;
#pragma unroll
    for (int nn = 0; nn < 32; nn++) {
        f[2 * nn]     = __expf(f[2 * nn] - mx0);     s0 += f[2 * nn];
        f[2 * nn + 1] = __expf(f[2 * nn + 1] - mx1); s1 += f[2 * nn + 1];
    }
    float inv0 = 1.f / s0, inv1 = 1.f / s1;
#pragma unroll
    for (int nn = 0; nn < 32; nn++) {
        __nv_bfloat162 p = __floats2bfloat162_rn(f[2 * nn] * inv0, f[2 * nn + 1] * inv1);
        *(uint32_t*)&g_P16[((size_t)nn << 20) + base] = *(uint32_t*)&p;
    }
}

// ---- a_s = V @ P^T + a_c = m_c @ v  (bf16 MMA); g_A16 = result (bf16) ----
// grid (it8, n32); block: c64 (M) x i128 (N).
__global__ void __launch_bounds__(256, 2) k_as() {
    __shared__ __align__(16) char sbuf[46080];
    __nv_bfloat16 (*sP)[40] = (__nv_bfloat16(*)[40])sbuf;            // [3][128][40]
    __nv_bfloat16 (*sV)[40] = (__nv_bfloat16(*)[40])(sbuf + 30720);  // [3][64][40]
    int it = blockIdx.x, n = blockIdx.y;
    int tid = threadIdx.x;
    const __nv_bfloat16* vb = g_v16 + n * PLANE;
    const __nv_bfloat16* pb = g_P16 + ((size_t)n << 20) + (it * 128) * 1024;

    auto stage = [&](int ch) {
        int s = ch % 3;
        int j0 = ch * 32;
#pragma unroll
        for (int v = 0; v < 2; v++) {
            int e = tid + v * 256;
            int row = e >> 2;
            int p8 = (e & 3) * 8;
            cp_async16(&sP[s * 128 + row][p8], pb + row * 1024 + j0 + p8);
        }
        {
            int row = tid >> 2;
            int p8 = (tid & 3) * 8;
            cp_async16(&sV[s * 64 + row][p8], vb + row * 1024 + j0 + p8);
        }
        cp_commit();
    };
    stage(0); stage(1);

    int warp = tid >> 5, lane = tid & 31;
    int r = lane >> 2, cc = lane & 3;
    int wc = (warp & 1) * 32;            // 2 warps along c (M)
    int wi = (warp >> 1) * 32;           // 4 warps along i (N)
    float acc[2][4][4] = {};

    for (int ch = 0; ch < 32; ch++) {
        cp_wait1();
        __syncthreads();
        if (ch + 2 < 32) stage(ch + 2);
        else cp_commit();
        int s = ch % 3;
#pragma unroll
        for (int ks = 0; ks < 2; ks++) {
            int kk = ks * 16;
            uint32_t a[2][4];
#pragma unroll
            for (int m = 0; m < 2; m++) {
                int c0 = wc + m * 16;
                a[m][0] = *(const uint32_t*)&sV[s * 64 + c0 + r][kk + 2 * cc];
                a[m][1] = *(const uint32_t*)&sV[s * 64 + c0 + r + 8][kk + 2 * cc];
                a[m][2] = *(const uint32_t*)&sV[s * 64 + c0 + r][kk + 2 * cc + 8];
                a[m][3] = *(const uint32_t*)&sV[s * 64 + c0 + r + 8][kk + 2 * cc + 8];
            }
#pragma unroll
            for (int t = 0; t < 4; t++) {
                uint32_t b0 = *(const uint32_t*)&sP[s * 128 + wi + t * 8 + r][kk + 2 * cc];
                uint32_t b1 = *(const uint32_t*)&sP[s * 128 + wi + t * 8 + r][kk + 2 * cc + 8];
#pragma unroll
                for (int m = 0; m < 2; m++) mma_bf16(acc[m][t], a[m], b0, b1);
            }
        }
    }

    // ---- a_c epilogue: acc += m_c[n] @ vT (K = 64 channels d) ----
    cp_wait0();
    __syncthreads();                      // buffers now reusable
    __nv_bfloat16 (*sMc)[72] = (__nv_bfloat16(*)[72])sbuf;           // [64][72]
    __nv_bfloat16 (*sVT)[72] = (__nv_bfloat16(*)[72])(sbuf + 9216);  // [128][72]
#pragma unroll
    for (int v = 0; v < 2; v++) {         // m_c: 64x64 bf16 = 512 x 16B
        int e = tid + v * 256;
        int row = e >> 3, p8 = (e & 7) * 8;
        cp_async16(&sMc[row][p8], g_mc16 + n * 4096 + row * 64 + p8);
    }
#pragma unroll
    for (int v = 0; v < 4; v++) {         // vT tile: 128x64 bf16 = 1024 x 16B
        int e = tid + v * 256;
        int row = e >> 3, p8 = (e & 7) * 8;
        cp_async16(&sVT[row][p8], g_vT16 + n * PLANE + (it * 128 + row) * 64 + p8);
    }
    cp_commit(); cp_wait0();
    __syncthreads();
#pragma unroll
    for (int ks = 0; ks < 4; ks++) {
        int kk = ks * 16;
        uint32_t a[2][4];
#pragma unroll
        for (int m = 0; m < 2; m++) {
            int c0 = wc + m * 16;
            a[m][0] = *(const uint32_t*)&sMc[c0 + r][kk + 2 * cc];
            a[m][1] = *(const uint32_t*)&sMc[c0 + r + 8][kk + 2 * cc];
            a[m][2] = *(const uint32_t*)&sMc[c0 + r][kk + 2 * cc + 8];
            a[m][3] = *(const uint32_t*)&sMc[c0 + r + 8][kk + 2 * cc + 8];
        }
#pragma unroll
        for (int t = 0; t < 4; t++) {
            uint32_t b0 = *(const uint32_t*)&sVT[wi + t * 8 + r][kk + 2 * cc];
            uint32_t b1 = *(const uint32_t*)&sVT[wi + t * 8 + r][kk + 2 * cc + 8];
#pragma unroll
            for (int m = 0; m < 2; m++) mma_bf16(acc[m][t], a[m], b0, b1);
        }
    }

    // ---- store bf16 ----
#pragma unroll
    for (int m = 0; m < 2; m++)
#pragma unroll
        for (int t = 0; t < 4; t++) {
            int c0 = wc + m * 16 + r;
            int i0 = it * 128 + wi + t * 8 + cc * 2;
            __nv_bfloat162 p0 = __floats2bfloat162_rn(acc[m][t][0], acc[m][t][1]);
            __nv_bfloat162 p1 = __floats2bfloat162_rn(acc[m][t][2], acc[m][t][3]);
            *(uint32_t*)&g_A16[n * PLANE + c0 * HWD + i0] = *(uint32_t*)&p0;
            *(uint32_t*)&g_A16[n * PLANE + (c0 + 8) * HWD + i0] = *(uint32_t*)&p1;
        }
}

// ---- temporal conv (3,1,1) pad 1 + relu -> g_Xe16 (bf16) ----
__global__ void k_tconv(const float* __restrict__ wX, const float* __restrict__ bX) {
    __shared__ float sA[32][132];
    __shared__ float sW[64][68];
    int n = blockIdx.y, it = blockIdx.x;
    int b = n >> 3, t = n & 7;
    int tid = threadIdx.x, tx = tid & 15, ty = tid >> 4;
    float acc[4][8] = {};
    for (int kk = 0; kk < 3; kk++) {
        int tp = t + kk - 1;
        if (tp < 0 || tp >= 8) continue;
        __syncthreads();
        for (int idx = tid; idx < 4096; idx += 256) {
            int o = idx >> 6, c = idx & 63;
            sW[o][c] = wX[o * 192 + c * 3 + kk];
        }
        for (int ch = 0; ch < 2; ch++) {
            __syncthreads();
            for (int e = tid; e < 2048; e += 256) {       // 2048 bf16 pairs
                int c = e >> 6, ii = (e & 63) * 2;
                uint32_t u = *(const uint32_t*)&g_A16[(b * 8 + tp) * PLANE +
                                (ch * 32 + c) * HWD + it * 128 + ii];
                float2 f = __bfloat1622float2(*(__nv_bfloat162*)&u);
                sA[c][ii] = f.x; sA[c][ii + 1] = f.y;
            }
            __syncthreads();
#pragma unroll 4
            for (int c = 0; c < 32; c++) {
                float rw[4];
#pragma unroll
                for (int v = 0; v < 4; v++) rw[v] = sW[ty * 4 + v][ch * 32 + c];
                float4 aa = *(const float4*)&sA[c][tx * 8];
                float4 ab = *(const float4*)&sA[c][tx * 8 + 4];
                float ra[8] = {aa.x, aa.y, aa.z, aa.w, ab.x, ab.y, ab.z, ab.w};
#pragma unroll
                for (int v = 0; v < 4; v++)
#pragma unroll
                    for (int u = 0; u < 8; u++) acc[v][u] = fmaf(rw[v], ra[u], acc[v][u]);
            }
        }
    }
#pragma unroll
    for (int v = 0; v < 4; v++) {
        float bb = bX[ty * 4 + v];
#pragma unroll
        for (int u = 0; u < 8; u += 2) {
            float r0 = fmaxf(acc[v][u] + bb, 0.f);
            float r1 = fmaxf(acc[v][u + 1] + bb, 0.f);
            __nv_bfloat162 p = __floats2bfloat162_rn(r0, r1);
            *(uint32_t*)&g_Xe16[n * PLANE + (ty * 4 + v) * HWD + it * 128 + tx * 8 + u] =
                *(uint32_t*)&p;
        }
    }
}

// ---- temporal Gram: g_tl[b,t,s] += partial dot over d-slice (bf16 Xe) ----
__global__ void k_tl() {
    __shared__ float sXe[8][1032];
    int b = blockIdx.y;
    int d0 = blockIdx.x * 1024;
    int tid = threadIdx.x;
#pragma unroll
    for (int v = 0; v < 4; v++) {
        int e = tid + v * 256;          // 0..1023 uint4s (8 bf16 each)
        int t = e >> 7;
        int d8 = (e & 127) * 8;
        uint4 raw = *(const uint4*)&g_Xe16[(b * 8 + t) * PLANE + d0 + d8];
        uint32_t* pu = (uint32_t*)&raw;
#pragma unroll
        for (int w = 0; w < 4; w++) {
            float2 f = __bfloat1622float2(*(__nv_bfloat162*)&pu[w]);
            sXe[t][d8 + 2 * w] = f.x; sXe[t][d8 + 2 * w + 1] = f.y;
        }
    }
    __syncthreads();
    int p = tid >> 2, sub = tid & 3;
    int t = p >> 3, s = p & 7;
    float acc = 0.f;
#pragma unroll 8
    for (int it = 0; it < 64; it++) {
        int col = sub * 4 + it * 16;
        float4 a = *(const float4*)&sXe[t][col];
        float4 c = *(const float4*)&sXe[s][col];
        acc += a.x * c.x + a.y * c.y + a.z * c.z + a.w * c.w;
    }
    acc += __shfl_xor_sync(0xffffffff, acc, 1);
    acc += __shfl_xor_sync(0xffffffff, acc, 2);
    if (sub == 0) atomicAdd(&g_tl[b * 64 + p], acc);
}

__global__ void k_softmax_t() {
    int p = threadIdx.x;
    float v0 = g_tl[p], v1 = g_tl[64 + p], v2 = g_tl[128 + p], v3 = g_tl[192 + p];
    float mx = fmaxf(fmaxf(v0, v1), fmaxf(v2, v3));
    v0 = __expf(v0 - mx); v1 = __expf(v1 - mx); v2 = __expf(v2 - mx); v3 = __expf(v3 - mx);
    float inv = 1.f / (v0 + v1 + v2 + v3);
    g_tl[p] = v0 * inv; g_tl[64 + p] = v1 * inv;
    g_tl[128 + p] = v2 * inv; g_tl[192 + p] = v3 * inv;
}

__global__ void k_out(float* __restrict__ out) {
    __shared__ float sM[64];
    int gid = blockIdx.x * 256 + threadIdx.x;
    int b = gid >> 16;
    if (threadIdx.x < 64) sM[threadIdx.x] = g_tl[b * 64 + threadIdx.x];
    __syncthreads();
    int rem = gid & 65535;
    int c = rem >> 10, i = rem & 1023;
    float vv[8];
#pragma unroll
    for (int s = 0; s < 8; s++) vv[s] = g_v[(b * 8 + s) * PLANE + c * HWD + i];
#pragma unroll
    for (int t = 0; t < 8; t++) {
        float rsum = 0.f;
#pragma unroll
        for (int s = 0; s < 8; s++) rsum = fmaf(sM[t * 8 + s], vv[s], rsum);
        out[((b * 64 + c) * 8 + t) * HWD + i] = rsum;
    }
}

// ============================================================
extern "C" void kernel_launch(void* const* d_in, const int* in_sizes, int n_in,
                              void* d_out, int out_size) {
    const float* x  = (const float*)d_in[0];
    const float* wq = (const float*)d_in[1];
    const float* bq = (const float*)d_in[2];
    const float* wk = (const float*)d_in[3];
    const float* bk = (const float*)d_in[4];
    const float* wv = (const float*)d_in[5];
    const float* bv = (const float*)d_in[6];
    const float* wX = (const float*)d_in[7];
    const float* bX = (const float*)d_in[8];
    float* out = (float*)d_out;

    k_qkv<<<512, 256>>>(x, wq, bq, wk, bk, wv, bv);        // 0
    k_cl<<<32, 256>>>();                                   // 1
    k_softmax_c<<<16, 256>>>();                            // 2
    k_slogits<<<dim3(8, 8, 32), 256>>>();                  // 3  <- ncu capture slot
    k_smax<<<2048, 256>>>();                               // 4
    k_as<<<dim3(8, 32), 256>>>();                          // 5
    k_tconv<<<dim3(8, 32), 256>>>(wX, bX);                 // 6
    k_tl<<<dim3(64, 4), 256>>>();                          // 7
    k_softmax_t<<<1, 64>>>();                              // 8
    k_out<<<1024, 256>>>(out);                             // 9
}

// round 15
// speedup vs baseline: 2.0296x; 1.1566x over previous
#include <cuda_runtime.h>
#include <cuda_bf16.h>
#include <cstdint>

#define N_BT  32
#define HWD   1024
#define CHN   64
#define PLANE 65536      /* CHN*HWD */
#define TOT   2097152    /* N_BT*PLANE */

// ---- scratch (module-load allocated, legal) ----
__device__ __nv_bfloat16 g_qT16[TOT];  // [n][i][c]  (k_slogits)
__device__ __nv_bfloat16 g_kT16[TOT];  // [n][j][c]
__device__ __nv_bfloat16 g_q16[TOT];   // [n][c][i]  (k_cl)
__device__ __nv_bfloat16 g_k16[TOT];   // [n][c][i]
__device__ float g_v [TOT];            // [n][c][i] fp32 (k_out)
__device__ __nv_bfloat16 g_v16[TOT];   // [n][c][i] bf16 (k_as A)
__device__ __nv_bfloat16 g_vT16[TOT];  // [n][i][c] bf16 (k_as a_c epilogue B)
__device__ __nv_bfloat16 g_A16[TOT];   // a_s + a_c   [n][i][c] bf16 (TRANSPOSED)
__device__ __nv_bfloat16 g_Xe16[TOT];  // [n][c][i] bf16
__device__ float g_cl[N_BT * 64 * 64];
__device__ __nv_bfloat16 g_mc16[N_BT * 64 * 64];  // m_c bf16 [n][c][d]
__device__ float g_tl[256];
__device__ __nv_bfloat16 g_L16[N_BT << 20]; // 64 MB spatial logits (bf16)
__device__ __nv_bfloat16 g_P16[N_BT << 20]; // 64 MB softmaxed probabilities (bf16)

__device__ __forceinline__ void mma_bf16(float* d, const uint32_t* a,
                                         uint32_t b0, uint32_t b1) {
    asm volatile(
        "mma.sync.aligned.m16n8k16.row.col.f32.bf16.bf16.f32 "
        "{%0,%1,%2,%3}, {%4,%5,%6,%7}, {%8,%9}, {%0,%1,%2,%3};\n"
        : "+f"(d[0]), "+f"(d[1]), "+f"(d[2]), "+f"(d[3])
        : "r"(a[0]), "r"(a[1]), "r"(a[2]), "r"(a[3]), "r"(b0), "r"(b1));
}

__device__ __forceinline__ void cp_async16(void* smem_dst, const void* gsrc) {
    uint32_t d = (uint32_t)__cvta_generic_to_shared(smem_dst);
    asm volatile("cp.async.cg.shared.global [%0], [%1], 16;\n" :: "r"(d), "l"(gsrc));
}
__device__ __forceinline__ void cp_commit() { asm volatile("cp.async.commit_group;\n"); }
__device__ __forceinline__ void cp_wait1()  { asm volatile("cp.async.wait_group 1;\n"); }
__device__ __forceinline__ void cp_wait0()  { asm volatile("cp.async.wait_group 0;\n"); }

// ============================================================
// ---- QKV fused: relu(W x + b). q,k -> bf16 [n][i][c] AND [n][c][i];
//      v -> fp32/bf16 [n][c][i] + vT bf16 [n][i][c]; zeroes g_tl.
__global__ void k_qkv(const float* __restrict__ x,
                      const float* __restrict__ wq, const float* __restrict__ bq,
                      const float* __restrict__ wk, const float* __restrict__ bk,
                      const float* __restrict__ wv, const float* __restrict__ bv) {
    __shared__ float sX[64][68];
    __shared__ float sW[64][68];
    int tid = threadIdx.x;
    int pt = blockIdx.x;
    if (pt == 0) g_tl[tid] = 0.f;
    int n  = pt >> 4;
    int i0 = (pt & 15) << 6;
    int b = n >> 3, t = n & 7;
    const float* ws[3] = {wq, wk, wv};
    const float* bs[3] = {bq, bk, bv};
    for (int idx = tid; idx < 4096; idx += 256) {
        int c = idx >> 6, p = idx & 63;
        sX[c][p] = x[((b * 64 + c) * 8 + t) * 1024 + i0 + p];
    }
    int tx = tid & 15, ty = tid >> 4;
    for (int ph = 0; ph < 3; ph++) {
        __syncthreads();
        for (int idx = tid; idx < 4096; idx += 256)
            sW[idx >> 6][idx & 63] = ws[ph][idx];
        __syncthreads();
        float acc[4][4] = {};
#pragma unroll
        for (int c = 0; c < 64; c++) {
            float4 a4 = *(const float4*)&sX[c][tx * 4];
            float ra[4] = {a4.x, a4.y, a4.z, a4.w};
            float rb[4];
#pragma unroll
            for (int v = 0; v < 4; v++) rb[v] = sW[ty * 4 + v][c];
#pragma unroll
            for (int v = 0; v < 4; v++)
#pragma unroll
                for (int u = 0; u < 4; u++) acc[v][u] = fmaf(rb[v], ra[u], acc[v][u]);
        }
#pragma unroll
        for (int v = 0; v < 4; v++) {
            float bb = bs[ph][ty * 4 + v];
#pragma unroll
            for (int u = 0; u < 4; u++) acc[v][u] = fmaxf(acc[v][u] + bb, 0.f);
        }
        if (ph == 2) {
            // direct [c][i] stores (fp32 + bf16)
#pragma unroll
            for (int v = 0; v < 4; v++)
#pragma unroll
                for (int u = 0; u < 4; u++) {
                    int a = n * PLANE + (ty * 4 + v) * HWD + i0 + tx * 4 + u;
                    g_v[a] = acc[v][u];
                    g_v16[a] = __float2bfloat16(acc[v][u]);
                }
            // transpose -> vT [i][c]
            __syncthreads();
#pragma unroll
            for (int v = 0; v < 4; v++)
#pragma unroll
                for (int u = 0; u < 4; u++)
                    sW[ty * 4 + v][tx * 4 + u] = acc[v][u];
            __syncthreads();
            for (int idx = tid; idx < 4096; idx += 256) {
                int li = idx >> 6, o = idx & 63;
                g_vT16[n * PLANE + (i0 + li) * 64 + o] = __float2bfloat16(sW[o][li]);
            }
        } else {
            // direct [c][i] bf16 store for k_cl
            __nv_bfloat16* dirp = (ph == 0) ? g_q16 : g_k16;
#pragma unroll
            for (int v = 0; v < 4; v++)
#pragma unroll
                for (int u = 0; u < 4; u++)
                    dirp[n * PLANE + (ty * 4 + v) * HWD + i0 + tx * 4 + u] =
                        __float2bfloat16(acc[v][u]);
            // transposed [i][c] store for k_slogits
            __syncthreads();
#pragma unroll
            for (int v = 0; v < 4; v++)
#pragma unroll
                for (int u = 0; u < 4; u++)
                    sW[ty * 4 + v][tx * 4 + u] = acc[v][u];
            __syncthreads();
            __nv_bfloat16* outp = (ph == 0) ? g_qT16 : g_kT16;
            for (int idx = tid; idx < 4096; idx += 256) {
                int li = idx >> 6, o = idx & 63;
                outp[n * PLANE + (i0 + li) * 64 + o] = __float2bfloat16(sW[o][li]);
            }
        }
    }
}

// ---- channel logits via bf16 MMA: cl[n,c,d] = sum_i q[c,i] k[d,i] (fp32 out) ----
__global__ void __launch_bounds__(256, 2) k_cl() {
    __shared__ __align__(16) __nv_bfloat16 sQ[3][64][40];
    __shared__ __align__(16) __nv_bfloat16 sK[3][64][40];
    int n = blockIdx.x;
    int tid = threadIdx.x;
    const __nv_bfloat16* qb = g_q16 + n * PLANE;
    const __nv_bfloat16* kb = g_k16 + n * PLANE;

    auto stage = [&](int ch) {
        int s = ch % 3;
        int i0 = ch * 32;
        {
            int row = tid >> 2;
            int p8 = (tid & 3) * 8;
            cp_async16(&sQ[s][row][p8], qb + row * HWD + i0 + p8);
            cp_async16(&sK[s][row][p8], kb + row * HWD + i0 + p8);
        }
        cp_commit();
    };
    stage(0); stage(1);

    int warp = tid >> 5, lane = tid & 31;
    int r = lane >> 2, cc = lane & 3;
    int wc = (warp & 1) * 32;
    int wd = (warp >> 1) * 16;
    float acc[2][2][4] = {};

    for (int ch = 0; ch < 32; ch++) {
        cp_wait1();
        __syncthreads();
        if (ch + 2 < 32) stage(ch + 2);
        else cp_commit();
        int s = ch % 3;
#pragma unroll
        for (int ks = 0; ks < 2; ks++) {
            int kk = ks * 16;
            uint32_t a[2][4];
#pragma unroll
            for (int m = 0; m < 2; m++) {
                int c0 = wc + m * 16;
                a[m][0] = *(const uint32_t*)&sQ[s][c0 + r][kk + 2 * cc];
                a[m][1] = *(const uint32_t*)&sQ[s][c0 + r + 8][kk + 2 * cc];
                a[m][2] = *(const uint32_t*)&sQ[s][c0 + r][kk + 2 * cc + 8];
                a[m][3] = *(const uint32_t*)&sQ[s][c0 + r + 8][kk + 2 * cc + 8];
            }
#pragma unroll
            for (int t = 0; t < 2; t++) {
                uint32_t b0 = *(const uint32_t*)&sK[s][wd + t * 8 + r][kk + 2 * cc];
                uint32_t b1 = *(const uint32_t*)&sK[s][wd + t * 8 + r][kk + 2 * cc + 8];
#pragma unroll
                for (int m = 0; m < 2; m++) mma_bf16(acc[m][t], a[m], b0, b1);
            }
        }
    }
#pragma unroll
    for (int m = 0; m < 2; m++)
#pragma unroll
        for (int t = 0; t < 2; t++) {
            int c0 = wc + m * 16 + r;
            int d0 = wd + t * 8 + cc * 2;
            float2 o0 = {acc[m][t][0], acc[m][t][1]};
            float2 o1 = {acc[m][t][2], acc[m][t][3]};
            *(float2*)&g_cl[n * 4096 + c0 * 64 + d0] = o0;
            *(float2*)&g_cl[n * 4096 + (c0 + 8) * 64 + d0] = o1;
        }
}

// ---- softmax over n on (n,c,d) -> m_c bf16 ----
__global__ void k_softmax_c() {
    int p = blockIdx.x * 256 + threadIdx.x;
    float vals[32], mx = -1e30f;
#pragma unroll
    for (int nn = 0; nn < 32; nn++) { vals[nn] = g_cl[nn * 4096 + p]; mx = fmaxf(mx, vals[nn]); }
    float s = 0.f;
#pragma unroll
    for (int nn = 0; nn < 32; nn++) { vals[nn] = __expf(vals[nn] - mx); s += vals[nn]; }
    float inv = 1.f / s;
#pragma unroll
    for (int nn = 0; nn < 32; nn++)
        g_mc16[nn * 4096 + p] = __float2bfloat16(vals[nn] * inv);
}

// ---- spatial logits via bf16 MMA: L[n,i,j] = sum_c q[i,c] k[j,c] -> bf16 ----
__global__ void __launch_bounds__(256, 2) k_slogits() {
    __shared__ __align__(16) __nv_bfloat16 sQK[2][128][72];
    int jt = blockIdx.x, it = blockIdx.y, n = blockIdx.z;
    int tid = threadIdx.x;
    const __nv_bfloat16* qb = g_qT16 + n * PLANE + (it * 128) * 64;
    const __nv_bfloat16* kb = g_kT16 + n * PLANE + (jt * 128) * 64;

#pragma unroll
    for (int v = 0; v < 8; v++) {
        int e = tid + v * 256;
        int row = e >> 3;
        int p8 = (e & 7) * 8;
        const __nv_bfloat16* src = (row < 128) ? (qb + row * 64 + p8)
                                               : (kb + (row - 128) * 64 + p8);
        cp_async16(&sQK[row >> 7][row & 127][p8], src);
    }
    cp_commit(); cp_wait0();
    __syncthreads();

    int warp = tid >> 5, lane = tid & 31;
    int r = lane >> 2, cc = lane & 3;
    int wi = (warp & 3) * 32;
    int wj = (warp >> 2) * 64;
    float acc[2][8][4] = {};

#pragma unroll
    for (int ks = 0; ks < 4; ks++) {
        int kk = ks * 16;
        uint32_t a[2][4];
#pragma unroll
        for (int m = 0; m < 2; m++) {
            int i0 = wi + m * 16;
            a[m][0] = *(const uint32_t*)&sQK[0][i0 + r][kk + 2 * cc];
            a[m][1] = *(const uint32_t*)&sQK[0][i0 + r + 8][kk + 2 * cc];
            a[m][2] = *(const uint32_t*)&sQK[0][i0 + r][kk + 2 * cc + 8];
            a[m][3] = *(const uint32_t*)&sQK[0][i0 + r + 8][kk + 2 * cc + 8];
        }
#pragma unroll
        for (int t = 0; t < 8; t++) {
            uint32_t b0 = *(const uint32_t*)&sQK[1][wj + t * 8 + r][kk + 2 * cc];
            uint32_t b1 = *(const uint32_t*)&sQK[1][wj + t * 8 + r][kk + 2 * cc + 8];
#pragma unroll
            for (int m = 0; m < 2; m++) mma_bf16(acc[m][t], a[m], b0, b1);
        }
    }

    __syncthreads();
    uint32_t (*stg)[68] = (uint32_t(*)[68])sQK;
#pragma unroll
    for (int m = 0; m < 2; m++)
#pragma unroll
        for (int t = 0; t < 8; t++) {
            int rowl = wi + m * 16 + r;
            int colw = (wj + t * 8) / 2 + cc;
            __nv_bfloat162 lo = __floats2bfloat162_rn(acc[m][t][0], acc[m][t][1]);
            __nv_bfloat162 hi = __floats2bfloat162_rn(acc[m][t][2], acc[m][t][3]);
            stg[rowl][colw]     = *(uint32_t*)&lo;
            stg[rowl + 8][colw] = *(uint32_t*)&hi;
        }
    __syncthreads();
#pragma unroll
    for (int v = 0; v < 8; v++) {
        int e = tid + v * 256;
        int row = e >> 4, q = e & 15;
        uint4 val = *(uint4*)&stg[row][q * 4];
        __nv_bfloat16* dst = g_L16 + ((size_t)n << 20) + (it * 128 + row) * 1024
                             + jt * 128 + q * 8;
        *(uint4*)dst = val;
    }
}

// ---- per-(i,j) softmax over n -> P bf16. 2 idx/thread, convert ONCE, exp ONCE ----
__global__ void k_smax() {
    int base = (blockIdx.x * 256 + threadIdx.x) * 2;
    float f[64];
#pragma unroll
    for (int nn = 0; nn < 32; nn++) {
        uint32_t u = *(const uint32_t*)&g_L16[((size_t)nn << 20) + base];
        float2 fp = __bfloat1622float2(*(__nv_bfloat162*)&u);
        f[2 * nn] = fp.x; f[2 * nn + 1] = fp.y;
    }
    float mx0 = -1e30f, mx1 = -1e30f;
#pragma unroll
    for (int nn = 0; nn < 32; nn++) {
        mx0 = fmaxf(mx0, f[2 * nn]); mx1 = fmaxf(mx1, f[2 * nn + 1]);
    }
    float s0 = 0.f, s1 = 0.f;
#pragma unroll
    for (int nn = 0; nn < 32; nn++) {
        f[2 * nn]     = __expf(f[2 * nn] - mx0);     s0 += f[2 * nn];
        f[2 * nn + 1] = __expf(f[2 * nn + 1] - mx1); s1 += f[2 * nn + 1];
    }
    float inv0 = 1.f / s0, inv1 = 1.f / s1;
#pragma unroll
    for (int nn = 0; nn < 32; nn++) {
        __nv_bfloat162 p = __floats2bfloat162_rn(f[2 * nn] * inv0, f[2 * nn + 1] * inv1);
        *(uint32_t*)&g_P16[((size_t)nn << 20) + base] = *(uint32_t*)&p;
    }
}

// ---- a_s = V @ P^T + a_c = m_c @ v  (bf16 MMA); g_A16 = result TRANSPOSED [i][c] ----
// grid (it8, n32); block: c64 (M) x i128 (N).
__global__ void __launch_bounds__(256, 2) k_as() {
    __shared__ __align__(16) char sbuf[46080];
    __nv_bfloat16 (*sP)[40] = (__nv_bfloat16(*)[40])sbuf;            // [3][128][40]
    __nv_bfloat16 (*sV)[40] = (__nv_bfloat16(*)[40])(sbuf + 30720);  // [3][64][40]
    int it = blockIdx.x, n = blockIdx.y;
    int tid = threadIdx.x;
    const __nv_bfloat16* vb = g_v16 + n * PLANE;
    const __nv_bfloat16* pb = g_P16 + ((size_t)n << 20) + (it * 128) * 1024;

    auto stage = [&](int ch) {
        int s = ch % 3;
        int j0 = ch * 32;
#pragma unroll
        for (int v = 0; v < 2; v++) {
            int e = tid + v * 256;
            int row = e >> 2;
            int p8 = (e & 3) * 8;
            cp_async16(&sP[s * 128 + row][p8], pb + row * 1024 + j0 + p8);
        }
        {
            int row = tid >> 2;
            int p8 = (tid & 3) * 8;
            cp_async16(&sV[s * 64 + row][p8], vb + row * 1024 + j0 + p8);
        }
        cp_commit();
    };
    stage(0); stage(1);

    int warp = tid >> 5, lane = tid & 31;
    int r = lane >> 2, cc = lane & 3;
    int wc = (warp & 1) * 32;            // 2 warps along c (M)
    int wi = (warp >> 1) * 32;           // 4 warps along i (N)
    float acc[2][4][4] = {};

    for (int ch = 0; ch < 32; ch++) {
        cp_wait1();
        __syncthreads();
        if (ch + 2 < 32) stage(ch + 2);
        else cp_commit();
        int s = ch % 3;
#pragma unroll
        for (int ks = 0; ks < 2; ks++) {
            int kk = ks * 16;
            uint32_t a[2][4];
#pragma unroll
            for (int m = 0; m < 2; m++) {
                int c0 = wc + m * 16;
                a[m][0] = *(const uint32_t*)&sV[s * 64 + c0 + r][kk + 2 * cc];
                a[m][1] = *(const uint32_t*)&sV[s * 64 + c0 + r + 8][kk + 2 * cc];
                a[m][2] = *(const uint32_t*)&sV[s * 64 + c0 + r][kk + 2 * cc + 8];
                a[m][3] = *(const uint32_t*)&sV[s * 64 + c0 + r + 8][kk + 2 * cc + 8];
            }
#pragma unroll
            for (int t = 0; t < 4; t++) {
                uint32_t b0 = *(const uint32_t*)&sP[s * 128 + wi + t * 8 + r][kk + 2 * cc];
                uint32_t b1 = *(const uint32_t*)&sP[s * 128 + wi + t * 8 + r][kk + 2 * cc + 8];
#pragma unroll
                for (int m = 0; m < 2; m++) mma_bf16(acc[m][t], a[m], b0, b1);
            }
        }
    }

    // ---- a_c epilogue: acc += m_c[n] @ vT (K = 64 channels d) ----
    cp_wait0();
    __syncthreads();
    __nv_bfloat16 (*sMc)[72] = (__nv_bfloat16(*)[72])sbuf;           // [64][72]
    __nv_bfloat16 (*sVT)[72] = (__nv_bfloat16(*)[72])(sbuf + 9216);  // [128][72]
#pragma unroll
    for (int v = 0; v < 2; v++) {
        int e = tid + v * 256;
        int row = e >> 3, p8 = (e & 7) * 8;
        cp_async16(&sMc[row][p8], g_mc16 + n * 4096 + row * 64 + p8);
    }
#pragma unroll
    for (int v = 0; v < 4; v++) {
        int e = tid + v * 256;
        int row = e >> 3, p8 = (e & 7) * 8;
        cp_async16(&sVT[row][p8], g_vT16 + n * PLANE + (it * 128 + row) * 64 + p8);
    }
    cp_commit(); cp_wait0();
    __syncthreads();
#pragma unroll
    for (int ks = 0; ks < 4; ks++) {
        int kk = ks * 16;
        uint32_t a[2][4];
#pragma unroll
        for (int m = 0; m < 2; m++) {
            int c0 = wc + m * 16;
            a[m][0] = *(const uint32_t*)&sMc[c0 + r][kk + 2 * cc];
            a[m][1] = *(const uint32_t*)&sMc[c0 + r + 8][kk + 2 * cc];
            a[m][2] = *(const uint32_t*)&sMc[c0 + r][kk + 2 * cc + 8];
            a[m][3] = *(const uint32_t*)&sMc[c0 + r + 8][kk + 2 * cc + 8];
        }
#pragma unroll
        for (int t = 0; t < 4; t++) {
            uint32_t b0 = *(const uint32_t*)&sVT[wi + t * 8 + r][kk + 2 * cc];
            uint32_t b1 = *(const uint32_t*)&sVT[wi + t * 8 + r][kk + 2 * cc + 8];
#pragma unroll
            for (int m = 0; m < 2; m++) mma_bf16(acc[m][t], a[m], b0, b1);
        }
    }

    // ---- store A^T [i][c] bf16 via smem staging ----
    __syncthreads();     // all fragment LDS reads done before overwriting sbuf
    __nv_bfloat16 (*sAT)[72] = (__nv_bfloat16(*)[72])sbuf;           // [128][72]
#pragma unroll
    for (int m = 0; m < 2; m++)
#pragma unroll
        for (int t = 0; t < 4; t++) {
            int c0 = wc + m * 16 + r;
            int i0 = wi + t * 8 + cc * 2;
            sAT[i0][c0]         = __float2bfloat16(acc[m][t][0]);
            sAT[i0 + 1][c0]     = __float2bfloat16(acc[m][t][1]);
            sAT[i0][c0 + 8]     = __float2bfloat16(acc[m][t][2]);
            sAT[i0 + 1][c0 + 8] = __float2bfloat16(acc[m][t][3]);
        }
    __syncthreads();
#pragma unroll
    for (int v = 0; v < 4; v++) {
        int e = tid + v * 256;       // 1024 chunks: 128 rows x 8
        int row = e >> 3, p8 = (e & 7) * 8;
        uint4 val = *(uint4*)&sAT[row][p8];
        *(uint4*)&g_A16[n * PLANE + (it * 128 + row) * 64 + p8] = val;
    }
}

// ---- temporal conv via bf16 MMA: Xe[o,i] = relu(sum_{kk,c} W[o,kk,c] A[tp][i,c] + b) ----
// grid (it8, n32); block: o64 (M) x i128 (N); K=192 (3 taps x 64 c).
__global__ void __launch_bounds__(256, 2) k_tconv(const float* __restrict__ wX,
                                                  const float* __restrict__ bX) {
    __shared__ __align__(16) __nv_bfloat16 sW16[64][200];  // [o][kk*64+c], 192 used
    __shared__ __align__(16) __nv_bfloat16 sAT[128][72];   // [i][c] per tap
    int it = blockIdx.x, n = blockIdx.y;
    int b = n >> 3, t = n & 7;
    int tid = threadIdx.x;

    // load + convert weights wX[o][c][kk] -> sW16[o][kk*64+c]
    for (int idx = tid; idx < 12288; idx += 256) {
        int o = idx / 192, rem = idx % 192;
        int c = rem / 3, kk = rem % 3;
        sW16[o][kk * 64 + c] = __float2bfloat16(wX[idx]);
    }

    int warp = tid >> 5, lane = tid & 31;
    int r = lane >> 2, cc = lane & 3;
    int wc = (warp & 1) * 32;            // 2 warps along o (M)
    int wi = (warp >> 1) * 32;           // 4 warps along i (N)
    float acc[2][4][4] = {};

    for (int kk = 0; kk < 3; kk++) {
        int tp = t + kk - 1;
        if (tp < 0 || tp >= 8) continue;
        __syncthreads();                 // prior mma reads of sAT (and sW16 writes) done
        const __nv_bfloat16* ab = g_A16 + (b * 8 + tp) * PLANE + (it * 128) * 64;
#pragma unroll
        for (int v = 0; v < 4; v++) {
            int e = tid + v * 256;
            int row = e >> 3, p8 = (e & 7) * 8;
            cp_async16(&sAT[row][p8], ab + row * 64 + p8);
        }
        cp_commit(); cp_wait0();
        __syncthreads();
#pragma unroll
        for (int ks = 0; ks < 4; ks++) {
            int kw = kk * 64 + ks * 16;
            int ka = ks * 16;
            uint32_t a[2][4];
#pragma unroll
            for (int m = 0; m < 2; m++) {
                int o0 = wc + m * 16;
                a[m][0] = *(const uint32_t*)&sW16[o0 + r][kw + 2 * cc];
                a[m][1] = *(const uint32_t*)&sW16[o0 + r + 8][kw + 2 * cc];
                a[m][2] = *(const uint32_t*)&sW16[o0 + r][kw + 2 * cc + 8];
                a[m][3] = *(const uint32_t*)&sW16[o0 + r + 8][kw + 2 * cc + 8];
            }
#pragma unroll
            for (int tt = 0; tt < 4; tt++) {
                uint32_t b0 = *(const uint32_t*)&sAT[wi + tt * 8 + r][ka + 2 * cc];
                uint32_t b1 = *(const uint32_t*)&sAT[wi + tt * 8 + r][ka + 2 * cc + 8];
#pragma unroll
                for (int m = 0; m < 2; m++) mma_bf16(acc[m][tt], a[m], b0, b1);
            }
        }
    }

    // bias + relu + bf16 pack -> g_Xe16 [n][c][i]
#pragma unroll
    for (int m = 0; m < 2; m++)
#pragma unroll
        for (int tt = 0; tt < 4; tt++) {
            int o0 = wc + m * 16 + r;
            int i0 = it * 128 + wi + tt * 8 + cc * 2;
            float b0f = bX[o0], b1f = bX[o0 + 8];
            float r00 = fmaxf(acc[m][tt][0] + b0f, 0.f);
            float r01 = fmaxf(acc[m][tt][1] + b0f, 0.f);
            float r10 = fmaxf(acc[m][tt][2] + b1f, 0.f);
            float r11 = fmaxf(acc[m][tt][3] + b1f, 0.f);
            __nv_bfloat162 p0 = __floats2bfloat162_rn(r00, r01);
            __nv_bfloat162 p1 = __floats2bfloat162_rn(r10, r11);
            *(uint32_t*)&g_Xe16[n * PLANE + o0 * HWD + i0] = *(uint32_t*)&p0;
            *(uint32_t*)&g_Xe16[n * PLANE + (o0 + 8) * HWD + i0] = *(uint32_t*)&p1;
        }
}

// ---- temporal Gram: g_tl[b,t,s] += partial dot over d-slice (bf16 Xe) ----
__global__ void k_tl() {
    __shared__ float sXe[8][1032];
    int b = blockIdx.y;
    int d0 = blockIdx.x * 1024;
    int tid = threadIdx.x;
#pragma unroll
    for (int v = 0; v < 4; v++) {
        int e = tid + v * 256;
        int t = e >> 7;
        int d8 = (e & 127) * 8;
        uint4 raw = *(const uint4*)&g_Xe16[(b * 8 + t) * PLANE + d0 + d8];
        uint32_t* pu = (uint32_t*)&raw;
#pragma unroll
        for (int w = 0; w < 4; w++) {
            float2 f = __bfloat1622float2(*(__nv_bfloat162*)&pu[w]);
            sXe[t][d8 + 2 * w] = f.x; sXe[t][d8 + 2 * w + 1] = f.y;
        }
    }
    __syncthreads();
    int p = tid >> 2, sub = tid & 3;
    int t = p >> 3, s = p & 7;
    float acc = 0.f;
#pragma unroll 8
    for (int it = 0; it < 64; it++) {
        int col = sub * 4 + it * 16;
        float4 a = *(const float4*)&sXe[t][col];
        float4 c = *(const float4*)&sXe[s][col];
        acc += a.x * c.x + a.y * c.y + a.z * c.z + a.w * c.w;
    }
    acc += __shfl_xor_sync(0xffffffff, acc, 1);
    acc += __shfl_xor_sync(0xffffffff, acc, 2);
    if (sub == 0) atomicAdd(&g_tl[b * 64 + p], acc);
}

__global__ void k_softmax_t() {
    int p = threadIdx.x;
    float v0 = g_tl[p], v1 = g_tl[64 + p], v2 = g_tl[128 + p], v3 = g_tl[192 + p];
    float mx = fmaxf(fmaxf(v0, v1), fmaxf(v2, v3));
    v0 = __expf(v0 - mx); v1 = __expf(v1 - mx); v2 = __expf(v2 - mx); v3 = __expf(v3 - mx);
    float inv = 1.f / (v0 + v1 + v2 + v3);
    g_tl[p] = v0 * inv; g_tl[64 + p] = v1 * inv;
    g_tl[128 + p] = v2 * inv; g_tl[192 + p] = v3 * inv;
}

__global__ void k_out(float* __restrict__ out) {
    __shared__ float sM[64];
    int gid = blockIdx.x * 256 + threadIdx.x;
    int b = gid >> 16;
    if (threadIdx.x < 64) sM[threadIdx.x] = g_tl[b * 64 + threadIdx.x];
    __syncthreads();
    int rem = gid & 65535;
    int c = rem >> 10, i = rem & 1023;
    float vv[8];
#pragma unroll
    for (int s = 0; s < 8; s++) vv[s] = g_v[(b * 8 + s) * PLANE + c * HWD + i];
#pragma unroll
    for (int t = 0; t < 8; t++) {
        float rsum = 0.f;
#pragma unroll
        for (int s = 0; s < 8; s++) rsum = fmaf(sM[t * 8 + s], vv[s], rsum);
        out[((b * 64 + c) * 8 + t) * HWD + i] = rsum;
    }
}

// ============================================================
extern "C" void kernel_launch(void* const* d_in, const int* in_sizes, int n_in,
                              void* d_out, int out_size) {
    const float* x  = (const float*)d_in[0];
    const float* wq = (const float*)d_in[1];
    const float* bq = (const float*)d_in[2];
    const float* wk = (const float*)d_in[3];
    const float* bk = (const float*)d_in[4];
    const float* wv = (const float*)d_in[5];
    const float* bv = (const float*)d_in[6];
    const float* wX = (const float*)d_in[7];
    const float* bX = (const float*)d_in[8];
    float* out = (float*)d_out;

    k_qkv<<<512, 256>>>(x, wq, bq, wk, bk, wv, bv);        // 0
    k_cl<<<32, 256>>>();                                   // 1
    k_softmax_c<<<16, 256>>>();                            // 2
    k_slogits<<<dim3(8, 8, 32), 256>>>();                  // 3  <- ncu capture slot
    k_smax<<<2048, 256>>>();                               // 4
    k_as<<<dim3(8, 32), 256>>>();                          // 5
    k_tconv<<<dim3(8, 32), 256>>>(wX, bX);                 // 6
    k_tl<<<dim3(64, 4), 256>>>();                          // 7
    k_softmax_t<<<1, 64>>>();                              // 8
    k_out<<<1024, 256>>>(out);                             // 9
}

// round 16
// speedup vs baseline: 2.2377x; 1.1025x over previous
#include <cuda_runtime.h>
#include <cuda_bf16.h>
#include <cstdint>

#define N_BT  32
#define HWD   1024
#define CHN   64
#define PLANE 65536      /* CHN*HWD */
#define TOT   2097152    /* N_BT*PLANE */

// ---- scratch (module-load allocated, legal) ----
__device__ __nv_bfloat16 g_qT16[TOT];  // [n][i][c]  (k_slogits)
__device__ __nv_bfloat16 g_kT16[TOT];  // [n][j][c]
__device__ __nv_bfloat16 g_q16[TOT];   // [n][c][i]  (k_cl)
__device__ __nv_bfloat16 g_k16[TOT];   // [n][c][i]
__device__ float g_v [TOT];            // [n][c][i] fp32 (k_out)
__device__ __nv_bfloat16 g_v16[TOT];   // [n][c][i] bf16 (k_as A)
__device__ __nv_bfloat16 g_vT16[TOT];  // [n][i][c] bf16 (k_as a_c epilogue B)
__device__ __nv_bfloat16 g_A16[TOT];   // a_s + a_c   [n][i][c] bf16 (TRANSPOSED)
__device__ __nv_bfloat16 g_Xe16[TOT];  // [n][c][i] bf16
__device__ float g_cl[N_BT * 64 * 64];
__device__ __nv_bfloat16 g_mc16[N_BT * 64 * 64];  // m_c bf16 [n][c][d]
__device__ float g_tl[256];
__device__ __nv_bfloat16 g_L16[N_BT << 20]; // 64 MB spatial logits (bf16)
__device__ __nv_bfloat16 g_P16[N_BT << 20]; // 64 MB softmaxed probabilities (bf16)

__device__ __forceinline__ void mma_bf16(float* d, const uint32_t* a,
                                         uint32_t b0, uint32_t b1) {
    asm volatile(
        "mma.sync.aligned.m16n8k16.row.col.f32.bf16.bf16.f32 "
        "{%0,%1,%2,%3}, {%4,%5,%6,%7}, {%8,%9}, {%0,%1,%2,%3};\n"
        : "+f"(d[0]), "+f"(d[1]), "+f"(d[2]), "+f"(d[3])
        : "r"(a[0]), "r"(a[1]), "r"(a[2]), "r"(a[3]), "r"(b0), "r"(b1));
}

__device__ __forceinline__ void cp_async16(void* smem_dst, const void* gsrc) {
    uint32_t d = (uint32_t)__cvta_generic_to_shared(smem_dst);
    asm volatile("cp.async.cg.shared.global [%0], [%1], 16;\n" :: "r"(d), "l"(gsrc));
}
__device__ __forceinline__ void cp_commit() { asm volatile("cp.async.commit_group;\n"); }
__device__ __forceinline__ void cp_wait1()  { asm volatile("cp.async.wait_group 1;\n"); }
__device__ __forceinline__ void cp_wait0()  { asm volatile("cp.async.wait_group 0;\n"); }

// ============================================================
// ---- V projection (fp32 FFMA — output-critical precision path) ----
// v -> fp32 g_v + bf16 g_v16 [n][c][i] + transposed g_vT16 [n][i][c]; zeroes g_tl.
__global__ void k_v(const float* __restrict__ x,
                    const float* __restrict__ wv, const float* __restrict__ bv) {
    __shared__ float sX[64][68];
    __shared__ float sW[64][68];
    int tid = threadIdx.x;
    int pt = blockIdx.x;
    if (pt == 0) g_tl[tid] = 0.f;
    int n  = pt >> 4;
    int i0 = (pt & 15) << 6;
    int b = n >> 3, t = n & 7;
    for (int idx = tid; idx < 4096; idx += 256) {
        int c = idx >> 6, p = idx & 63;
        sX[c][p] = x[((b * 64 + c) * 8 + t) * 1024 + i0 + p];
        sW[c][p] = wv[idx];   // (c,p) reused as (o,cin)
    }
    __syncthreads();
    int tx = tid & 15, ty = tid >> 4;
    float acc[4][4] = {};
#pragma unroll
    for (int c = 0; c < 64; c++) {
        float4 a4 = *(const float4*)&sX[c][tx * 4];
        float ra[4] = {a4.x, a4.y, a4.z, a4.w};
        float rb[4];
#pragma unroll
        for (int v = 0; v < 4; v++) rb[v] = sW[ty * 4 + v][c];
#pragma unroll
        for (int v = 0; v < 4; v++)
#pragma unroll
            for (int u = 0; u < 4; u++) acc[v][u] = fmaf(rb[v], ra[u], acc[v][u]);
    }
#pragma unroll
    for (int v = 0; v < 4; v++) {
        float bb = bv[ty * 4 + v];
#pragma unroll
        for (int u = 0; u < 4; u++) acc[v][u] = fmaxf(acc[v][u] + bb, 0.f);
    }
    // direct [c][i] stores (fp32 + bf16)
#pragma unroll
    for (int v = 0; v < 4; v++)
#pragma unroll
        for (int u = 0; u < 4; u++) {
            int a = n * PLANE + (ty * 4 + v) * HWD + i0 + tx * 4 + u;
            g_v[a] = acc[v][u];
            g_v16[a] = __float2bfloat16(acc[v][u]);
        }
    // transpose -> vT [i][c]
    __syncthreads();
#pragma unroll
    for (int v = 0; v < 4; v++)
#pragma unroll
        for (int u = 0; u < 4; u++)
            sW[ty * 4 + v][tx * 4 + u] = acc[v][u];
    __syncthreads();
    for (int idx = tid; idx < 4096; idx += 256) {
        int li = idx >> 6, o = idx & 63;
        g_vT16[n * PLANE + (i0 + li) * 64 + o] = __float2bfloat16(sW[o][li]);
    }
}

// ---- Q/K projections via bf16 MMA ----
// grid (it8, n32); block: o64 (M) x i128 (N), K=64.
__global__ void __launch_bounds__(256, 2) k_qk(const float* __restrict__ x,
                                               const float* __restrict__ wq,
                                               const float* __restrict__ bq,
                                               const float* __restrict__ wk,
                                               const float* __restrict__ bk) {
    __shared__ __align__(16) __nv_bfloat16 sXT[128][72];   // [i][c]
    __shared__ __align__(16) __nv_bfloat16 sW2[2][64][72]; // [ph][o][c]
    int it = blockIdx.x, n = blockIdx.y;
    int b = n >> 3, t = n & 7;
    int tid = threadIdx.x;

    // load x tile (fp32, coalesced in i) -> transposed bf16 sXT
    for (int idx = tid; idx < 8192; idx += 256) {
        int c = idx >> 7, i = idx & 127;
        sXT[i][c] = __float2bfloat16(x[((b * 64 + c) * 8 + t) * 1024 + it * 128 + i]);
    }
    for (int idx = tid; idx < 4096; idx += 256) {
        int o = idx >> 6, c = idx & 63;
        sW2[0][o][c] = __float2bfloat16(wq[idx]);
        sW2[1][o][c] = __float2bfloat16(wk[idx]);
    }
    __syncthreads();

    int warp = tid >> 5, lane = tid & 31;
    int r = lane >> 2, cc = lane & 3;
    int wc = (warp & 1) * 32;            // 2 warps along o (M)
    int wi = (warp >> 1) * 32;           // 4 warps along i (N)

    for (int ph = 0; ph < 2; ph++) {
        const float* bias = ph ? bk : bq;
        float acc[2][4][4] = {};
#pragma unroll
        for (int ks = 0; ks < 4; ks++) {
            int kk = ks * 16;
            uint32_t a[2][4];
#pragma unroll
            for (int m = 0; m < 2; m++) {
                int o0 = wc + m * 16;
                a[m][0] = *(const uint32_t*)&sW2[ph][o0 + r][kk + 2 * cc];
                a[m][1] = *(const uint32_t*)&sW2[ph][o0 + r + 8][kk + 2 * cc];
                a[m][2] = *(const uint32_t*)&sW2[ph][o0 + r][kk + 2 * cc + 8];
                a[m][3] = *(const uint32_t*)&sW2[ph][o0 + r + 8][kk + 2 * cc + 8];
            }
#pragma unroll
            for (int tt = 0; tt < 4; tt++) {
                uint32_t b0 = *(const uint32_t*)&sXT[wi + tt * 8 + r][kk + 2 * cc];
                uint32_t b1 = *(const uint32_t*)&sXT[wi + tt * 8 + r][kk + 2 * cc + 8];
#pragma unroll
                for (int m = 0; m < 2; m++) mma_bf16(acc[m][tt], a[m], b0, b1);
            }
        }
        // bias + relu in place
#pragma unroll
        for (int m = 0; m < 2; m++) {
            int o0 = wc + m * 16 + r;
            float b0f = bias[o0], b1f = bias[o0 + 8];
#pragma unroll
            for (int tt = 0; tt < 4; tt++) {
                acc[m][tt][0] = fmaxf(acc[m][tt][0] + b0f, 0.f);
                acc[m][tt][1] = fmaxf(acc[m][tt][1] + b0f, 0.f);
                acc[m][tt][2] = fmaxf(acc[m][tt][2] + b1f, 0.f);
                acc[m][tt][3] = fmaxf(acc[m][tt][3] + b1f, 0.f);
            }
        }
        // direct [c][i] packed stores
        __nv_bfloat16* outp = ph ? g_k16 : g_q16;
#pragma unroll
        for (int m = 0; m < 2; m++)
#pragma unroll
            for (int tt = 0; tt < 4; tt++) {
                int o0 = wc + m * 16 + r;
                int i0g = it * 128 + wi + tt * 8 + cc * 2;
                __nv_bfloat162 p0 = __floats2bfloat162_rn(acc[m][tt][0], acc[m][tt][1]);
                __nv_bfloat162 p1 = __floats2bfloat162_rn(acc[m][tt][2], acc[m][tt][3]);
                *(uint32_t*)&outp[n * PLANE + o0 * HWD + i0g] = *(uint32_t*)&p0;
                *(uint32_t*)&outp[n * PLANE + (o0 + 8) * HWD + i0g] = *(uint32_t*)&p1;
            }
        // transposed [i][c] store staged through sW2[ph] (now dead), 2 halves
        __nv_bfloat16* outT = ph ? g_kT16 : g_qT16;
        __nv_bfloat16 (*stg)[72] = sW2[ph];
        int myhalf = wi >> 6;            // warp-uniform: 0 for wi<64, 1 otherwise
        for (int half = 0; half < 2; half++) {
            __syncthreads();             // all mma reads of sW2[ph] done / prev copy done
            if (myhalf == half) {
#pragma unroll
                for (int m = 0; m < 2; m++)
#pragma unroll
                    for (int tt = 0; tt < 4; tt++) {
                        int o0 = wc + m * 16 + r;
                        int il = wi + tt * 8 + cc * 2 - half * 64;
                        stg[il][o0]         = __float2bfloat16(acc[m][tt][0]);
                        stg[il + 1][o0]     = __float2bfloat16(acc[m][tt][1]);
                        stg[il][o0 + 8]     = __float2bfloat16(acc[m][tt][2]);
                        stg[il + 1][o0 + 8] = __float2bfloat16(acc[m][tt][3]);
                    }
            }
            __syncthreads();
            for (int e = tid; e < 512; e += 256) {   // 64 rows x 8 uint4
                int row = e >> 3, q8 = (e & 7) * 8;
                uint4 val = *(uint4*)&stg[row][q8];
                *(uint4*)&outT[n * PLANE + (it * 128 + half * 64 + row) * 64 + q8] = val;
            }
        }
        __syncthreads();                 // stg copy done before next phase reuses nothing, but keep ordering
    }
}

// ---- channel logits via bf16 MMA: cl[n,c,d] = sum_i q[c,i] k[d,i] (fp32 out) ----
__global__ void __launch_bounds__(256, 2) k_cl() {
    __shared__ __align__(16) __nv_bfloat16 sQ[3][64][40];
    __shared__ __align__(16) __nv_bfloat16 sK[3][64][40];
    int n = blockIdx.x;
    int tid = threadIdx.x;
    const __nv_bfloat16* qb = g_q16 + n * PLANE;
    const __nv_bfloat16* kb = g_k16 + n * PLANE;

    auto stage = [&](int ch) {
        int s = ch % 3;
        int i0 = ch * 32;
        {
            int row = tid >> 2;
            int p8 = (tid & 3) * 8;
            cp_async16(&sQ[s][row][p8], qb + row * HWD + i0 + p8);
            cp_async16(&sK[s][row][p8], kb + row * HWD + i0 + p8);
        }
        cp_commit();
    };
    stage(0); stage(1);

    int warp = tid >> 5, lane = tid & 31;
    int r = lane >> 2, cc = lane & 3;
    int wc = (warp & 1) * 32;
    int wd = (warp >> 1) * 16;
    float acc[2][2][4] = {};

    for (int ch = 0; ch < 32; ch++) {
        cp_wait1();
        __syncthreads();
        if (ch + 2 < 32) stage(ch + 2);
        else cp_commit();
        int s = ch % 3;
#pragma unroll
        for (int ks = 0; ks < 2; ks++) {
            int kk = ks * 16;
            uint32_t a[2][4];
#pragma unroll
            for (int m = 0; m < 2; m++) {
                int c0 = wc + m * 16;
                a[m][0] = *(const uint32_t*)&sQ[s][c0 + r][kk + 2 * cc];
                a[m][1] = *(const uint32_t*)&sQ[s][c0 + r + 8][kk + 2 * cc];
                a[m][2] = *(const uint32_t*)&sQ[s][c0 + r][kk + 2 * cc + 8];
                a[m][3] = *(const uint32_t*)&sQ[s][c0 + r + 8][kk + 2 * cc + 8];
            }
#pragma unroll
            for (int t = 0; t < 2; t++) {
                uint32_t b0 = *(const uint32_t*)&sK[s][wd + t * 8 + r][kk + 2 * cc];
                uint32_t b1 = *(const uint32_t*)&sK[s][wd + t * 8 + r][kk + 2 * cc + 8];
#pragma unroll
                for (int m = 0; m < 2; m++) mma_bf16(acc[m][t], a[m], b0, b1);
            }
        }
    }
#pragma unroll
    for (int m = 0; m < 2; m++)
#pragma unroll
        for (int t = 0; t < 2; t++) {
            int c0 = wc + m * 16 + r;
            int d0 = wd + t * 8 + cc * 2;
            float2 o0 = {acc[m][t][0], acc[m][t][1]};
            float2 o1 = {acc[m][t][2], acc[m][t][3]};
            *(float2*)&g_cl[n * 4096 + c0 * 64 + d0] = o0;
            *(float2*)&g_cl[n * 4096 + (c0 + 8) * 64 + d0] = o1;
        }
}

// ---- softmax over n on (n,c,d) -> m_c bf16 ----
__global__ void k_softmax_c() {
    int p = blockIdx.x * 256 + threadIdx.x;
    float vals[32], mx = -1e30f;
#pragma unroll
    for (int nn = 0; nn < 32; nn++) { vals[nn] = g_cl[nn * 4096 + p]; mx = fmaxf(mx, vals[nn]); }
    float s = 0.f;
#pragma unroll
    for (int nn = 0; nn < 32; nn++) { vals[nn] = __expf(vals[nn] - mx); s += vals[nn]; }
    float inv = 1.f / s;
#pragma unroll
    for (int nn = 0; nn < 32; nn++)
        g_mc16[nn * 4096 + p] = __float2bfloat16(vals[nn] * inv);
}

// ---- spatial logits via bf16 MMA: L[n,i,j] = sum_c q[i,c] k[j,c] -> bf16 ----
__global__ void __launch_bounds__(256, 2) k_slogits() {
    __shared__ __align__(16) __nv_bfloat16 sQK[2][128][72];
    int jt = blockIdx.x, it = blockIdx.y, n = blockIdx.z;
    int tid = threadIdx.x;
    const __nv_bfloat16* qb = g_qT16 + n * PLANE + (it * 128) * 64;
    const __nv_bfloat16* kb = g_kT16 + n * PLANE + (jt * 128) * 64;

#pragma unroll
    for (int v = 0; v < 8; v++) {
        int e = tid + v * 256;
        int row = e >> 3;
        int p8 = (e & 7) * 8;
        const __nv_bfloat16* src = (row < 128) ? (qb + row * 64 + p8)
                                               : (kb + (row - 128) * 64 + p8);
        cp_async16(&sQK[row >> 7][row & 127][p8], src);
    }
    cp_commit(); cp_wait0();
    __syncthreads();

    int warp = tid >> 5, lane = tid & 31;
    int r = lane >> 2, cc = lane & 3;
    int wi = (warp & 3) * 32;
    int wj = (warp >> 2) * 64;
    float acc[2][8][4] = {};

#pragma unroll
    for (int ks = 0; ks < 4; ks++) {
        int kk = ks * 16;
        uint32_t a[2][4];
#pragma unroll
        for (int m = 0; m < 2; m++) {
            int i0 = wi + m * 16;
            a[m][0] = *(const uint32_t*)&sQK[0][i0 + r][kk + 2 * cc];
            a[m][1] = *(const uint32_t*)&sQK[0][i0 + r + 8][kk + 2 * cc];
            a[m][2] = *(const uint32_t*)&sQK[0][i0 + r][kk + 2 * cc + 8];
            a[m][3] = *(const uint32_t*)&sQK[0][i0 + r + 8][kk + 2 * cc + 8];
        }
#pragma unroll
        for (int t = 0; t < 8; t++) {
            uint32_t b0 = *(const uint32_t*)&sQK[1][wj + t * 8 + r][kk + 2 * cc];
            uint32_t b1 = *(const uint32_t*)&sQK[1][wj + t * 8 + r][kk + 2 * cc + 8];
#pragma unroll
            for (int m = 0; m < 2; m++) mma_bf16(acc[m][t], a[m], b0, b1);
        }
    }

    __syncthreads();
    uint32_t (*stg)[68] = (uint32_t(*)[68])sQK;
#pragma unroll
    for (int m = 0; m < 2; m++)
#pragma unroll
        for (int t = 0; t < 8; t++) {
            int rowl = wi + m * 16 + r;
            int colw = (wj + t * 8) / 2 + cc;
            __nv_bfloat162 lo = __floats2bfloat162_rn(acc[m][t][0], acc[m][t][1]);
            __nv_bfloat162 hi = __floats2bfloat162_rn(acc[m][t][2], acc[m][t][3]);
            stg[rowl][colw]     = *(uint32_t*)&lo;
            stg[rowl + 8][colw] = *(uint32_t*)&hi;
        }
    __syncthreads();
#pragma unroll
    for (int v = 0; v < 8; v++) {
        int e = tid + v * 256;
        int row = e >> 4, q = e & 15;
        uint4 val = *(uint4*)&stg[row][q * 4];
        __nv_bfloat16* dst = g_L16 + ((size_t)n << 20) + (it * 128 + row) * 1024
                             + jt * 128 + q * 8;
        *(uint4*)dst = val;
    }
}

// ---- per-(i,j) softmax over n -> P bf16 ----
__global__ void k_smax() {
    int base = (blockIdx.x * 256 + threadIdx.x) * 2;
    float f[64];
#pragma unroll
    for (int nn = 0; nn < 32; nn++) {
        uint32_t u = *(const uint32_t*)&g_L16[((size_t)nn << 20) + base];
        float2 fp = __bfloat1622float2(*(__nv_bfloat162*)&u);
        f[2 * nn] = fp.x; f[2 * nn + 1] = fp.y;
    }
    float mx0 = -1e30f, mx1 = -1e30f;
#pragma unroll
    for (int nn = 0; nn < 32; nn++) {
        mx0 = fmaxf(mx0, f[2 * nn]); mx1 = fmaxf(mx1, f[2 * nn + 1]);
    }
    float s0 = 0.f, s1 = 0.f;
#pragma unroll
    for (int nn = 0; nn < 32; nn++) {
        f[2 * nn]     = __expf(f[2 * nn] - mx0);     s0 += f[2 * nn];
        f[2 * nn + 1] = __expf(f[2 * nn + 1] - mx1); s1 += f[2 * nn + 1];
    }
    float inv0 = 1.f / s0, inv1 = 1.f / s1;
#pragma unroll
    for (int nn = 0; nn < 32; nn++) {
        __nv_bfloat162 p = __floats2bfloat162_rn(f[2 * nn] * inv0, f[2 * nn + 1] * inv1);
        *(uint32_t*)&g_P16[((size_t)nn << 20) + base] = *(uint32_t*)&p;
    }
}

// ---- a_s = V @ P^T + a_c = m_c @ v  (bf16 MMA); g_A16 = result TRANSPOSED [i][c] ----
__global__ void __launch_bounds__(256, 2) k_as() {
    __shared__ __align__(16) char sbuf[46080];
    __nv_bfloat16 (*sP)[40] = (__nv_bfloat16(*)[40])sbuf;            // [3][128][40]
    __nv_bfloat16 (*sV)[40] = (__nv_bfloat16(*)[40])(sbuf + 30720);  // [3][64][40]
    int it = blockIdx.x, n = blockIdx.y;
    int tid = threadIdx.x;
    const __nv_bfloat16* vb = g_v16 + n * PLANE;
    const __nv_bfloat16* pb = g_P16 + ((size_t)n << 20) + (it * 128) * 1024;

    auto stage = [&](int ch) {
        int s = ch % 3;
        int j0 = ch * 32;
#pragma unroll
        for (int v = 0; v < 2; v++) {
            int e = tid + v * 256;
            int row = e >> 2;
            int p8 = (e & 3) * 8;
            cp_async16(&sP[s * 128 + row][p8], pb + row * 1024 + j0 + p8);
        }
        {
            int row = tid >> 2;
            int p8 = (tid & 3) * 8;
            cp_async16(&sV[s * 64 + row][p8], vb + row * 1024 + j0 + p8);
        }
        cp_commit();
    };
    stage(0); stage(1);

    int warp = tid >> 5, lane = tid & 31;
    int r = lane >> 2, cc = lane & 3;
    int wc = (warp & 1) * 32;            // 2 warps along c (M)
    int wi = (warp >> 1) * 32;           // 4 warps along i (N)
    float acc[2][4][4] = {};

    for (int ch = 0; ch < 32; ch++) {
        cp_wait1();
        __syncthreads();
        if (ch + 2 < 32) stage(ch + 2);
        else cp_commit();
        int s = ch % 3;
#pragma unroll
        for (int ks = 0; ks < 2; ks++) {
            int kk = ks * 16;
            uint32_t a[2][4];
#pragma unroll
            for (int m = 0; m < 2; m++) {
                int c0 = wc + m * 16;
                a[m][0] = *(const uint32_t*)&sV[s * 64 + c0 + r][kk + 2 * cc];
                a[m][1] = *(const uint32_t*)&sV[s * 64 + c0 + r + 8][kk + 2 * cc];
                a[m][2] = *(const uint32_t*)&sV[s * 64 + c0 + r][kk + 2 * cc + 8];
                a[m][3] = *(const uint32_t*)&sV[s * 64 + c0 + r + 8][kk + 2 * cc + 8];
            }
#pragma unroll
            for (int t = 0; t < 4; t++) {
                uint32_t b0 = *(const uint32_t*)&sP[s * 128 + wi + t * 8 + r][kk + 2 * cc];
                uint32_t b1 = *(const uint32_t*)&sP[s * 128 + wi + t * 8 + r][kk + 2 * cc + 8];
#pragma unroll
                for (int m = 0; m < 2; m++) mma_bf16(acc[m][t], a[m], b0, b1);
            }
        }
    }

    // ---- a_c epilogue: acc += m_c[n] @ vT (K = 64 channels d) ----
    cp_wait0();
    __syncthreads();
    __nv_bfloat16 (*sMc)[72] = (__nv_bfloat16(*)[72])sbuf;           // [64][72]
    __nv_bfloat16 (*sVT)[72] = (__nv_bfloat16(*)[72])(sbuf + 9216);  // [128][72]
#pragma unroll
    for (int v = 0; v < 2; v++) {
        int e = tid + v * 256;
        int row = e >> 3, p8 = (e & 7) * 8;
        cp_async16(&sMc[row][p8], g_mc16 + n * 4096 + row * 64 + p8);
    }
#pragma unroll
    for (int v = 0; v < 4; v++) {
        int e = tid + v * 256;
        int row = e >> 3, p8 = (e & 7) * 8;
        cp_async16(&sVT[row][p8], g_vT16 + n * PLANE + (it * 128 + row) * 64 + p8);
    }
    cp_commit(); cp_wait0();
    __syncthreads();
#pragma unroll
    for (int ks = 0; ks < 4; ks++) {
        int kk = ks * 16;
        uint32_t a[2][4];
#pragma unroll
        for (int m = 0; m < 2; m++) {
            int c0 = wc + m * 16;
            a[m][0] = *(const uint32_t*)&sMc[c0 + r][kk + 2 * cc];
            a[m][1] = *(const uint32_t*)&sMc[c0 + r + 8][kk + 2 * cc];
            a[m][2] = *(const uint32_t*)&sMc[c0 + r][kk + 2 * cc + 8];
            a[m][3] = *(const uint32_t*)&sMc[c0 + r + 8][kk + 2 * cc + 8];
        }
#pragma unroll
        for (int t = 0; t < 4; t++) {
            uint32_t b0 = *(const uint32_t*)&sVT[wi + t * 8 + r][kk + 2 * cc];
            uint32_t b1 = *(const uint32_t*)&sVT[wi + t * 8 + r][kk + 2 * cc + 8];
#pragma unroll
            for (int m = 0; m < 2; m++) mma_bf16(acc[m][t], a[m], b0, b1);
        }
    }

    // ---- store A^T [i][c] bf16 via smem staging ----
    __syncthreads();
    __nv_bfloat16 (*sAT)[72] = (__nv_bfloat16(*)[72])sbuf;           // [128][72]
#pragma unroll
    for (int m = 0; m < 2; m++)
#pragma unroll
        for (int t = 0; t < 4; t++) {
            int c0 = wc + m * 16 + r;
            int i0 = wi + t * 8 + cc * 2;
            sAT[i0][c0]         = __float2bfloat16(acc[m][t][0]);
            sAT[i0 + 1][c0]     = __float2bfloat16(acc[m][t][1]);
            sAT[i0][c0 + 8]     = __float2bfloat16(acc[m][t][2]);
            sAT[i0 + 1][c0 + 8] = __float2bfloat16(acc[m][t][3]);
        }
    __syncthreads();
#pragma unroll
    for (int v = 0; v < 4; v++) {
        int e = tid + v * 256;
        int row = e >> 3, p8 = (e & 7) * 8;
        uint4 val = *(uint4*)&sAT[row][p8];
        *(uint4*)&g_A16[n * PLANE + (it * 128 + row) * 64 + p8] = val;
    }
}

// ---- temporal conv via bf16 MMA ----
__global__ void __launch_bounds__(256, 2) k_tconv(const float* __restrict__ wX,
                                                  const float* __restrict__ bX) {
    __shared__ __align__(16) __nv_bfloat16 sW16[64][200];  // [o][kk*64+c], 192 used
    __shared__ __align__(16) __nv_bfloat16 sAT[128][72];   // [i][c] per tap
    int it = blockIdx.x, n = blockIdx.y;
    int b = n >> 3, t = n & 7;
    int tid = threadIdx.x;

    for (int idx = tid; idx < 12288; idx += 256) {
        int o = idx / 192, rem = idx % 192;
        int c = rem / 3, kk = rem % 3;
        sW16[o][kk * 64 + c] = __float2bfloat16(wX[idx]);
    }

    int warp = tid >> 5, lane = tid & 31;
    int r = lane >> 2, cc = lane & 3;
    int wc = (warp & 1) * 32;
    int wi = (warp >> 1) * 32;
    float acc[2][4][4] = {};

    for (int kk = 0; kk < 3; kk++) {
        int tp = t + kk - 1;
        if (tp < 0 || tp >= 8) continue;
        __syncthreads();
        const __nv_bfloat16* ab = g_A16 + (b * 8 + tp) * PLANE + (it * 128) * 64;
#pragma unroll
        for (int v = 0; v < 4; v++) {
            int e = tid + v * 256;
            int row = e >> 3, p8 = (e & 7) * 8;
            cp_async16(&sAT[row][p8], ab + row * 64 + p8);
        }
        cp_commit(); cp_wait0();
        __syncthreads();
#pragma unroll
        for (int ks = 0; ks < 4; ks++) {
            int kw = kk * 64 + ks * 16;
            int ka = ks * 16;
            uint32_t a[2][4];
#pragma unroll
            for (int m = 0; m < 2; m++) {
                int o0 = wc + m * 16;
                a[m][0] = *(const uint32_t*)&sW16[o0 + r][kw + 2 * cc];
                a[m][1] = *(const uint32_t*)&sW16[o0 + r + 8][kw + 2 * cc];
                a[m][2] = *(const uint32_t*)&sW16[o0 + r][kw + 2 * cc + 8];
                a[m][3] = *(const uint32_t*)&sW16[o0 + r + 8][kw + 2 * cc + 8];
            }
#pragma unroll
            for (int tt = 0; tt < 4; tt++) {
                uint32_t b0 = *(const uint32_t*)&sAT[wi + tt * 8 + r][ka + 2 * cc];
                uint32_t b1 = *(const uint32_t*)&sAT[wi + tt * 8 + r][ka + 2 * cc + 8];
#pragma unroll
                for (int m = 0; m < 2; m++) mma_bf16(acc[m][tt], a[m], b0, b1);
            }
        }
    }

#pragma unroll
    for (int m = 0; m < 2; m++)
#pragma unroll
        for (int tt = 0; tt < 4; tt++) {
            int o0 = wc + m * 16 + r;
            int i0 = it * 128 + wi + tt * 8 + cc * 2;
            float b0f = bX[o0], b1f = bX[o0 + 8];
            float r00 = fmaxf(acc[m][tt][0] + b0f, 0.f);
            float r01 = fmaxf(acc[m][tt][1] + b0f, 0.f);
            float r10 = fmaxf(acc[m][tt][2] + b1f, 0.f);
            float r11 = fmaxf(acc[m][tt][3] + b1f, 0.f);
            __nv_bfloat162 p0 = __floats2bfloat162_rn(r00, r01);
            __nv_bfloat162 p1 = __floats2bfloat162_rn(r10, r11);
            *(uint32_t*)&g_Xe16[n * PLANE + o0 * HWD + i0] = *(uint32_t*)&p0;
            *(uint32_t*)&g_Xe16[n * PLANE + (o0 + 8) * HWD + i0] = *(uint32_t*)&p1;
        }
}

// ---- temporal Gram ----
__global__ void k_tl() {
    __shared__ float sXe[8][1032];
    int b = blockIdx.y;
    int d0 = blockIdx.x * 1024;
    int tid = threadIdx.x;
#pragma unroll
    for (int v = 0; v < 4; v++) {
        int e = tid + v * 256;
        int t = e >> 7;
        int d8 = (e & 127) * 8;
        uint4 raw = *(const uint4*)&g_Xe16[(b * 8 + t) * PLANE + d0 + d8];
        uint32_t* pu = (uint32_t*)&raw;
#pragma unroll
        for (int w = 0; w < 4; w++) {
            float2 f = __bfloat1622float2(*(__nv_bfloat162*)&pu[w]);
            sXe[t][d8 + 2 * w] = f.x; sXe[t][d8 + 2 * w + 1] = f.y;
        }
    }
    __syncthreads();
    int p = tid >> 2, sub = tid & 3;
    int t = p >> 3, s = p & 7;
    float acc = 0.f;
#pragma unroll 8
    for (int it = 0; it < 64; it++) {
        int col = sub * 4 + it * 16;
        float4 a = *(const float4*)&sXe[t][col];
        float4 c = *(const float4*)&sXe[s][col];
        acc += a.x * c.x + a.y * c.y + a.z * c.z + a.w * c.w;
    }
    acc += __shfl_xor_sync(0xffffffff, acc, 1);
    acc += __shfl_xor_sync(0xffffffff, acc, 2);
    if (sub == 0) atomicAdd(&g_tl[b * 64 + p], acc);
}

__global__ void k_softmax_t() {
    int p = threadIdx.x;
    float v0 = g_tl[p], v1 = g_tl[64 + p], v2 = g_tl[128 + p], v3 = g_tl[192 + p];
    float mx = fmaxf(fmaxf(v0, v1), fmaxf(v2, v3));
    v0 = __expf(v0 - mx); v1 = __expf(v1 - mx); v2 = __expf(v2 - mx); v3 = __expf(v3 - mx);
    float inv = 1.f / (v0 + v1 + v2 + v3);
    g_tl[p] = v0 * inv; g_tl[64 + p] = v1 * inv;
    g_tl[128 + p] = v2 * inv; g_tl[192 + p] = v3 * inv;
}

__global__ void k_out(float* __restrict__ out) {
    __shared__ float sM[64];
    int gid = blockIdx.x * 256 + threadIdx.x;
    int b = gid >> 16;
    if (threadIdx.x < 64) sM[threadIdx.x] = g_tl[b * 64 + threadIdx.x];
    __syncthreads();
    int rem = gid & 65535;
    int c = rem >> 10, i = rem & 1023;
    float vv[8];
#pragma unroll
    for (int s = 0; s < 8; s++) vv[s] = g_v[(b * 8 + s) * PLANE + c * HWD + i];
#pragma unroll
    for (int t = 0; t < 8; t++) {
        float rsum = 0.f;
#pragma unroll
        for (int s = 0; s < 8; s++) rsum = fmaf(sM[t * 8 + s], vv[s], rsum);
        out[((b * 64 + c) * 8 + t) * HWD + i] = rsum;
    }
}

// ============================================================
extern "C" void kernel_launch(void* const* d_in, const int* in_sizes, int n_in,
                              void* d_out, int out_size) {
    const float* x  = (const float*)d_in[0];
    const float* wq = (const float*)d_in[1];
    const float* bq = (const float*)d_in[2];
    const float* wk = (const float*)d_in[3];
    const float* bk = (const float*)d_in[4];
    const float* wv = (const float*)d_in[5];
    const float* bv = (const float*)d_in[6];
    const float* wX = (const float*)d_in[7];
    const float* bX = (const float*)d_in[8];
    float* out = (float*)d_out;

    k_v<<<512, 256>>>(x, wv, bv);                          // 0
    k_qk<<<dim3(8, 32), 256>>>(x, wq, bq, wk, bk);         // 1
    k_cl<<<32, 256>>>();                                   // 2
    k_slogits<<<dim3(8, 8, 32), 256>>>();                  // 3  <- ncu capture slot
    k_softmax_c<<<16, 256>>>();                            // 4
    k_smax<<<2048, 256>>>();                               // 5
    k_as<<<dim3(8, 32), 256>>>();                          // 6
    k_tconv<<<dim3(8, 32), 256>>>(wX, bX);                 // 7
    k_tl<<<dim3(64, 4), 256>>>();                          // 8
    k_softmax_t<<<1, 64>>>();                              // 9
    k_out<<<1024, 256>>>(out);                             // 10
}